// round 1
// baseline (speedup 1.0000x reference)
#include <cuda_runtime.h>
#include <math.h>

// Problem constants
#define BB 2
#define SS 2048
#define DD 1024
#define HH 16
#define HD 64
#define WW 16
#define DFF 4096
#define MM (BB * SS)   // 4096 rows

// ---------------- scratch (no allocations allowed) ----------------
__device__ float g_h[MM * DD];          // LN1 output
__device__ float g_qkv[MM * 3 * DD];    // QKV
__device__ float g_attn[MM * DD];       // attention output
__device__ float g_x1[MM * DD];         // residual-1 output
__device__ float g_xn[MM * DD];         // LN2 output
__device__ float g_ff[MM * DFF];        // MLP hidden

// ---------------- LayerNorm: one block per row, D=1024 ----------------
__global__ void ln_kernel(const float* __restrict__ x,
                          const float* __restrict__ g,
                          const float* __restrict__ b,
                          float* __restrict__ y) {
    int row = blockIdx.x;
    const float* xp = x + (size_t)row * DD;
    int i = threadIdx.x * 4;            // 256 threads * 4 = 1024
    float4 xv = *(const float4*)(xp + i);
    float s  = xv.x + xv.y + xv.z + xv.w;
    float ss = xv.x*xv.x + xv.y*xv.y + xv.z*xv.z + xv.w*xv.w;

    // warp reduce
    for (int o = 16; o > 0; o >>= 1) {
        s  += __shfl_xor_sync(0xffffffffu, s,  o);
        ss += __shfl_xor_sync(0xffffffffu, ss, o);
    }
    __shared__ float sh_s[8], sh_ss[8];
    int wid = threadIdx.x >> 5, lane = threadIdx.x & 31;
    if (lane == 0) { sh_s[wid] = s; sh_ss[wid] = ss; }
    __syncthreads();
    if (wid == 0) {
        s  = (lane < 8) ? sh_s[lane]  : 0.f;
        ss = (lane < 8) ? sh_ss[lane] : 0.f;
        for (int o = 4; o > 0; o >>= 1) {
            s  += __shfl_xor_sync(0xffffffffu, s,  o);
            ss += __shfl_xor_sync(0xffffffffu, ss, o);
        }
        if (lane == 0) { sh_s[0] = s; sh_ss[0] = ss; }
    }
    __syncthreads();
    float mean = sh_s[0] * (1.0f / DD);
    float var  = sh_ss[0] * (1.0f / DD) - mean * mean;
    float inv  = rsqrtf(var + 1e-5f);

    float4 gv = *(const float4*)(g + i);
    float4 bv = *(const float4*)(b + i);
    float4 ov;
    ov.x = (xv.x - mean) * inv * gv.x + bv.x;
    ov.y = (xv.y - mean) * inv * gv.y + bv.y;
    ov.z = (xv.z - mean) * inv * gv.z + bv.z;
    ov.w = (xv.w - mean) * inv * gv.w + bv.w;
    *(float4*)(y + (size_t)row * DD + i) = ov;
}

// ---------------- SGEMM: C[M,N] = A[M,K] @ Bw[N,K]^T  (+ epilogue) ----------------
// epi: 0 = +bias ; 1 = +bias+res ; 2 = gelu(+bias)
#define BM 128
#define BN 128
#define BK 16
#define TM 8
#define TN 8

__device__ __forceinline__ float gelu_tanh(float x) {
    float x3 = x * x * x;
    return 0.5f * x * (1.0f + tanhf(0.7978845608028654f * (x + 0.044715f * x3)));
}

__global__ __launch_bounds__(256, 2)
void sgemm_nt(const float* __restrict__ A, const float* __restrict__ Bw,
              const float* __restrict__ bias, const float* __restrict__ res,
              float* __restrict__ C, int Mm, int Nn, int Kk, int epi) {
    __shared__ float As[BK][BM];
    __shared__ float Bs[BK][BN];
    int tid = threadIdx.x;
    int bm = blockIdx.y * BM;
    int bn = blockIdx.x * BN;
    int lr = tid >> 2;           // 0..63
    int lc = (tid & 3) * 4;      // 0,4,8,12
    int ty = tid >> 4;           // 0..15
    int tx = tid & 15;           // 0..15

    float acc[TM][TN];
    #pragma unroll
    for (int i = 0; i < TM; i++)
        #pragma unroll
        for (int j = 0; j < TN; j++) acc[i][j] = 0.f;

    for (int k0 = 0; k0 < Kk; k0 += BK) {
        #pragma unroll
        for (int t = 0; t < 2; t++) {
            int r = lr + t * 64;
            float4 av = *(const float4*)(A  + (size_t)(bm + r) * Kk + k0 + lc);
            As[lc + 0][r] = av.x; As[lc + 1][r] = av.y;
            As[lc + 2][r] = av.z; As[lc + 3][r] = av.w;
            float4 bv = *(const float4*)(Bw + (size_t)(bn + r) * Kk + k0 + lc);
            Bs[lc + 0][r] = bv.x; Bs[lc + 1][r] = bv.y;
            Bs[lc + 2][r] = bv.z; Bs[lc + 3][r] = bv.w;
        }
        __syncthreads();
        #pragma unroll
        for (int kk = 0; kk < BK; kk++) {
            float4 a0 = *(const float4*)&As[kk][ty * TM];
            float4 a1 = *(const float4*)&As[kk][ty * TM + 4];
            float4 b0 = *(const float4*)&Bs[kk][tx * TN];
            float4 b1 = *(const float4*)&Bs[kk][tx * TN + 4];
            float a[TM] = {a0.x, a0.y, a0.z, a0.w, a1.x, a1.y, a1.z, a1.w};
            float b[TN] = {b0.x, b0.y, b0.z, b0.w, b1.x, b1.y, b1.z, b1.w};
            #pragma unroll
            for (int i = 0; i < TM; i++)
                #pragma unroll
                for (int j = 0; j < TN; j++)
                    acc[i][j] = fmaf(a[i], b[j], acc[i][j]);
        }
        __syncthreads();
    }

    #pragma unroll
    for (int i = 0; i < TM; i++) {
        int row = bm + ty * TM + i;
        #pragma unroll
        for (int j = 0; j < TN; j++) {
            int col = bn + tx * TN + j;
            float v = acc[i][j] + bias[col];
            if (epi == 1)      v += res[(size_t)row * Nn + col];
            else if (epi == 2) v = gelu_tanh(v);
            C[(size_t)row * Nn + col] = v;
        }
    }
}

// ---------------- Sliding-window causal attention (W=16) ----------------
// One warp per (b, s, h). Lane j (<16) owns key at offset j back from query.
__global__ void attn_kernel(const float* __restrict__ qkv, float* __restrict__ out) {
    int gwarp = (blockIdx.x * blockDim.x + threadIdx.x) >> 5;
    int lane = threadIdx.x & 31;
    if (gwarp >= MM * HH) return;
    int m = gwarp / HH;
    int h = gwarp % HH;
    int s = m & (SS - 1);

    const float* qp = qkv + (size_t)m * (3 * DD) + h * HD;
    float score = -INFINITY;
    if (lane < WW && lane <= s) {
        const float* kp = qkv + (size_t)(m - lane) * (3 * DD) + DD + h * HD;
        float acc = 0.f;
        #pragma unroll
        for (int d = 0; d < HD; d += 4) {
            float4 qa = *(const float4*)(qp + d);
            float4 ka = *(const float4*)(kp + d);
            acc = fmaf(qa.x, ka.x, acc);
            acc = fmaf(qa.y, ka.y, acc);
            acc = fmaf(qa.z, ka.z, acc);
            acc = fmaf(qa.w, ka.w, acc);
        }
        score = acc * 0.125f;   // 1/sqrt(64)
    }
    float mx = score;
    for (int o = 16; o > 0; o >>= 1) mx = fmaxf(mx, __shfl_xor_sync(0xffffffffu, mx, o));
    float p = (score == -INFINITY) ? 0.f : __expf(score - mx);
    float sum = p;
    for (int o = 16; o > 0; o >>= 1) sum += __shfl_xor_sync(0xffffffffu, sum, o);
    float inv = 1.f / sum;

    int d = lane * 2;           // each lane handles 2 output dims (64 total)
    float o0 = 0.f, o1 = 0.f;
    int jmax = min(WW - 1, s);
    for (int jj = 0; jj <= jmax; jj++) {
        float pj = __shfl_sync(0xffffffffu, p, jj);
        const float* vp = qkv + (size_t)(m - jj) * (3 * DD) + 2 * DD + h * HD + d;
        o0 = fmaf(pj, vp[0], o0);
        o1 = fmaf(pj, vp[1], o1);
    }
    float* op = out + (size_t)m * DD + h * HD + d;
    op[0] = o0 * inv;
    op[1] = o1 * inv;
}

// ---------------- launch ----------------
extern "C" void kernel_launch(void* const* d_in, const int* in_sizes, int n_in,
                              void* d_out, int out_size) {
    const float* x          = (const float*)d_in[0];
    const float* ln1_g      = (const float*)d_in[1];
    const float* ln1_b      = (const float*)d_in[2];
    const float* in_proj_w  = (const float*)d_in[3];
    const float* in_proj_b  = (const float*)d_in[4];
    const float* out_proj_w = (const float*)d_in[5];
    const float* out_proj_b = (const float*)d_in[6];
    const float* ln2_g      = (const float*)d_in[7];
    const float* ln2_b      = (const float*)d_in[8];
    const float* mlp_w1     = (const float*)d_in[9];
    const float* mlp_b1     = (const float*)d_in[10];
    const float* mlp_w2     = (const float*)d_in[11];
    const float* mlp_b2     = (const float*)d_in[12];
    float* out = (float*)d_out;

    float *p_h, *p_qkv, *p_attn, *p_x1, *p_xn, *p_ff;
    cudaGetSymbolAddress((void**)&p_h,    g_h);
    cudaGetSymbolAddress((void**)&p_qkv,  g_qkv);
    cudaGetSymbolAddress((void**)&p_attn, g_attn);
    cudaGetSymbolAddress((void**)&p_x1,   g_x1);
    cudaGetSymbolAddress((void**)&p_xn,   g_xn);
    cudaGetSymbolAddress((void**)&p_ff,   g_ff);

    // 1. LN1
    ln_kernel<<<MM, 256>>>(x, ln1_g, ln1_b, p_h);
    // 2. QKV = h @ W_in^T + b   [4096, 3072]
    sgemm_nt<<<dim3(3 * DD / BN, MM / BM), 256>>>(p_h, in_proj_w, in_proj_b, nullptr,
                                                  p_qkv, MM, 3 * DD, DD, 0);
    // 3. windowed attention
    attn_kernel<<<(MM * HH) / 8, 256>>>(p_qkv, p_attn);
    // 4. out proj + residual(x)  [4096, 1024]
    sgemm_nt<<<dim3(DD / BN, MM / BM), 256>>>(p_attn, out_proj_w, out_proj_b, x,
                                              p_x1, MM, DD, DD, 1);
    // 5. LN2
    ln_kernel<<<MM, 256>>>(p_x1, ln2_g, ln2_b, p_xn);
    // 6. MLP up + GELU  [4096, 4096]
    sgemm_nt<<<dim3(DFF / BN, MM / BM), 256>>>(p_xn, mlp_w1, mlp_b1, nullptr,
                                               p_ff, MM, DFF, DD, 2);
    // 7. MLP down + residual(x1) -> out  [4096, 1024]
    sgemm_nt<<<dim3(DD / BN, MM / BM), 256>>>(p_ff, mlp_w2, mlp_b2, p_x1,
                                              out, MM, DD, DFF, 1);
}

// round 3
// speedup vs baseline: 2.4343x; 2.4343x over previous
#include <cuda_runtime.h>
#include <cuda_bf16.h>
#include <math.h>
#include <stdint.h>

// Problem constants
#define BB 2
#define SS 2048
#define DD 1024
#define HH 16
#define HD 64
#define WW 16
#define DFF 4096
#define MM (BB * SS)   // 4096 rows

// ---------------- scratch (no allocations allowed) ----------------
__device__ float g_qkv[MM * 3 * DD];          // QKV fp32
__device__ float g_x1[MM * DD];               // residual-1 output fp32
__device__ __nv_bfloat16 g_h_hi[MM * DD],   g_h_lo[MM * DD];     // LN1 out split
__device__ __nv_bfloat16 g_at_hi[MM * DD],  g_at_lo[MM * DD];    // attn out split
__device__ __nv_bfloat16 g_xn_hi[MM * DD],  g_xn_lo[MM * DD];    // LN2 out split
__device__ __nv_bfloat16 g_ff_hi[MM * DFF], g_ff_lo[MM * DFF];   // MLP hidden split
__device__ __nv_bfloat16 g_wq_hi[3 * DD * DD], g_wq_lo[3 * DD * DD];
__device__ __nv_bfloat16 g_wo_hi[DD * DD],     g_wo_lo[DD * DD];
__device__ __nv_bfloat16 g_w1_hi[DFF * DD],    g_w1_lo[DFF * DD];
__device__ __nv_bfloat16 g_w2_hi[DD * DFF],    g_w2_lo[DD * DFF];

__device__ __forceinline__ uint32_t smem_u32(const void* p) {
    return (uint32_t)__cvta_generic_to_shared(p);
}

__device__ __forceinline__ void split_bf16(float v, __nv_bfloat16& hi, __nv_bfloat16& lo) {
    hi = __float2bfloat16(v);
    lo = __float2bfloat16(v - __bfloat162float(hi));
}

__device__ __forceinline__ float gelu_tanh(float x) {
    float x3 = x * x * x;
    return 0.5f * x * (1.0f + tanhf(0.7978845608028654f * (x + 0.044715f * x3)));
}

// ---------------- weight split kernel ----------------
__global__ void split_kernel(const float* __restrict__ in,
                             __nv_bfloat16* __restrict__ hi,
                             __nv_bfloat16* __restrict__ lo, int n) {
    int i = (blockIdx.x * blockDim.x + threadIdx.x) * 4;
    if (i >= n) return;
    float4 v = *(const float4*)(in + i);
    __nv_bfloat16 h0, l0, h1, l1, h2, l2, h3, l3;
    split_bf16(v.x, h0, l0); split_bf16(v.y, h1, l1);
    split_bf16(v.z, h2, l2); split_bf16(v.w, h3, l3);
    *(__nv_bfloat162*)(hi + i)     = __nv_bfloat162(h0, h1);
    *(__nv_bfloat162*)(hi + i + 2) = __nv_bfloat162(h2, h3);
    *(__nv_bfloat162*)(lo + i)     = __nv_bfloat162(l0, l1);
    *(__nv_bfloat162*)(lo + i + 2) = __nv_bfloat162(l2, l3);
}

// ---------------- LayerNorm -> split bf16 ----------------
__global__ void ln_split_kernel(const float* __restrict__ x,
                                const float* __restrict__ g,
                                const float* __restrict__ b,
                                __nv_bfloat16* __restrict__ yhi,
                                __nv_bfloat16* __restrict__ ylo) {
    int row = blockIdx.x;
    const float* xp = x + (size_t)row * DD;
    int i = threadIdx.x * 4;
    float4 xv = *(const float4*)(xp + i);
    float s  = xv.x + xv.y + xv.z + xv.w;
    float ss = xv.x*xv.x + xv.y*xv.y + xv.z*xv.z + xv.w*xv.w;
    for (int o = 16; o > 0; o >>= 1) {
        s  += __shfl_xor_sync(0xffffffffu, s,  o);
        ss += __shfl_xor_sync(0xffffffffu, ss, o);
    }
    __shared__ float sh_s[8], sh_ss[8];
    int wid = threadIdx.x >> 5, lane = threadIdx.x & 31;
    if (lane == 0) { sh_s[wid] = s; sh_ss[wid] = ss; }
    __syncthreads();
    if (wid == 0) {
        s  = (lane < 8) ? sh_s[lane]  : 0.f;
        ss = (lane < 8) ? sh_ss[lane] : 0.f;
        for (int o = 4; o > 0; o >>= 1) {
            s  += __shfl_xor_sync(0xffffffffu, s,  o);
            ss += __shfl_xor_sync(0xffffffffu, ss, o);
        }
        if (lane == 0) { sh_s[0] = s; sh_ss[0] = ss; }
    }
    __syncthreads();
    float mean = sh_s[0] * (1.0f / DD);
    float var  = sh_ss[0] * (1.0f / DD) - mean * mean;
    float inv  = rsqrtf(var + 1e-5f);
    float4 gv = *(const float4*)(g + i);
    float4 bv = *(const float4*)(b + i);
    float o0 = (xv.x - mean) * inv * gv.x + bv.x;
    float o1 = (xv.y - mean) * inv * gv.y + bv.y;
    float o2 = (xv.z - mean) * inv * gv.z + bv.z;
    float o3 = (xv.w - mean) * inv * gv.w + bv.w;
    __nv_bfloat16 h0, l0, h1, l1, h2, l2, h3, l3;
    split_bf16(o0, h0, l0); split_bf16(o1, h1, l1);
    split_bf16(o2, h2, l2); split_bf16(o3, h3, l3);
    size_t idx = (size_t)row * DD + i;
    *(__nv_bfloat162*)(yhi + idx)     = __nv_bfloat162(h0, h1);
    *(__nv_bfloat162*)(yhi + idx + 2) = __nv_bfloat162(h2, h3);
    *(__nv_bfloat162*)(ylo + idx)     = __nv_bfloat162(l0, l1);
    *(__nv_bfloat162*)(ylo + idx + 2) = __nv_bfloat162(l2, l3);
}

// ---------------- mma.sync split-bf16 GEMM: C[M,N] = A[M,K] @ Bw[N,K]^T (+epi) ----------------
// epi: 0 = fp32 +bias ; 1 = fp32 +bias+res ; 2 = gelu(+bias) -> split bf16
#define BKT 32
#define PADE 8
#define LROW (BKT + PADE)               // 40 bf16 per smem row
#define TILE_BYTES (128 * LROW * 2)     // 10240
#define OFF_AH 0
#define OFF_AL TILE_BYTES
#define OFF_BH (2 * TILE_BYTES)
#define OFF_BL (3 * TILE_BYTES)
#define STAGE_BYTES (4 * TILE_BYTES)    // 40960
#define GEMM_SMEM (2 * STAGE_BYTES)     // 81920

#define LDMX4(r0, r1, r2, r3, addr) \
    asm volatile("ldmatrix.sync.aligned.m8n8.x4.shared.b16 {%0,%1,%2,%3}, [%4];" \
                 : "=r"(r0), "=r"(r1), "=r"(r2), "=r"(r3) : "r"(addr))

#define MMA_BF16(d, a, b0, b1) \
    asm volatile("mma.sync.aligned.m16n8k16.row.col.f32.bf16.bf16.f32 " \
                 "{%0,%1,%2,%3}, {%4,%5,%6,%7}, {%8,%9}, {%0,%1,%2,%3};" \
                 : "+f"((d)[0]), "+f"((d)[1]), "+f"((d)[2]), "+f"((d)[3]) \
                 : "r"((a)[0]), "r"((a)[1]), "r"((a)[2]), "r"((a)[3]), "r"(b0), "r"(b1))

__device__ __forceinline__ void load_tile(const __nv_bfloat16* __restrict__ g,
                                          int ldk, int row0, int k0,
                                          uint32_t sbase, int tid) {
    #pragma unroll
    for (int j = 0; j < 2; j++) {
        int ch = tid + 256 * j;          // 0..511
        int r = ch >> 2;
        int c = ch & 3;
        const void* gp = g + (size_t)(row0 + r) * ldk + k0 + c * 8;
        uint32_t sa = sbase + r * (LROW * 2) + c * 16;
        asm volatile("cp.async.cg.shared.global [%0], [%1], 16;" :: "r"(sa), "l"(gp) : "memory");
    }
}

__global__ __launch_bounds__(256, 1)
void gemm3(const __nv_bfloat16* __restrict__ Ahi, const __nv_bfloat16* __restrict__ Alo,
           const __nv_bfloat16* __restrict__ Bhi, const __nv_bfloat16* __restrict__ Blo,
           const float* __restrict__ bias, const float* __restrict__ res,
           float* __restrict__ outF,
           __nv_bfloat16* __restrict__ outHi, __nv_bfloat16* __restrict__ outLo,
           int Nn, int Kk, int epi) {
    extern __shared__ __align__(16) char dsm[];
    uint32_t sbase = smem_u32(dsm);
    int tid = threadIdx.x;
    int lane = tid & 31;
    int wid = tid >> 5;
    int wr = wid & 1;      // warp row: m offset wr*64
    int wc = wid >> 1;     // warp col: n offset wc*32
    int bm = blockIdx.y * 128;
    int bn = blockIdx.x * 128;

    float acc[4][4][4];
    #pragma unroll
    for (int mi = 0; mi < 4; mi++)
        #pragma unroll
        for (int ni = 0; ni < 4; ni++)
            #pragma unroll
            for (int q = 0; q < 4; q++) acc[mi][ni][q] = 0.f;

    const int NC = Kk >> 5;   // BKT=32 chunks

    // prologue
    load_tile(Ahi, Kk, bm, 0, sbase + OFF_AH, tid);
    load_tile(Alo, Kk, bm, 0, sbase + OFF_AL, tid);
    load_tile(Bhi, Kk, bn, 0, sbase + OFF_BH, tid);
    load_tile(Blo, Kk, bn, 0, sbase + OFF_BL, tid);
    asm volatile("cp.async.commit_group;" ::: "memory");

    // per-thread ldmatrix address components (element units)
    int a_row = wr * 64 + (lane & 15);
    int a_colsel = (lane >> 4) << 3;            // 0 or 8
    int b_row = wc * 32 + (lane & 7) + ((lane >> 4) & 1) * 8;
    int b_colsel = ((lane >> 3) & 1) * 8;       // 0 or 8

    for (int c = 0; c < NC; c++) {
        if (c + 1 < NC) {
            uint32_t st = sbase + ((c + 1) & 1) * STAGE_BYTES;
            int k0 = (c + 1) << 5;
            load_tile(Ahi, Kk, bm, k0, st + OFF_AH, tid);
            load_tile(Alo, Kk, bm, k0, st + OFF_AL, tid);
            load_tile(Bhi, Kk, bn, k0, st + OFF_BH, tid);
            load_tile(Blo, Kk, bn, k0, st + OFF_BL, tid);
            asm volatile("cp.async.commit_group;" ::: "memory");
            asm volatile("cp.async.wait_group 1;" ::: "memory");
        } else {
            asm volatile("cp.async.wait_group 0;" ::: "memory");
        }
        __syncthreads();

        uint32_t st = sbase + (c & 1) * STAGE_BYTES;
        #pragma unroll
        for (int kk = 0; kk < 2; kk++) {
            int kb = kk * 16;
            uint32_t ah[4][4], al[4][4];
            #pragma unroll
            for (int mi = 0; mi < 4; mi++) {
                uint32_t off = ((a_row + mi * 16) * LROW + kb + a_colsel) * 2;
                LDMX4(ah[mi][0], ah[mi][1], ah[mi][2], ah[mi][3], st + OFF_AH + off);
                LDMX4(al[mi][0], al[mi][1], al[mi][2], al[mi][3], st + OFF_AL + off);
            }
            uint32_t bh[8], bl[8];
            #pragma unroll
            for (int g = 0; g < 2; g++) {
                uint32_t off = ((b_row + g * 16) * LROW + kb + b_colsel) * 2;
                LDMX4(bh[g*4+0], bh[g*4+1], bh[g*4+2], bh[g*4+3], st + OFF_BH + off);
                LDMX4(bl[g*4+0], bl[g*4+1], bl[g*4+2], bl[g*4+3], st + OFF_BL + off);
            }
            #pragma unroll
            for (int mi = 0; mi < 4; mi++)
                #pragma unroll
                for (int ni = 0; ni < 4; ni++) {
                    MMA_BF16(acc[mi][ni], ah[mi], bh[ni*2], bh[ni*2+1]);
                    MMA_BF16(acc[mi][ni], ah[mi], bl[ni*2], bl[ni*2+1]);
                    MMA_BF16(acc[mi][ni], al[mi], bh[ni*2], bh[ni*2+1]);
                }
        }
        __syncthreads();
    }

    // epilogue
    int m0 = bm + wr * 64 + (lane >> 2);
    int n0 = bn + wc * 32 + (lane & 3) * 2;
    #pragma unroll
    for (int mi = 0; mi < 4; mi++) {
        #pragma unroll
        for (int r2 = 0; r2 < 2; r2++) {
            int row = m0 + mi * 16 + r2 * 8;
            size_t rbase = (size_t)row * Nn;
            #pragma unroll
            for (int ni = 0; ni < 4; ni++) {
                int col = n0 + ni * 8;
                float v0 = acc[mi][ni][r2*2+0] + bias[col];
                float v1 = acc[mi][ni][r2*2+1] + bias[col+1];
                if (epi == 0) {
                    *(float2*)(outF + rbase + col) = make_float2(v0, v1);
                } else if (epi == 1) {
                    float2 rv = *(const float2*)(res + rbase + col);
                    *(float2*)(outF + rbase + col) = make_float2(v0 + rv.x, v1 + rv.y);
                } else {
                    v0 = gelu_tanh(v0); v1 = gelu_tanh(v1);
                    __nv_bfloat16 h0, l0, h1, l1;
                    split_bf16(v0, h0, l0); split_bf16(v1, h1, l1);
                    *(__nv_bfloat162*)(outHi + rbase + col) = __nv_bfloat162(h0, h1);
                    *(__nv_bfloat162*)(outLo + rbase + col) = __nv_bfloat162(l0, l1);
                }
            }
        }
    }
}

// ---------------- Sliding-window causal attention (W=16) -> split bf16 ----------------
__global__ void attn_kernel(const float* __restrict__ qkv,
                            __nv_bfloat16* __restrict__ ohi,
                            __nv_bfloat16* __restrict__ olo) {
    int gwarp = (blockIdx.x * blockDim.x + threadIdx.x) >> 5;
    int lane = threadIdx.x & 31;
    if (gwarp >= MM * HH) return;
    int m = gwarp / HH;
    int h = gwarp % HH;
    int s = m & (SS - 1);

    const float* qp = qkv + (size_t)m * (3 * DD) + h * HD;
    float score = -INFINITY;
    if (lane < WW && lane <= s) {
        const float* kp = qkv + (size_t)(m - lane) * (3 * DD) + DD + h * HD;
        float acc = 0.f;
        #pragma unroll
        for (int d = 0; d < HD; d += 4) {
            float4 qa = *(const float4*)(qp + d);
            float4 ka = *(const float4*)(kp + d);
            acc = fmaf(qa.x, ka.x, acc);
            acc = fmaf(qa.y, ka.y, acc);
            acc = fmaf(qa.z, ka.z, acc);
            acc = fmaf(qa.w, ka.w, acc);
        }
        score = acc * 0.125f;
    }
    float mx = score;
    for (int o = 16; o > 0; o >>= 1) mx = fmaxf(mx, __shfl_xor_sync(0xffffffffu, mx, o));
    float p = (score == -INFINITY) ? 0.f : __expf(score - mx);
    float sum = p;
    for (int o = 16; o > 0; o >>= 1) sum += __shfl_xor_sync(0xffffffffu, sum, o);
    float inv = 1.f / sum;

    int d = lane * 2;
    float o0 = 0.f, o1 = 0.f;
    int jmax = min(WW - 1, s);
    for (int jj = 0; jj <= jmax; jj++) {
        float pj = __shfl_sync(0xffffffffu, p, jj);
        const float* vp = qkv + (size_t)(m - jj) * (3 * DD) + 2 * DD + h * HD + d;
        o0 = fmaf(pj, vp[0], o0);
        o1 = fmaf(pj, vp[1], o1);
    }
    o0 *= inv; o1 *= inv;
    size_t idx = (size_t)m * DD + h * HD + d;
    __nv_bfloat16 h0, l0, h1, l1;
    split_bf16(o0, h0, l0); split_bf16(o1, h1, l1);
    *(__nv_bfloat162*)(ohi + idx) = __nv_bfloat162(h0, h1);
    *(__nv_bfloat162*)(olo + idx) = __nv_bfloat162(l0, l1);
}

// ---------------- launch ----------------
extern "C" void kernel_launch(void* const* d_in, const int* in_sizes, int n_in,
                              void* d_out, int out_size) {
    const float* x          = (const float*)d_in[0];
    const float* ln1_g      = (const float*)d_in[1];
    const float* ln1_b      = (const float*)d_in[2];
    const float* in_proj_w  = (const float*)d_in[3];
    const float* in_proj_b  = (const float*)d_in[4];
    const float* out_proj_w = (const float*)d_in[5];
    const float* out_proj_b = (const float*)d_in[6];
    const float* ln2_g      = (const float*)d_in[7];
    const float* ln2_b      = (const float*)d_in[8];
    const float* mlp_w1     = (const float*)d_in[9];
    const float* mlp_b1     = (const float*)d_in[10];
    const float* mlp_w2     = (const float*)d_in[11];
    const float* mlp_b2     = (const float*)d_in[12];
    float* out = (float*)d_out;

    float *p_qkv, *p_x1;
    __nv_bfloat16 *p_h_hi, *p_h_lo, *p_at_hi, *p_at_lo, *p_xn_hi, *p_xn_lo, *p_ff_hi, *p_ff_lo;
    __nv_bfloat16 *p_wq_hi, *p_wq_lo, *p_wo_hi, *p_wo_lo, *p_w1_hi, *p_w1_lo, *p_w2_hi, *p_w2_lo;
    cudaGetSymbolAddress((void**)&p_qkv,   g_qkv);
    cudaGetSymbolAddress((void**)&p_x1,    g_x1);
    cudaGetSymbolAddress((void**)&p_h_hi,  g_h_hi);
    cudaGetSymbolAddress((void**)&p_h_lo,  g_h_lo);
    cudaGetSymbolAddress((void**)&p_at_hi, g_at_hi);
    cudaGetSymbolAddress((void**)&p_at_lo, g_at_lo);
    cudaGetSymbolAddress((void**)&p_xn_hi, g_xn_hi);
    cudaGetSymbolAddress((void**)&p_xn_lo, g_xn_lo);
    cudaGetSymbolAddress((void**)&p_ff_hi, g_ff_hi);
    cudaGetSymbolAddress((void**)&p_ff_lo, g_ff_lo);
    cudaGetSymbolAddress((void**)&p_wq_hi, g_wq_hi);
    cudaGetSymbolAddress((void**)&p_wq_lo, g_wq_lo);
    cudaGetSymbolAddress((void**)&p_wo_hi, g_wo_hi);
    cudaGetSymbolAddress((void**)&p_wo_lo, g_wo_lo);
    cudaGetSymbolAddress((void**)&p_w1_hi, g_w1_hi);
    cudaGetSymbolAddress((void**)&p_w1_lo, g_w1_lo);
    cudaGetSymbolAddress((void**)&p_w2_hi, g_w2_hi);
    cudaGetSymbolAddress((void**)&p_w2_lo, g_w2_lo);

    cudaFuncSetAttribute(gemm3, cudaFuncAttributeMaxDynamicSharedMemorySize, GEMM_SMEM);

    // weight splits
    split_kernel<<<(3 * DD * DD) / 1024, 256>>>(in_proj_w,  p_wq_hi, p_wq_lo, 3 * DD * DD);
    split_kernel<<<(DD * DD) / 1024, 256>>>(out_proj_w, p_wo_hi, p_wo_lo, DD * DD);
    split_kernel<<<(DFF * DD) / 1024, 256>>>(mlp_w1, p_w1_hi, p_w1_lo, DFF * DD);
    split_kernel<<<(DD * DFF) / 1024, 256>>>(mlp_w2, p_w2_hi, p_w2_lo, DD * DFF);

    // 1. LN1 -> split
    ln_split_kernel<<<MM, 256>>>(x, ln1_g, ln1_b, p_h_hi, p_h_lo);
    // 2. QKV = h @ W_in^T + b   [4096, 3072]
    gemm3<<<dim3(3 * DD / 128, MM / 128), 256, GEMM_SMEM>>>(
        p_h_hi, p_h_lo, p_wq_hi, p_wq_lo, in_proj_b, nullptr,
        p_qkv, nullptr, nullptr, 3 * DD, DD, 0);
    // 3. windowed attention -> split
    attn_kernel<<<(MM * HH) / 8, 256>>>(p_qkv, p_at_hi, p_at_lo);
    // 4. out proj + residual(x) -> x1 fp32  [4096, 1024]
    gemm3<<<dim3(DD / 128, MM / 128), 256, GEMM_SMEM>>>(
        p_at_hi, p_at_lo, p_wo_hi, p_wo_lo, out_proj_b, x,
        p_x1, nullptr, nullptr, DD, DD, 1);
    // 5. LN2 -> split
    ln_split_kernel<<<MM, 256>>>(p_x1, ln2_g, ln2_b, p_xn_hi, p_xn_lo);
    // 6. MLP up + GELU -> split   [4096, 4096]
    gemm3<<<dim3(DFF / 128, MM / 128), 256, GEMM_SMEM>>>(
        p_xn_hi, p_xn_lo, p_w1_hi, p_w1_lo, mlp_b1, nullptr,
        nullptr, p_ff_hi, p_ff_lo, DFF, DD, 2);
    // 7. MLP down + residual(x1) -> out   [4096, 1024]
    gemm3<<<dim3(DD / 128, MM / 128), 256, GEMM_SMEM>>>(
        p_ff_hi, p_ff_lo, p_w2_hi, p_w2_lo, mlp_b2, p_x1,
        out, nullptr, nullptr, DD, DFF, 1);
}

// round 4
// speedup vs baseline: 2.8204x; 1.1586x over previous
#include <cuda_runtime.h>
#include <cuda_bf16.h>
#include <math.h>
#include <stdint.h>

// Problem constants
#define BB 2
#define SS 2048
#define DD 1024
#define HH 16
#define HD 64
#define WW 16
#define DFF 4096
#define MM (BB * SS)   // 4096 rows

// ---------------- scratch (no allocations allowed) ----------------
__device__ float g_qkv[MM * 3 * DD];          // QKV fp32
__device__ float g_x1[MM * DD];               // residual-1 output fp32
__device__ __nv_bfloat16 g_h_hi[MM * DD],   g_h_lo[MM * DD];     // LN1 out split
__device__ __nv_bfloat16 g_at_hi[MM * DD],  g_at_lo[MM * DD];    // attn out split
__device__ __nv_bfloat16 g_xn_hi[MM * DD],  g_xn_lo[MM * DD];    // LN2 out split
__device__ __nv_bfloat16 g_ff_hi[MM * DFF], g_ff_lo[MM * DFF];   // MLP hidden split
__device__ __nv_bfloat16 g_wq_hi[3 * DD * DD], g_wq_lo[3 * DD * DD];
__device__ __nv_bfloat16 g_wo_hi[DD * DD],     g_wo_lo[DD * DD];
__device__ __nv_bfloat16 g_w1_hi[DFF * DD],    g_w1_lo[DFF * DD];
__device__ __nv_bfloat16 g_w2_hi[DD * DFF],    g_w2_lo[DD * DFF];

__device__ __forceinline__ uint32_t smem_u32(const void* p) {
    return (uint32_t)__cvta_generic_to_shared(p);
}

__device__ __forceinline__ void split_bf16(float v, __nv_bfloat16& hi, __nv_bfloat16& lo) {
    hi = __float2bfloat16(v);
    lo = __float2bfloat16(v - __bfloat162float(hi));
}

__device__ __forceinline__ float gelu_tanh(float x) {
    float x3 = x * x * x;
    return 0.5f * x * (1.0f + tanhf(0.7978845608028654f * (x + 0.044715f * x3)));
}

// ---------------- weight split kernel ----------------
__global__ void split_kernel(const float* __restrict__ in,
                             __nv_bfloat16* __restrict__ hi,
                             __nv_bfloat16* __restrict__ lo, int n) {
    int i = (blockIdx.x * blockDim.x + threadIdx.x) * 4;
    if (i >= n) return;
    float4 v = *(const float4*)(in + i);
    __nv_bfloat16 h0, l0, h1, l1, h2, l2, h3, l3;
    split_bf16(v.x, h0, l0); split_bf16(v.y, h1, l1);
    split_bf16(v.z, h2, l2); split_bf16(v.w, h3, l3);
    *(__nv_bfloat162*)(hi + i)     = __nv_bfloat162(h0, h1);
    *(__nv_bfloat162*)(hi + i + 2) = __nv_bfloat162(h2, h3);
    *(__nv_bfloat162*)(lo + i)     = __nv_bfloat162(l0, l1);
    *(__nv_bfloat162*)(lo + i + 2) = __nv_bfloat162(l2, l3);
}

// ---------------- LayerNorm -> split bf16 ----------------
__global__ void ln_split_kernel(const float* __restrict__ x,
                                const float* __restrict__ g,
                                const float* __restrict__ b,
                                __nv_bfloat16* __restrict__ yhi,
                                __nv_bfloat16* __restrict__ ylo) {
    int row = blockIdx.x;
    const float* xp = x + (size_t)row * DD;
    int i = threadIdx.x * 4;
    float4 xv = *(const float4*)(xp + i);
    float s  = xv.x + xv.y + xv.z + xv.w;
    float ss = xv.x*xv.x + xv.y*xv.y + xv.z*xv.z + xv.w*xv.w;
    for (int o = 16; o > 0; o >>= 1) {
        s  += __shfl_xor_sync(0xffffffffu, s,  o);
        ss += __shfl_xor_sync(0xffffffffu, ss, o);
    }
    __shared__ float sh_s[8], sh_ss[8];
    int wid = threadIdx.x >> 5, lane = threadIdx.x & 31;
    if (lane == 0) { sh_s[wid] = s; sh_ss[wid] = ss; }
    __syncthreads();
    if (wid == 0) {
        s  = (lane < 8) ? sh_s[lane]  : 0.f;
        ss = (lane < 8) ? sh_ss[lane] : 0.f;
        for (int o = 4; o > 0; o >>= 1) {
            s  += __shfl_xor_sync(0xffffffffu, s,  o);
            ss += __shfl_xor_sync(0xffffffffu, ss, o);
        }
        if (lane == 0) { sh_s[0] = s; sh_ss[0] = ss; }
    }
    __syncthreads();
    float mean = sh_s[0] * (1.0f / DD);
    float var  = sh_ss[0] * (1.0f / DD) - mean * mean;
    float inv  = rsqrtf(var + 1e-5f);
    float4 gv = *(const float4*)(g + i);
    float4 bv = *(const float4*)(b + i);
    float o0 = (xv.x - mean) * inv * gv.x + bv.x;
    float o1 = (xv.y - mean) * inv * gv.y + bv.y;
    float o2 = (xv.z - mean) * inv * gv.z + bv.z;
    float o3 = (xv.w - mean) * inv * gv.w + bv.w;
    __nv_bfloat16 h0, l0, h1, l1, h2, l2, h3, l3;
    split_bf16(o0, h0, l0); split_bf16(o1, h1, l1);
    split_bf16(o2, h2, l2); split_bf16(o3, h3, l3);
    size_t idx = (size_t)row * DD + i;
    *(__nv_bfloat162*)(yhi + idx)     = __nv_bfloat162(h0, h1);
    *(__nv_bfloat162*)(yhi + idx + 2) = __nv_bfloat162(h2, h3);
    *(__nv_bfloat162*)(ylo + idx)     = __nv_bfloat162(l0, l1);
    *(__nv_bfloat162*)(ylo + idx + 2) = __nv_bfloat162(l2, l3);
}

// ---------------- mma.sync split-bf16 GEMM: C[M,N] = A[M,K] @ Bw[N,K]^T (+epi) ----------------
// epi: 0 = fp32 +bias ; 1 = fp32 +bias+res ; 2 = gelu(+bias) -> split bf16
#define BKT 32
#define PADE 8
#define LROW (BKT + PADE)               // 40 bf16 per smem row
#define TILE_BYTES (128 * LROW * 2)     // 10240
#define OFF_AH 0
#define OFF_AL TILE_BYTES
#define OFF_BH (2 * TILE_BYTES)
#define OFF_BL (3 * TILE_BYTES)
#define STAGE_BYTES (4 * TILE_BYTES)    // 40960
#define GEMM_SMEM (2 * STAGE_BYTES)     // 81920

#define LDMX4(r0, r1, r2, r3, addr) \
    asm volatile("ldmatrix.sync.aligned.m8n8.x4.shared.b16 {%0,%1,%2,%3}, [%4];" \
                 : "=r"(r0), "=r"(r1), "=r"(r2), "=r"(r3) : "r"(addr))

#define MMA_BF16(d, a, b0, b1) \
    asm volatile("mma.sync.aligned.m16n8k16.row.col.f32.bf16.bf16.f32 " \
                 "{%0,%1,%2,%3}, {%4,%5,%6,%7}, {%8,%9}, {%0,%1,%2,%3};" \
                 : "+f"((d)[0]), "+f"((d)[1]), "+f"((d)[2]), "+f"((d)[3]) \
                 : "r"((a)[0]), "r"((a)[1]), "r"((a)[2]), "r"((a)[3]), "r"(b0), "r"(b1))

__device__ __forceinline__ void load_tile(const __nv_bfloat16* __restrict__ g,
                                          int ldk, int row0, int k0,
                                          uint32_t sbase, int tid) {
    #pragma unroll
    for (int j = 0; j < 2; j++) {
        int ch = tid + 256 * j;          // 0..511
        int r = ch >> 2;
        int c = ch & 3;
        const void* gp = g + (size_t)(row0 + r) * ldk + k0 + c * 8;
        uint32_t sa = sbase + r * (LROW * 2) + c * 16;
        asm volatile("cp.async.cg.shared.global [%0], [%1], 16;" :: "r"(sa), "l"(gp) : "memory");
    }
}

__global__ __launch_bounds__(256, 2)
void gemm3(const __nv_bfloat16* __restrict__ Ahi, const __nv_bfloat16* __restrict__ Alo,
           const __nv_bfloat16* __restrict__ Bhi, const __nv_bfloat16* __restrict__ Blo,
           const float* __restrict__ bias, const float* __restrict__ res,
           float* __restrict__ outF,
           __nv_bfloat16* __restrict__ outHi, __nv_bfloat16* __restrict__ outLo,
           int Nn, int Kk, int epi) {
    extern __shared__ __align__(16) char dsm[];
    uint32_t sbase = smem_u32(dsm);
    int tid = threadIdx.x;
    int lane = tid & 31;
    int wid = tid >> 5;
    int wr = wid & 1;      // warp row: m offset wr*64
    int wc = wid >> 1;     // warp col: n offset wc*32
    int bm = blockIdx.y * 128;
    int bn = blockIdx.x * 128;

    float acc[4][4][4];
    #pragma unroll
    for (int mi = 0; mi < 4; mi++)
        #pragma unroll
        for (int ni = 0; ni < 4; ni++)
            #pragma unroll
            for (int q = 0; q < 4; q++) acc[mi][ni][q] = 0.f;

    const int NC = Kk >> 5;   // BKT=32 chunks

    // prologue
    load_tile(Ahi, Kk, bm, 0, sbase + OFF_AH, tid);
    load_tile(Alo, Kk, bm, 0, sbase + OFF_AL, tid);
    load_tile(Bhi, Kk, bn, 0, sbase + OFF_BH, tid);
    load_tile(Blo, Kk, bn, 0, sbase + OFF_BL, tid);
    asm volatile("cp.async.commit_group;" ::: "memory");

    // per-thread ldmatrix address components (element units)
    int a_row = wr * 64 + (lane & 15);
    int a_colsel = (lane >> 4) << 3;            // 0 or 8
    int b_row = wc * 32 + (lane & 7) + ((lane >> 4) & 1) * 8;
    int b_colsel = ((lane >> 3) & 1) * 8;       // 0 or 8

    for (int c = 0; c < NC; c++) {
        if (c + 1 < NC) {
            uint32_t st = sbase + ((c + 1) & 1) * STAGE_BYTES;
            int k0 = (c + 1) << 5;
            load_tile(Ahi, Kk, bm, k0, st + OFF_AH, tid);
            load_tile(Alo, Kk, bm, k0, st + OFF_AL, tid);
            load_tile(Bhi, Kk, bn, k0, st + OFF_BH, tid);
            load_tile(Blo, Kk, bn, k0, st + OFF_BL, tid);
            asm volatile("cp.async.commit_group;" ::: "memory");
            asm volatile("cp.async.wait_group 1;" ::: "memory");
        } else {
            asm volatile("cp.async.wait_group 0;" ::: "memory");
        }
        __syncthreads();

        uint32_t st = sbase + (c & 1) * STAGE_BYTES;
        #pragma unroll
        for (int kk = 0; kk < 2; kk++) {
            int kb = kk * 16;
            // B fragments for this k-slice (live across the mi loop)
            uint32_t bh[8], bl[8];
            #pragma unroll
            for (int g = 0; g < 2; g++) {
                uint32_t off = ((b_row + g * 16) * LROW + kb + b_colsel) * 2;
                LDMX4(bh[g*4+0], bh[g*4+1], bh[g*4+2], bh[g*4+3], st + OFF_BH + off);
                LDMX4(bl[g*4+0], bl[g*4+1], bl[g*4+2], bl[g*4+3], st + OFF_BL + off);
            }
            // A fragments loaded per-mi to cap register pressure
            #pragma unroll
            for (int mi = 0; mi < 4; mi++) {
                uint32_t ah[4], al[4];
                uint32_t off = ((a_row + mi * 16) * LROW + kb + a_colsel) * 2;
                LDMX4(ah[0], ah[1], ah[2], ah[3], st + OFF_AH + off);
                LDMX4(al[0], al[1], al[2], al[3], st + OFF_AL + off);
                #pragma unroll
                for (int ni = 0; ni < 4; ni++) {
                    MMA_BF16(acc[mi][ni], ah, bh[ni*2], bh[ni*2+1]);
                    MMA_BF16(acc[mi][ni], ah, bl[ni*2], bl[ni*2+1]);
                    MMA_BF16(acc[mi][ni], al, bh[ni*2], bh[ni*2+1]);
                }
            }
        }
        __syncthreads();
    }

    // epilogue
    int m0 = bm + wr * 64 + (lane >> 2);
    int n0 = bn + wc * 32 + (lane & 3) * 2;
    #pragma unroll
    for (int mi = 0; mi < 4; mi++) {
        #pragma unroll
        for (int r2 = 0; r2 < 2; r2++) {
            int row = m0 + mi * 16 + r2 * 8;
            size_t rbase = (size_t)row * Nn;
            #pragma unroll
            for (int ni = 0; ni < 4; ni++) {
                int col = n0 + ni * 8;
                float v0 = acc[mi][ni][r2*2+0] + bias[col];
                float v1 = acc[mi][ni][r2*2+1] + bias[col+1];
                if (epi == 0) {
                    *(float2*)(outF + rbase + col) = make_float2(v0, v1);
                } else if (epi == 1) {
                    float2 rv = *(const float2*)(res + rbase + col);
                    *(float2*)(outF + rbase + col) = make_float2(v0 + rv.x, v1 + rv.y);
                } else {
                    v0 = gelu_tanh(v0); v1 = gelu_tanh(v1);
                    __nv_bfloat16 h0, l0, h1, l1;
                    split_bf16(v0, h0, l0); split_bf16(v1, h1, l1);
                    *(__nv_bfloat162*)(outHi + rbase + col) = __nv_bfloat162(h0, h1);
                    *(__nv_bfloat162*)(outLo + rbase + col) = __nv_bfloat162(l0, l1);
                }
            }
        }
    }
}

// ---------------- Sliding-window causal attention (W=16) -> split bf16 ----------------
__global__ void attn_kernel(const float* __restrict__ qkv,
                            __nv_bfloat16* __restrict__ ohi,
                            __nv_bfloat16* __restrict__ olo) {
    int gwarp = (blockIdx.x * blockDim.x + threadIdx.x) >> 5;
    int lane = threadIdx.x & 31;
    if (gwarp >= MM * HH) return;
    int m = gwarp / HH;
    int h = gwarp % HH;
    int s = m & (SS - 1);

    const float* qp = qkv + (size_t)m * (3 * DD) + h * HD;
    float score = -INFINITY;
    if (lane < WW && lane <= s) {
        const float* kp = qkv + (size_t)(m - lane) * (3 * DD) + DD + h * HD;
        float acc = 0.f;
        #pragma unroll
        for (int d = 0; d < HD; d += 4) {
            float4 qa = *(const float4*)(qp + d);
            float4 ka = *(const float4*)(kp + d);
            acc = fmaf(qa.x, ka.x, acc);
            acc = fmaf(qa.y, ka.y, acc);
            acc = fmaf(qa.z, ka.z, acc);
            acc = fmaf(qa.w, ka.w, acc);
        }
        score = acc * 0.125f;
    }
    float mx = score;
    for (int o = 16; o > 0; o >>= 1) mx = fmaxf(mx, __shfl_xor_sync(0xffffffffu, mx, o));
    float p = (score == -INFINITY) ? 0.f : __expf(score - mx);
    float sum = p;
    for (int o = 16; o > 0; o >>= 1) sum += __shfl_xor_sync(0xffffffffu, sum, o);
    float inv = 1.f / sum;

    int d = lane * 2;
    float o0 = 0.f, o1 = 0.f;
    int jmax = min(WW - 1, s);
    for (int jj = 0; jj <= jmax; jj++) {
        float pj = __shfl_sync(0xffffffffu, p, jj);
        const float* vp = qkv + (size_t)(m - jj) * (3 * DD) + 2 * DD + h * HD + d;
        o0 = fmaf(pj, vp[0], o0);
        o1 = fmaf(pj, vp[1], o1);
    }
    o0 *= inv; o1 *= inv;
    size_t idx = (size_t)m * DD + h * HD + d;
    __nv_bfloat16 h0, l0, h1, l1;
    split_bf16(o0, h0, l0); split_bf16(o1, h1, l1);
    *(__nv_bfloat162*)(ohi + idx) = __nv_bfloat162(h0, h1);
    *(__nv_bfloat162*)(olo + idx) = __nv_bfloat162(l0, l1);
}

// ---------------- launch ----------------
extern "C" void kernel_launch(void* const* d_in, const int* in_sizes, int n_in,
                              void* d_out, int out_size) {
    const float* x          = (const float*)d_in[0];
    const float* ln1_g      = (const float*)d_in[1];
    const float* ln1_b      = (const float*)d_in[2];
    const float* in_proj_w  = (const float*)d_in[3];
    const float* in_proj_b  = (const float*)d_in[4];
    const float* out_proj_w = (const float*)d_in[5];
    const float* out_proj_b = (const float*)d_in[6];
    const float* ln2_g      = (const float*)d_in[7];
    const float* ln2_b      = (const float*)d_in[8];
    const float* mlp_w1     = (const float*)d_in[9];
    const float* mlp_b1     = (const float*)d_in[10];
    const float* mlp_w2     = (const float*)d_in[11];
    const float* mlp_b2     = (const float*)d_in[12];
    float* out = (float*)d_out;

    float *p_qkv, *p_x1;
    __nv_bfloat16 *p_h_hi, *p_h_lo, *p_at_hi, *p_at_lo, *p_xn_hi, *p_xn_lo, *p_ff_hi, *p_ff_lo;
    __nv_bfloat16 *p_wq_hi, *p_wq_lo, *p_wo_hi, *p_wo_lo, *p_w1_hi, *p_w1_lo, *p_w2_hi, *p_w2_lo;
    cudaGetSymbolAddress((void**)&p_qkv,   g_qkv);
    cudaGetSymbolAddress((void**)&p_x1,    g_x1);
    cudaGetSymbolAddress((void**)&p_h_hi,  g_h_hi);
    cudaGetSymbolAddress((void**)&p_h_lo,  g_h_lo);
    cudaGetSymbolAddress((void**)&p_at_hi, g_at_hi);
    cudaGetSymbolAddress((void**)&p_at_lo, g_at_lo);
    cudaGetSymbolAddress((void**)&p_xn_hi, g_xn_hi);
    cudaGetSymbolAddress((void**)&p_xn_lo, g_xn_lo);
    cudaGetSymbolAddress((void**)&p_ff_hi, g_ff_hi);
    cudaGetSymbolAddress((void**)&p_ff_lo, g_ff_lo);
    cudaGetSymbolAddress((void**)&p_wq_hi, g_wq_hi);
    cudaGetSymbolAddress((void**)&p_wq_lo, g_wq_lo);
    cudaGetSymbolAddress((void**)&p_wo_hi, g_wo_hi);
    cudaGetSymbolAddress((void**)&p_wo_lo, g_wo_lo);
    cudaGetSymbolAddress((void**)&p_w1_hi, g_w1_hi);
    cudaGetSymbolAddress((void**)&p_w1_lo, g_w1_lo);
    cudaGetSymbolAddress((void**)&p_w2_hi, g_w2_hi);
    cudaGetSymbolAddress((void**)&p_w2_lo, g_w2_lo);

    cudaFuncSetAttribute(gemm3, cudaFuncAttributeMaxDynamicSharedMemorySize, GEMM_SMEM);

    // interleaved order (also improves odds ncu -s 5 samples a gemm)
    split_kernel<<<(3 * DD * DD) / 1024, 256>>>(in_proj_w,  p_wq_hi, p_wq_lo, 3 * DD * DD);
    ln_split_kernel<<<MM, 256>>>(x, ln1_g, ln1_b, p_h_hi, p_h_lo);
    // QKV = h @ W_in^T + b   [4096, 3072]
    gemm3<<<dim3(3 * DD / 128, MM / 128), 256, GEMM_SMEM>>>(
        p_h_hi, p_h_lo, p_wq_hi, p_wq_lo, in_proj_b, nullptr,
        p_qkv, nullptr, nullptr, 3 * DD, DD, 0);
    // windowed attention -> split
    attn_kernel<<<(MM * HH) / 8, 256>>>(p_qkv, p_at_hi, p_at_lo);
    split_kernel<<<(DD * DD) / 1024, 256>>>(out_proj_w, p_wo_hi, p_wo_lo, DD * DD);
    // out proj + residual(x) -> x1 fp32  [4096, 1024]
    gemm3<<<dim3(DD / 128, MM / 128), 256, GEMM_SMEM>>>(
        p_at_hi, p_at_lo, p_wo_hi, p_wo_lo, out_proj_b, x,
        p_x1, nullptr, nullptr, DD, DD, 1);
    // LN2 -> split
    ln_split_kernel<<<MM, 256>>>(p_x1, ln2_g, ln2_b, p_xn_hi, p_xn_lo);
    split_kernel<<<(DFF * DD) / 1024, 256>>>(mlp_w1, p_w1_hi, p_w1_lo, DFF * DD);
    // MLP up + GELU -> split   [4096, 4096]
    gemm3<<<dim3(DFF / 128, MM / 128), 256, GEMM_SMEM>>>(
        p_xn_hi, p_xn_lo, p_w1_hi, p_w1_lo, mlp_b1, nullptr,
        nullptr, p_ff_hi, p_ff_lo, DFF, DD, 2);
    split_kernel<<<(DD * DFF) / 1024, 256>>>(mlp_w2, p_w2_hi, p_w2_lo, DD * DFF);
    // MLP down + residual(x1) -> out   [4096, 1024]
    gemm3<<<dim3(DD / 128, MM / 128), 256, GEMM_SMEM>>>(
        p_ff_hi, p_ff_lo, p_w2_hi, p_w2_lo, mlp_b2, p_x1,
        out, nullptr, nullptr, DD, DFF, 1);
}

// round 5
// speedup vs baseline: 2.8712x; 1.0180x over previous
#include <cuda_runtime.h>
#include <cuda_bf16.h>
#include <math.h>
#include <stdint.h>

// Problem constants
#define BB 2
#define SS 2048
#define DD 1024
#define HH 16
#define HD 64
#define WW 16
#define DFF 4096
#define MM (BB * SS)   // 4096 rows

// ---------------- scratch (no allocations allowed) ----------------
__device__ float g_qkv[MM * 3 * DD];          // QKV fp32
__device__ float g_x1[MM * DD];               // residual-1 output fp32
__device__ __nv_bfloat16 g_h_hi[MM * DD],   g_h_lo[MM * DD];     // LN1 out split
__device__ __nv_bfloat16 g_at_hi[MM * DD],  g_at_lo[MM * DD];    // attn out split
__device__ __nv_bfloat16 g_xn_hi[MM * DD],  g_xn_lo[MM * DD];    // LN2 out split
__device__ __nv_bfloat16 g_ff_hi[MM * DFF], g_ff_lo[MM * DFF];   // MLP hidden split
__device__ __nv_bfloat16 g_wq_hi[3 * DD * DD], g_wq_lo[3 * DD * DD];
__device__ __nv_bfloat16 g_wo_hi[DD * DD],     g_wo_lo[DD * DD];
__device__ __nv_bfloat16 g_w1_hi[DFF * DD],    g_w1_lo[DFF * DD];
__device__ __nv_bfloat16 g_w2_hi[DD * DFF],    g_w2_lo[DD * DFF];

__device__ __forceinline__ uint32_t smem_u32(const void* p) {
    return (uint32_t)__cvta_generic_to_shared(p);
}

__device__ __forceinline__ void split_bf16(float v, __nv_bfloat16& hi, __nv_bfloat16& lo) {
    hi = __float2bfloat16(v);
    lo = __float2bfloat16(v - __bfloat162float(hi));
}

__device__ __forceinline__ float gelu_tanh(float x) {
    float x3 = x * x * x;
    return 0.5f * x * (1.0f + tanhf(0.7978845608028654f * (x + 0.044715f * x3)));
}

// ---------------- weight split kernel ----------------
__global__ void split_kernel(const float* __restrict__ in,
                             __nv_bfloat16* __restrict__ hi,
                             __nv_bfloat16* __restrict__ lo, int n) {
    int i = (blockIdx.x * blockDim.x + threadIdx.x) * 4;
    if (i >= n) return;
    float4 v = *(const float4*)(in + i);
    __nv_bfloat16 h0, l0, h1, l1, h2, l2, h3, l3;
    split_bf16(v.x, h0, l0); split_bf16(v.y, h1, l1);
    split_bf16(v.z, h2, l2); split_bf16(v.w, h3, l3);
    *(__nv_bfloat162*)(hi + i)     = __nv_bfloat162(h0, h1);
    *(__nv_bfloat162*)(hi + i + 2) = __nv_bfloat162(h2, h3);
    *(__nv_bfloat162*)(lo + i)     = __nv_bfloat162(l0, l1);
    *(__nv_bfloat162*)(lo + i + 2) = __nv_bfloat162(l2, l3);
}

// ---------------- LayerNorm -> split bf16 ----------------
__global__ void ln_split_kernel(const float* __restrict__ x,
                                const float* __restrict__ g,
                                const float* __restrict__ b,
                                __nv_bfloat16* __restrict__ yhi,
                                __nv_bfloat16* __restrict__ ylo) {
    int row = blockIdx.x;
    const float* xp = x + (size_t)row * DD;
    int i = threadIdx.x * 4;
    float4 xv = *(const float4*)(xp + i);
    float s  = xv.x + xv.y + xv.z + xv.w;
    float ss = xv.x*xv.x + xv.y*xv.y + xv.z*xv.z + xv.w*xv.w;
    for (int o = 16; o > 0; o >>= 1) {
        s  += __shfl_xor_sync(0xffffffffu, s,  o);
        ss += __shfl_xor_sync(0xffffffffu, ss, o);
    }
    __shared__ float sh_s[8], sh_ss[8];
    int wid = threadIdx.x >> 5, lane = threadIdx.x & 31;
    if (lane == 0) { sh_s[wid] = s; sh_ss[wid] = ss; }
    __syncthreads();
    if (wid == 0) {
        s  = (lane < 8) ? sh_s[lane]  : 0.f;
        ss = (lane < 8) ? sh_ss[lane] : 0.f;
        for (int o = 4; o > 0; o >>= 1) {
            s  += __shfl_xor_sync(0xffffffffu, s,  o);
            ss += __shfl_xor_sync(0xffffffffu, ss, o);
        }
        if (lane == 0) { sh_s[0] = s; sh_ss[0] = ss; }
    }
    __syncthreads();
    float mean = sh_s[0] * (1.0f / DD);
    float var  = sh_ss[0] * (1.0f / DD) - mean * mean;
    float inv  = rsqrtf(var + 1e-5f);
    float4 gv = *(const float4*)(g + i);
    float4 bv = *(const float4*)(b + i);
    float o0 = (xv.x - mean) * inv * gv.x + bv.x;
    float o1 = (xv.y - mean) * inv * gv.y + bv.y;
    float o2 = (xv.z - mean) * inv * gv.z + bv.z;
    float o3 = (xv.w - mean) * inv * gv.w + bv.w;
    __nv_bfloat16 h0, l0, h1, l1, h2, l2, h3, l3;
    split_bf16(o0, h0, l0); split_bf16(o1, h1, l1);
    split_bf16(o2, h2, l2); split_bf16(o3, h3, l3);
    size_t idx = (size_t)row * DD + i;
    *(__nv_bfloat162*)(yhi + idx)     = __nv_bfloat162(h0, h1);
    *(__nv_bfloat162*)(yhi + idx + 2) = __nv_bfloat162(h2, h3);
    *(__nv_bfloat162*)(ylo + idx)     = __nv_bfloat162(l0, l1);
    *(__nv_bfloat162*)(ylo + idx + 2) = __nv_bfloat162(l2, l3);
}

// ---------------- mma.sync split-bf16 GEMM: C[M,N] = A[M,K] @ Bw[N,K]^T (+epi) ----------------
// epi: 0 = fp32 +bias ; 1 = fp32 +bias+res ; 2 = gelu(+bias) -> split bf16
#define BKT 32
#define PADE 8
#define LROW (BKT + PADE)               // 40 bf16 per smem row
#define TILE_BYTES (128 * LROW * 2)     // 10240
#define OFF_AH 0
#define OFF_AL TILE_BYTES
#define OFF_BH (2 * TILE_BYTES)
#define OFF_BL (3 * TILE_BYTES)
#define STAGE_BYTES (4 * TILE_BYTES)    // 40960
#define GEMM_SMEM (2 * STAGE_BYTES)     // 81920

#define LDMX4(r0, r1, r2, r3, addr) \
    asm volatile("ldmatrix.sync.aligned.m8n8.x4.shared.b16 {%0,%1,%2,%3}, [%4];" \
                 : "=r"(r0), "=r"(r1), "=r"(r2), "=r"(r3) : "r"(addr))

#define MMA_BF16(d, a, b0, b1) \
    asm volatile("mma.sync.aligned.m16n8k16.row.col.f32.bf16.bf16.f32 " \
                 "{%0,%1,%2,%3}, {%4,%5,%6,%7}, {%8,%9}, {%0,%1,%2,%3};" \
                 : "+f"((d)[0]), "+f"((d)[1]), "+f"((d)[2]), "+f"((d)[3]) \
                 : "r"((a)[0]), "r"((a)[1]), "r"((a)[2]), "r"((a)[3]), "r"(b0), "r"(b1))

__device__ __forceinline__ void load_tile(const __nv_bfloat16* __restrict__ g,
                                          int ldk, int row0, int k0,
                                          uint32_t sbase, int tid) {
    #pragma unroll
    for (int j = 0; j < 2; j++) {
        int ch = tid + 256 * j;          // 0..511
        int r = ch >> 2;
        int c = ch & 3;
        const void* gp = g + (size_t)(row0 + r) * ldk + k0 + c * 8;
        uint32_t sa = sbase + r * (LROW * 2) + c * 16;
        asm volatile("cp.async.cg.shared.global [%0], [%1], 16;" :: "r"(sa), "l"(gp) : "memory");
    }
}

__global__ __launch_bounds__(256, 2)
void gemm3(const __nv_bfloat16* __restrict__ Ahi, const __nv_bfloat16* __restrict__ Alo,
           const __nv_bfloat16* __restrict__ Bhi, const __nv_bfloat16* __restrict__ Blo,
           const float* __restrict__ bias, const float* __restrict__ res,
           float* __restrict__ outF,
           __nv_bfloat16* __restrict__ outHi, __nv_bfloat16* __restrict__ outLo,
           int Nn, int Kk, int epi) {
    extern __shared__ __align__(16) char dsm[];
    uint32_t sbase = smem_u32(dsm);
    int tid = threadIdx.x;
    int lane = tid & 31;
    int wid = tid >> 5;
    int wr = wid & 1;      // warp row: m offset wr*64
    int wc = wid >> 1;     // warp col: n offset wc*32
    int bm = blockIdx.y * 128;
    int bn = blockIdx.x * 128;

    float acc[4][4][4];
    #pragma unroll
    for (int mi = 0; mi < 4; mi++)
        #pragma unroll
        for (int ni = 0; ni < 4; ni++)
            #pragma unroll
            for (int q = 0; q < 4; q++) acc[mi][ni][q] = 0.f;

    const int NC = Kk >> 5;   // BKT=32 chunks

    // prologue
    load_tile(Ahi, Kk, bm, 0, sbase + OFF_AH, tid);
    load_tile(Alo, Kk, bm, 0, sbase + OFF_AL, tid);
    load_tile(Bhi, Kk, bn, 0, sbase + OFF_BH, tid);
    load_tile(Blo, Kk, bn, 0, sbase + OFF_BL, tid);
    asm volatile("cp.async.commit_group;" ::: "memory");

    // per-thread ldmatrix address components (element units)
    int a_row = wr * 64 + (lane & 15);
    int a_colsel = (lane >> 4) << 3;            // 0 or 8
    int b_row = wc * 32 + (lane & 7) + ((lane >> 4) & 1) * 8;
    int b_colsel = ((lane >> 3) & 1) * 8;       // 0 or 8

    for (int c = 0; c < NC; c++) {
        if (c + 1 < NC) {
            uint32_t st = sbase + ((c + 1) & 1) * STAGE_BYTES;
            int k0 = (c + 1) << 5;
            load_tile(Ahi, Kk, bm, k0, st + OFF_AH, tid);
            load_tile(Alo, Kk, bm, k0, st + OFF_AL, tid);
            load_tile(Bhi, Kk, bn, k0, st + OFF_BH, tid);
            load_tile(Blo, Kk, bn, k0, st + OFF_BL, tid);
            asm volatile("cp.async.commit_group;" ::: "memory");
            asm volatile("cp.async.wait_group 1;" ::: "memory");
        } else {
            asm volatile("cp.async.wait_group 0;" ::: "memory");
        }
        __syncthreads();

        uint32_t st = sbase + (c & 1) * STAGE_BYTES;
        #pragma unroll
        for (int kk = 0; kk < 2; kk++) {
            int kb = kk * 16;
            // B fragments for this k-slice (live across the mi loop)
            uint32_t bh[8], bl[8];
            #pragma unroll
            for (int g = 0; g < 2; g++) {
                uint32_t off = ((b_row + g * 16) * LROW + kb + b_colsel) * 2;
                LDMX4(bh[g*4+0], bh[g*4+1], bh[g*4+2], bh[g*4+3], st + OFF_BH + off);
                LDMX4(bl[g*4+0], bl[g*4+1], bl[g*4+2], bl[g*4+3], st + OFF_BL + off);
            }
            // A fragments loaded per-mi to cap register pressure
            #pragma unroll
            for (int mi = 0; mi < 4; mi++) {
                uint32_t ah[4], al[4];
                uint32_t off = ((a_row + mi * 16) * LROW + kb + a_colsel) * 2;
                LDMX4(ah[0], ah[1], ah[2], ah[3], st + OFF_AH + off);
                LDMX4(al[0], al[1], al[2], al[3], st + OFF_AL + off);
                #pragma unroll
                for (int ni = 0; ni < 4; ni++) {
                    MMA_BF16(acc[mi][ni], ah, bh[ni*2], bh[ni*2+1]);
                    MMA_BF16(acc[mi][ni], ah, bl[ni*2], bl[ni*2+1]);
                    MMA_BF16(acc[mi][ni], al, bh[ni*2], bh[ni*2+1]);
                }
            }
        }
        __syncthreads();
    }

    // epilogue
    int m0 = bm + wr * 64 + (lane >> 2);
    int n0 = bn + wc * 32 + (lane & 3) * 2;
    #pragma unroll
    for (int mi = 0; mi < 4; mi++) {
        #pragma unroll
        for (int r2 = 0; r2 < 2; r2++) {
            int row = m0 + mi * 16 + r2 * 8;
            size_t rbase = (size_t)row * Nn;
            #pragma unroll
            for (int ni = 0; ni < 4; ni++) {
                int col = n0 + ni * 8;
                float v0 = acc[mi][ni][r2*2+0] + bias[col];
                float v1 = acc[mi][ni][r2*2+1] + bias[col+1];
                if (epi == 0) {
                    *(float2*)(outF + rbase + col) = make_float2(v0, v1);
                } else if (epi == 1) {
                    float2 rv = *(const float2*)(res + rbase + col);
                    *(float2*)(outF + rbase + col) = make_float2(v0 + rv.x, v1 + rv.y);
                } else {
                    v0 = gelu_tanh(v0); v1 = gelu_tanh(v1);
                    __nv_bfloat16 h0, l0, h1, l1;
                    split_bf16(v0, h0, l0); split_bf16(v1, h1, l1);
                    *(__nv_bfloat162*)(outHi + rbase + col) = __nv_bfloat162(h0, h1);
                    *(__nv_bfloat162*)(outLo + rbase + col) = __nv_bfloat162(l0, l1);
                }
            }
        }
    }
}

// ---------------- Sliding-window causal attention (W=16), smem-tiled ----------------
// One CTA per (query tile of 128, head, batch). K/V rows staged in smem.
#define TQ 128
#define KR (TQ + WW - 1)     // 143 key rows
#define PK 68                // padded floats per smem row (float4-friendly, 2-way max conflict)
#define ATTN_SMEM (2 * 144 * PK * 4)   // 78336 bytes

__global__ __launch_bounds__(256)
void attn_kernel(const float* __restrict__ qkv,
                 __nv_bfloat16* __restrict__ ohi,
                 __nv_bfloat16* __restrict__ olo) {
    extern __shared__ __align__(16) float asm_f[];
    float* Ks = asm_f;                 // [144][PK]
    float* Vs = asm_f + 144 * PK;      // [144][PK]

    int tile = blockIdx.x;
    int h = blockIdx.y;
    int b = blockIdx.z;
    int s0 = tile * TQ;
    int tid = threadIdx.x;
    int lane = tid & 31;
    int w = tid >> 5;

    // cooperative load of K/V rows [s0-15, s0+127] -> smem rows 0..142
    for (int i = tid; i < KR * (HD / 4); i += 256) {
        int r = i >> 4;                // row 0..142
        int c = (i & 15) * 4;          // dim 0..60
        int seq = s0 - (WW - 1) + r;
        if (seq >= 0) {
            size_t base = ((size_t)(b * SS + seq)) * (3 * DD) + h * HD + c;
            *(float4*)&Ks[r * PK + c] = *(const float4*)(qkv + base + DD);
            *(float4*)&Vs[r * PK + c] = *(const float4*)(qkv + base + 2 * DD);
        }
    }
    __syncthreads();

    // each warp handles 16 queries
    for (int qq = 0; qq < 16; qq++) {
        int qi = w * 16 + qq;          // local query 0..127
        int s = s0 + qi;               // global seq
        int m = b * SS + s;
        const float* qp = qkv + (size_t)m * (3 * DD) + h * HD;

        float score = -INFINITY;
        if (lane < WW && lane <= s) {
            const float* kp = &Ks[(qi + WW - 1 - lane) * PK];
            float acc = 0.f;
            #pragma unroll
            for (int d = 0; d < HD; d += 4) {
                float4 qa = *(const float4*)(qp + d);
                float4 ka = *(const float4*)(kp + d);
                acc = fmaf(qa.x, ka.x, acc);
                acc = fmaf(qa.y, ka.y, acc);
                acc = fmaf(qa.z, ka.z, acc);
                acc = fmaf(qa.w, ka.w, acc);
            }
            score = acc * 0.125f;
        }
        float mx = score;
        for (int o = 16; o > 0; o >>= 1) mx = fmaxf(mx, __shfl_xor_sync(0xffffffffu, mx, o));
        float p = (score == -INFINITY) ? 0.f : __expf(score - mx);
        float sum = p;
        for (int o = 16; o > 0; o >>= 1) sum += __shfl_xor_sync(0xffffffffu, sum, o);
        float inv = 1.f / sum;

        // V accumulation: lane owns dims 2*lane, 2*lane+1
        float o0 = 0.f, o1 = 0.f;
        int jmax = min(WW - 1, s);
        for (int jj = 0; jj <= jmax; jj++) {
            float pj = __shfl_sync(0xffffffffu, p, jj);
            float2 vv = *(const float2*)&Vs[(qi + WW - 1 - jj) * PK + 2 * lane];
            o0 = fmaf(pj, vv.x, o0);
            o1 = fmaf(pj, vv.y, o1);
        }
        o0 *= inv; o1 *= inv;
        size_t idx = (size_t)m * DD + h * HD + 2 * lane;
        __nv_bfloat16 h0, l0, h1, l1;
        split_bf16(o0, h0, l0); split_bf16(o1, h1, l1);
        *(__nv_bfloat162*)(ohi + idx) = __nv_bfloat162(h0, h1);
        *(__nv_bfloat162*)(olo + idx) = __nv_bfloat162(l0, l1);
    }
}

// ---------------- launch ----------------
extern "C" void kernel_launch(void* const* d_in, const int* in_sizes, int n_in,
                              void* d_out, int out_size) {
    const float* x          = (const float*)d_in[0];
    const float* ln1_g      = (const float*)d_in[1];
    const float* ln1_b      = (const float*)d_in[2];
    const float* in_proj_w  = (const float*)d_in[3];
    const float* in_proj_b  = (const float*)d_in[4];
    const float* out_proj_w = (const float*)d_in[5];
    const float* out_proj_b = (const float*)d_in[6];
    const float* ln2_g      = (const float*)d_in[7];
    const float* ln2_b      = (const float*)d_in[8];
    const float* mlp_w1     = (const float*)d_in[9];
    const float* mlp_b1     = (const float*)d_in[10];
    const float* mlp_w2     = (const float*)d_in[11];
    const float* mlp_b2     = (const float*)d_in[12];
    float* out = (float*)d_out;

    float *p_qkv, *p_x1;
    __nv_bfloat16 *p_h_hi, *p_h_lo, *p_at_hi, *p_at_lo, *p_xn_hi, *p_xn_lo, *p_ff_hi, *p_ff_lo;
    __nv_bfloat16 *p_wq_hi, *p_wq_lo, *p_wo_hi, *p_wo_lo, *p_w1_hi, *p_w1_lo, *p_w2_hi, *p_w2_lo;
    cudaGetSymbolAddress((void**)&p_qkv,   g_qkv);
    cudaGetSymbolAddress((void**)&p_x1,    g_x1);
    cudaGetSymbolAddress((void**)&p_h_hi,  g_h_hi);
    cudaGetSymbolAddress((void**)&p_h_lo,  g_h_lo);
    cudaGetSymbolAddress((void**)&p_at_hi, g_at_hi);
    cudaGetSymbolAddress((void**)&p_at_lo, g_at_lo);
    cudaGetSymbolAddress((void**)&p_xn_hi, g_xn_hi);
    cudaGetSymbolAddress((void**)&p_xn_lo, g_xn_lo);
    cudaGetSymbolAddress((void**)&p_ff_hi, g_ff_hi);
    cudaGetSymbolAddress((void**)&p_ff_lo, g_ff_lo);
    cudaGetSymbolAddress((void**)&p_wq_hi, g_wq_hi);
    cudaGetSymbolAddress((void**)&p_wq_lo, g_wq_lo);
    cudaGetSymbolAddress((void**)&p_wo_hi, g_wo_hi);
    cudaGetSymbolAddress((void**)&p_wo_lo, g_wo_lo);
    cudaGetSymbolAddress((void**)&p_w1_hi, g_w1_hi);
    cudaGetSymbolAddress((void**)&p_w1_lo, g_w1_lo);
    cudaGetSymbolAddress((void**)&p_w2_hi, g_w2_hi);
    cudaGetSymbolAddress((void**)&p_w2_lo, g_w2_lo);

    cudaFuncSetAttribute(gemm3, cudaFuncAttributeMaxDynamicSharedMemorySize, GEMM_SMEM);
    cudaFuncSetAttribute(attn_kernel, cudaFuncAttributeMaxDynamicSharedMemorySize, ATTN_SMEM);

    split_kernel<<<(3 * DD * DD) / 1024, 256>>>(in_proj_w,  p_wq_hi, p_wq_lo, 3 * DD * DD);
    ln_split_kernel<<<MM, 256>>>(x, ln1_g, ln1_b, p_h_hi, p_h_lo);
    // QKV = h @ W_in^T + b   [4096, 3072]
    gemm3<<<dim3(3 * DD / 128, MM / 128), 256, GEMM_SMEM>>>(
        p_h_hi, p_h_lo, p_wq_hi, p_wq_lo, in_proj_b, nullptr,
        p_qkv, nullptr, nullptr, 3 * DD, DD, 0);
    // windowed attention (smem-tiled) -> split
    attn_kernel<<<dim3(SS / TQ, HH, BB), 256, ATTN_SMEM>>>(p_qkv, p_at_hi, p_at_lo);
    split_kernel<<<(DD * DD) / 1024, 256>>>(out_proj_w, p_wo_hi, p_wo_lo, DD * DD);
    // out proj + residual(x) -> x1 fp32  [4096, 1024]
    gemm3<<<dim3(DD / 128, MM / 128), 256, GEMM_SMEM>>>(
        p_at_hi, p_at_lo, p_wo_hi, p_wo_lo, out_proj_b, x,
        p_x1, nullptr, nullptr, DD, DD, 1);
    // LN2 -> split
    ln_split_kernel<<<MM, 256>>>(p_x1, ln2_g, ln2_b, p_xn_hi, p_xn_lo);
    split_kernel<<<(DFF * DD) / 1024, 256>>>(mlp_w1, p_w1_hi, p_w1_lo, DFF * DD);
    // MLP up + GELU -> split   [4096, 4096]
    gemm3<<<dim3(DFF / 128, MM / 128), 256, GEMM_SMEM>>>(
        p_xn_hi, p_xn_lo, p_w1_hi, p_w1_lo, mlp_b1, nullptr,
        nullptr, p_ff_hi, p_ff_lo, DFF, DD, 2);
    split_kernel<<<(DD * DFF) / 1024, 256>>>(mlp_w2, p_w2_hi, p_w2_lo, DD * DFF);
    // MLP down + residual(x1) -> out   [4096, 1024]
    gemm3<<<dim3(DD / 128, MM / 128), 256, GEMM_SMEM>>>(
        p_ff_hi, p_ff_lo, p_w2_hi, p_w2_lo, mlp_b2, p_x1,
        out, nullptr, nullptr, DD, DFF, 1);
}

// round 6
// speedup vs baseline: 2.9803x; 1.0380x over previous
#include <cuda_runtime.h>
#include <cuda_bf16.h>
#include <math.h>
#include <stdint.h>

// Problem constants
#define BB 2
#define SS 2048
#define DD 1024
#define HH 16
#define HD 64
#define WW 16
#define DFF 4096
#define MM (BB * SS)   // 4096 rows

// ---------------- scratch (no allocations allowed) ----------------
__device__ float g_qkv[MM * 3 * DD];          // QKV fp32
__device__ float g_x1[MM * DD];               // residual-1 output fp32
__device__ __nv_bfloat16 g_h_hi[MM * DD],   g_h_lo[MM * DD];     // LN1 out split
__device__ __nv_bfloat16 g_at_hi[MM * DD],  g_at_lo[MM * DD];    // attn out split
__device__ __nv_bfloat16 g_xn_hi[MM * DD],  g_xn_lo[MM * DD];    // LN2 out split
__device__ __nv_bfloat16 g_ff_hi[MM * DFF], g_ff_lo[MM * DFF];   // MLP hidden split
__device__ __nv_bfloat16 g_wq_hi[3 * DD * DD], g_wq_lo[3 * DD * DD];
__device__ __nv_bfloat16 g_wo_hi[DD * DD],     g_wo_lo[DD * DD];
__device__ __nv_bfloat16 g_w1_hi[DFF * DD],    g_w1_lo[DFF * DD];
__device__ __nv_bfloat16 g_w2_hi[DD * DFF],    g_w2_lo[DD * DFF];

__device__ __forceinline__ uint32_t smem_u32(const void* p) {
    return (uint32_t)__cvta_generic_to_shared(p);
}

__device__ __forceinline__ void split_bf16(float v, __nv_bfloat16& hi, __nv_bfloat16& lo) {
    hi = __float2bfloat16(v);
    lo = __float2bfloat16(v - __bfloat162float(hi));
}

__device__ __forceinline__ float gelu_tanh(float x) {
    float x3 = x * x * x;
    return 0.5f * x * (1.0f + tanhf(0.7978845608028654f * (x + 0.044715f * x3)));
}

// ---------------- weight split kernel ----------------
__global__ void split_kernel(const float* __restrict__ in,
                             __nv_bfloat16* __restrict__ hi,
                             __nv_bfloat16* __restrict__ lo, int n) {
    int i = (blockIdx.x * blockDim.x + threadIdx.x) * 4;
    if (i >= n) return;
    float4 v = *(const float4*)(in + i);
    __nv_bfloat16 h0, l0, h1, l1, h2, l2, h3, l3;
    split_bf16(v.x, h0, l0); split_bf16(v.y, h1, l1);
    split_bf16(v.z, h2, l2); split_bf16(v.w, h3, l3);
    *(__nv_bfloat162*)(hi + i)     = __nv_bfloat162(h0, h1);
    *(__nv_bfloat162*)(hi + i + 2) = __nv_bfloat162(h2, h3);
    *(__nv_bfloat162*)(lo + i)     = __nv_bfloat162(l0, l1);
    *(__nv_bfloat162*)(lo + i + 2) = __nv_bfloat162(l2, l3);
}

// ---------------- LayerNorm -> split bf16 ----------------
__global__ void ln_split_kernel(const float* __restrict__ x,
                                const float* __restrict__ g,
                                const float* __restrict__ b,
                                __nv_bfloat16* __restrict__ yhi,
                                __nv_bfloat16* __restrict__ ylo) {
    int row = blockIdx.x;
    const float* xp = x + (size_t)row * DD;
    int i = threadIdx.x * 4;
    float4 xv = *(const float4*)(xp + i);
    float s  = xv.x + xv.y + xv.z + xv.w;
    float ss = xv.x*xv.x + xv.y*xv.y + xv.z*xv.z + xv.w*xv.w;
    for (int o = 16; o > 0; o >>= 1) {
        s  += __shfl_xor_sync(0xffffffffu, s,  o);
        ss += __shfl_xor_sync(0xffffffffu, ss, o);
    }
    __shared__ float sh_s[8], sh_ss[8];
    int wid = threadIdx.x >> 5, lane = threadIdx.x & 31;
    if (lane == 0) { sh_s[wid] = s; sh_ss[wid] = ss; }
    __syncthreads();
    if (wid == 0) {
        s  = (lane < 8) ? sh_s[lane]  : 0.f;
        ss = (lane < 8) ? sh_ss[lane] : 0.f;
        for (int o = 4; o > 0; o >>= 1) {
            s  += __shfl_xor_sync(0xffffffffu, s,  o);
            ss += __shfl_xor_sync(0xffffffffu, ss, o);
        }
        if (lane == 0) { sh_s[0] = s; sh_ss[0] = ss; }
    }
    __syncthreads();
    float mean = sh_s[0] * (1.0f / DD);
    float var  = sh_ss[0] * (1.0f / DD) - mean * mean;
    float inv  = rsqrtf(var + 1e-5f);
    float4 gv = *(const float4*)(g + i);
    float4 bv = *(const float4*)(b + i);
    float o0 = (xv.x - mean) * inv * gv.x + bv.x;
    float o1 = (xv.y - mean) * inv * gv.y + bv.y;
    float o2 = (xv.z - mean) * inv * gv.z + bv.z;
    float o3 = (xv.w - mean) * inv * gv.w + bv.w;
    __nv_bfloat16 h0, l0, h1, l1, h2, l2, h3, l3;
    split_bf16(o0, h0, l0); split_bf16(o1, h1, l1);
    split_bf16(o2, h2, l2); split_bf16(o3, h3, l3);
    size_t idx = (size_t)row * DD + i;
    *(__nv_bfloat162*)(yhi + idx)     = __nv_bfloat162(h0, h1);
    *(__nv_bfloat162*)(yhi + idx + 2) = __nv_bfloat162(h2, h3);
    *(__nv_bfloat162*)(ylo + idx)     = __nv_bfloat162(l0, l1);
    *(__nv_bfloat162*)(ylo + idx + 2) = __nv_bfloat162(l2, l3);
}

// ---------------- mma.sync split-bf16 GEMM: C[M,N] = A[M,K] @ Bw[N,K]^T (+epi) ----------------
// 3-stage cp.async pipeline, XOR-swizzled smem (64B rows), 1 barrier/chunk.
// epi: 0 = fp32 +bias ; 1 = fp32 +bias+res ; 2 = gelu(+bias) -> split bf16
#define BKT 32
#define TILE_BYTES (128 * 64)           // 8192 (32 bf16 = 64 B per row)
#define OFF_AH 0
#define OFF_AL TILE_BYTES
#define OFF_BH (2 * TILE_BYTES)
#define OFF_BL (3 * TILE_BYTES)
#define STAGE_BYTES (4 * TILE_BYTES)    // 32768
#define NSTAGE 3
#define GEMM_SMEM (NSTAGE * STAGE_BYTES)  // 98304

#define LDMX4(r0, r1, r2, r3, addr) \
    asm volatile("ldmatrix.sync.aligned.m8n8.x4.shared.b16 {%0,%1,%2,%3}, [%4];" \
                 : "=r"(r0), "=r"(r1), "=r"(r2), "=r"(r3) : "r"(addr))

#define MMA_BF16(d, a, b0, b1) \
    asm volatile("mma.sync.aligned.m16n8k16.row.col.f32.bf16.bf16.f32 " \
                 "{%0,%1,%2,%3}, {%4,%5,%6,%7}, {%8,%9}, {%0,%1,%2,%3};" \
                 : "+f"((d)[0]), "+f"((d)[1]), "+f"((d)[2]), "+f"((d)[3]) \
                 : "r"((a)[0]), "r"((a)[1]), "r"((a)[2]), "r"((a)[3]), "r"(b0), "r"(b1))

// swizzled byte offset inside one 128x32 tile: row r (0..127), 16B-unit u (0..3)
__device__ __forceinline__ uint32_t sw_off(int r, int u) {
    return (uint32_t)(r * 64 + ((u ^ (r & 3)) << 4));
}

__device__ __forceinline__ void load_tile(const __nv_bfloat16* __restrict__ g,
                                          int ldk, int row0, int k0,
                                          uint32_t sbase, int tid) {
    #pragma unroll
    for (int j = 0; j < 2; j++) {
        int ch = tid + 256 * j;          // 0..511
        int r = ch >> 2;
        int u = ch & 3;
        const void* gp = g + (size_t)(row0 + r) * ldk + k0 + u * 8;
        uint32_t sa = sbase + sw_off(r, u);
        asm volatile("cp.async.cg.shared.global [%0], [%1], 16;" :: "r"(sa), "l"(gp) : "memory");
    }
}

__device__ __forceinline__ void load_chunk(const __nv_bfloat16* Ahi, const __nv_bfloat16* Alo,
                                           const __nv_bfloat16* Bhi, const __nv_bfloat16* Blo,
                                           int Kk, int bm, int bn, int k0,
                                           uint32_t st, int tid) {
    load_tile(Ahi, Kk, bm, k0, st + OFF_AH, tid);
    load_tile(Alo, Kk, bm, k0, st + OFF_AL, tid);
    load_tile(Bhi, Kk, bn, k0, st + OFF_BH, tid);
    load_tile(Blo, Kk, bn, k0, st + OFF_BL, tid);
    asm volatile("cp.async.commit_group;" ::: "memory");
}

__global__ __launch_bounds__(256, 2)
void gemm3(const __nv_bfloat16* __restrict__ Ahi, const __nv_bfloat16* __restrict__ Alo,
           const __nv_bfloat16* __restrict__ Bhi, const __nv_bfloat16* __restrict__ Blo,
           const float* __restrict__ bias, const float* __restrict__ res,
           float* __restrict__ outF,
           __nv_bfloat16* __restrict__ outHi, __nv_bfloat16* __restrict__ outLo,
           int Nn, int Kk, int epi) {
    extern __shared__ __align__(16) char dsm[];
    uint32_t sbase = smem_u32(dsm);
    int tid = threadIdx.x;
    int lane = tid & 31;
    int wid = tid >> 5;
    int wr = wid & 1;      // warp row: m offset wr*64
    int wc = wid >> 1;     // warp col: n offset wc*32
    int bm = blockIdx.y * 128;
    int bn = blockIdx.x * 128;

    float acc[4][4][4];
    #pragma unroll
    for (int mi = 0; mi < 4; mi++)
        #pragma unroll
        for (int ni = 0; ni < 4; ni++)
            #pragma unroll
            for (int q = 0; q < 4; q++) acc[mi][ni][q] = 0.f;

    const int NC = Kk >> 5;   // BKT=32 chunks

    // prologue: chunks 0 and 1
    load_chunk(Ahi, Alo, Bhi, Blo, Kk, bm, bn, 0, sbase, tid);
    if (NC > 1)
        load_chunk(Ahi, Alo, Bhi, Blo, Kk, bm, bn, 32, sbase + STAGE_BYTES, tid);

    int a_row = wr * 64 + (lane & 15);
    int a_usel = (lane >> 4) & 1;
    int b_row = wc * 32 + (lane & 7) + ((lane >> 4) & 1) * 8;
    int b_usel = (lane >> 3) & 1;

    for (int c = 0; c < NC; c++) {
        if (c == NC - 1) asm volatile("cp.async.wait_group 0;" ::: "memory");
        else             asm volatile("cp.async.wait_group 1;" ::: "memory");
        __syncthreads();   // all warps done with chunk c-1 -> safe to overwrite stage (c+2)%3
        if (c + 2 < NC)
            load_chunk(Ahi, Alo, Bhi, Blo, Kk, bm, bn, (c + 2) << 5,
                       sbase + ((c + 2) % NSTAGE) * STAGE_BYTES, tid);

        uint32_t st = sbase + (c % NSTAGE) * STAGE_BYTES;
        #pragma unroll
        for (int kk = 0; kk < 2; kk++) {
            uint32_t bh[8], bl[8];
            #pragma unroll
            for (int g = 0; g < 2; g++) {
                int r = b_row + g * 16;
                uint32_t off = sw_off(r, kk * 2 + b_usel);
                LDMX4(bh[g*4+0], bh[g*4+1], bh[g*4+2], bh[g*4+3], st + OFF_BH + off);
                LDMX4(bl[g*4+0], bl[g*4+1], bl[g*4+2], bl[g*4+3], st + OFF_BL + off);
            }
            #pragma unroll
            for (int mi = 0; mi < 4; mi++) {
                uint32_t ah[4], al[4];
                int r = a_row + mi * 16;
                uint32_t off = sw_off(r, kk * 2 + a_usel);
                LDMX4(ah[0], ah[1], ah[2], ah[3], st + OFF_AH + off);
                LDMX4(al[0], al[1], al[2], al[3], st + OFF_AL + off);
                #pragma unroll
                for (int ni = 0; ni < 4; ni++) {
                    MMA_BF16(acc[mi][ni], ah, bh[ni*2], bh[ni*2+1]);
                    MMA_BF16(acc[mi][ni], ah, bl[ni*2], bl[ni*2+1]);
                    MMA_BF16(acc[mi][ni], al, bh[ni*2], bh[ni*2+1]);
                }
            }
        }
    }

    // epilogue
    int m0 = bm + wr * 64 + (lane >> 2);
    int n0 = bn + wc * 32 + (lane & 3) * 2;
    #pragma unroll
    for (int mi = 0; mi < 4; mi++) {
        #pragma unroll
        for (int r2 = 0; r2 < 2; r2++) {
            int row = m0 + mi * 16 + r2 * 8;
            size_t rbase = (size_t)row * Nn;
            #pragma unroll
            for (int ni = 0; ni < 4; ni++) {
                int col = n0 + ni * 8;
                float v0 = acc[mi][ni][r2*2+0] + bias[col];
                float v1 = acc[mi][ni][r2*2+1] + bias[col+1];
                if (epi == 0) {
                    *(float2*)(outF + rbase + col) = make_float2(v0, v1);
                } else if (epi == 1) {
                    float2 rv = *(const float2*)(res + rbase + col);
                    *(float2*)(outF + rbase + col) = make_float2(v0 + rv.x, v1 + rv.y);
                } else {
                    v0 = gelu_tanh(v0); v1 = gelu_tanh(v1);
                    __nv_bfloat16 h0, l0, h1, l1;
                    split_bf16(v0, h0, l0); split_bf16(v1, h1, l1);
                    *(__nv_bfloat162*)(outHi + rbase + col) = __nv_bfloat162(h0, h1);
                    *(__nv_bfloat162*)(outLo + rbase + col) = __nv_bfloat162(l0, l1);
                }
            }
        }
    }
}

// ---------------- Sliding-window causal attention (W=16), smem-tiled ----------------
// One CTA per (query tile of 64, head, batch). 42.5 KB smem -> 4 CTAs/SM.
#define TQ 64
#define KR (TQ + WW - 1)     // 79 key rows
#define PK 68                // padded floats per smem row
#define ATTN_SMEM (2 * 80 * PK * 4)   // 43520 bytes

__global__ __launch_bounds__(256, 4)
void attn_kernel(const float* __restrict__ qkv,
                 __nv_bfloat16* __restrict__ ohi,
                 __nv_bfloat16* __restrict__ olo) {
    extern __shared__ __align__(16) float asm_f[];
    float* Ks = asm_f;                 // [80][PK]
    float* Vs = asm_f + 80 * PK;       // [80][PK]

    int tile = blockIdx.x;
    int h = blockIdx.y;
    int b = blockIdx.z;
    int s0 = tile * TQ;
    int tid = threadIdx.x;
    int lane = tid & 31;
    int w = tid >> 5;

    // cooperative load of K/V rows [s0-15, s0+63] -> smem rows 0..78
    for (int i = tid; i < KR * (HD / 4); i += 256) {
        int r = i >> 4;                // row 0..78
        int c = (i & 15) * 4;          // dim 0..60
        int seq = s0 - (WW - 1) + r;
        if (seq >= 0) {
            size_t base = ((size_t)(b * SS + seq)) * (3 * DD) + h * HD + c;
            *(float4*)&Ks[r * PK + c] = *(const float4*)(qkv + base + DD);
            *(float4*)&Vs[r * PK + c] = *(const float4*)(qkv + base + 2 * DD);
        }
    }
    __syncthreads();

    // each warp handles 8 queries
    for (int qq = 0; qq < 8; qq++) {
        int qi = w * 8 + qq;           // local query 0..63
        int s = s0 + qi;               // global seq
        int m = b * SS + s;
        const float* qp = qkv + (size_t)m * (3 * DD) + h * HD;

        float score = -INFINITY;
        if (lane < WW && lane <= s) {
            const float* kp = &Ks[(qi + WW - 1 - lane) * PK];
            float acc = 0.f;
            #pragma unroll
            for (int d = 0; d < HD; d += 4) {
                float4 qa = *(const float4*)(qp + d);
                float4 ka = *(const float4*)(kp + d);
                acc = fmaf(qa.x, ka.x, acc);
                acc = fmaf(qa.y, ka.y, acc);
                acc = fmaf(qa.z, ka.z, acc);
                acc = fmaf(qa.w, ka.w, acc);
            }
            score = acc * 0.125f;
        }
        float mx = score;
        for (int o = 16; o > 0; o >>= 1) mx = fmaxf(mx, __shfl_xor_sync(0xffffffffu, mx, o));
        float p = (score == -INFINITY) ? 0.f : __expf(score - mx);
        float sum = p;
        for (int o = 16; o > 0; o >>= 1) sum += __shfl_xor_sync(0xffffffffu, sum, o);
        float inv = 1.f / sum;

        // V accumulation: lane owns dims 2*lane, 2*lane+1
        float o0 = 0.f, o1 = 0.f;
        int jmax = min(WW - 1, s);
        for (int jj = 0; jj <= jmax; jj++) {
            float pj = __shfl_sync(0xffffffffu, p, jj);
            float2 vv = *(const float2*)&Vs[(qi + WW - 1 - jj) * PK + 2 * lane];
            o0 = fmaf(pj, vv.x, o0);
            o1 = fmaf(pj, vv.y, o1);
        }
        o0 *= inv; o1 *= inv;
        size_t idx = (size_t)m * DD + h * HD + 2 * lane;
        __nv_bfloat16 h0, l0, h1, l1;
        split_bf16(o0, h0, l0); split_bf16(o1, h1, l1);
        *(__nv_bfloat162*)(ohi + idx) = __nv_bfloat162(h0, h1);
        *(__nv_bfloat162*)(olo + idx) = __nv_bfloat162(l0, l1);
    }
}

// ---------------- launch ----------------
extern "C" void kernel_launch(void* const* d_in, const int* in_sizes, int n_in,
                              void* d_out, int out_size) {
    const float* x          = (const float*)d_in[0];
    const float* ln1_g      = (const float*)d_in[1];
    const float* ln1_b      = (const float*)d_in[2];
    const float* in_proj_w  = (const float*)d_in[3];
    const float* in_proj_b  = (const float*)d_in[4];
    const float* out_proj_w = (const float*)d_in[5];
    const float* out_proj_b = (const float*)d_in[6];
    const float* ln2_g      = (const float*)d_in[7];
    const float* ln2_b      = (const float*)d_in[8];
    const float* mlp_w1     = (const float*)d_in[9];
    const float* mlp_b1     = (const float*)d_in[10];
    const float* mlp_w2     = (const float*)d_in[11];
    const float* mlp_b2     = (const float*)d_in[12];
    float* out = (float*)d_out;

    float *p_qkv, *p_x1;
    __nv_bfloat16 *p_h_hi, *p_h_lo, *p_at_hi, *p_at_lo, *p_xn_hi, *p_xn_lo, *p_ff_hi, *p_ff_lo;
    __nv_bfloat16 *p_wq_hi, *p_wq_lo, *p_wo_hi, *p_wo_lo, *p_w1_hi, *p_w1_lo, *p_w2_hi, *p_w2_lo;
    cudaGetSymbolAddress((void**)&p_qkv,   g_qkv);
    cudaGetSymbolAddress((void**)&p_x1,    g_x1);
    cudaGetSymbolAddress((void**)&p_h_hi,  g_h_hi);
    cudaGetSymbolAddress((void**)&p_h_lo,  g_h_lo);
    cudaGetSymbolAddress((void**)&p_at_hi, g_at_hi);
    cudaGetSymbolAddress((void**)&p_at_lo, g_at_lo);
    cudaGetSymbolAddress((void**)&p_xn_hi, g_xn_hi);
    cudaGetSymbolAddress((void**)&p_xn_lo, g_xn_lo);
    cudaGetSymbolAddress((void**)&p_ff_hi, g_ff_hi);
    cudaGetSymbolAddress((void**)&p_ff_lo, g_ff_lo);
    cudaGetSymbolAddress((void**)&p_wq_hi, g_wq_hi);
    cudaGetSymbolAddress((void**)&p_wq_lo, g_wq_lo);
    cudaGetSymbolAddress((void**)&p_wo_hi, g_wo_hi);
    cudaGetSymbolAddress((void**)&p_wo_lo, g_wo_lo);
    cudaGetSymbolAddress((void**)&p_w1_hi, g_w1_hi);
    cudaGetSymbolAddress((void**)&p_w1_lo, g_w1_lo);
    cudaGetSymbolAddress((void**)&p_w2_hi, g_w2_hi);
    cudaGetSymbolAddress((void**)&p_w2_lo, g_w2_lo);

    cudaFuncSetAttribute(gemm3, cudaFuncAttributeMaxDynamicSharedMemorySize, GEMM_SMEM);
    cudaFuncSetAttribute(attn_kernel, cudaFuncAttributeMaxDynamicSharedMemorySize, ATTN_SMEM);

    split_kernel<<<(3 * DD * DD) / 1024, 256>>>(in_proj_w,  p_wq_hi, p_wq_lo, 3 * DD * DD);
    ln_split_kernel<<<MM, 256>>>(x, ln1_g, ln1_b, p_h_hi, p_h_lo);
    // QKV = h @ W_in^T + b   [4096, 3072]
    gemm3<<<dim3(3 * DD / 128, MM / 128), 256, GEMM_SMEM>>>(
        p_h_hi, p_h_lo, p_wq_hi, p_wq_lo, in_proj_b, nullptr,
        p_qkv, nullptr, nullptr, 3 * DD, DD, 0);
    // windowed attention (smem-tiled) -> split
    attn_kernel<<<dim3(SS / TQ, HH, BB), 256, ATTN_SMEM>>>(p_qkv, p_at_hi, p_at_lo);
    split_kernel<<<(DD * DD) / 1024, 256>>>(out_proj_w, p_wo_hi, p_wo_lo, DD * DD);
    // out proj + residual(x) -> x1 fp32  [4096, 1024]
    gemm3<<<dim3(DD / 128, MM / 128), 256, GEMM_SMEM>>>(
        p_at_hi, p_at_lo, p_wo_hi, p_wo_lo, out_proj_b, x,
        p_x1, nullptr, nullptr, DD, DD, 1);
    // LN2 -> split
    ln_split_kernel<<<MM, 256>>>(p_x1, ln2_g, ln2_b, p_xn_hi, p_xn_lo);
    split_kernel<<<(DFF * DD) / 1024, 256>>>(mlp_w1, p_w1_hi, p_w1_lo, DFF * DD);
    // MLP up + GELU -> split   [4096, 4096]
    gemm3<<<dim3(DFF / 128, MM / 128), 256, GEMM_SMEM>>>(
        p_xn_hi, p_xn_lo, p_w1_hi, p_w1_lo, mlp_b1, nullptr,
        nullptr, p_ff_hi, p_ff_lo, DFF, DD, 2);
    split_kernel<<<(DD * DFF) / 1024, 256>>>(mlp_w2, p_w2_hi, p_w2_lo, DD * DFF);
    // MLP down + residual(x1) -> out   [4096, 1024]
    gemm3<<<dim3(DD / 128, MM / 128), 256, GEMM_SMEM>>>(
        p_ff_hi, p_ff_lo, p_w2_hi, p_w2_lo, mlp_b2, p_x1,
        out, nullptr, nullptr, DD, DFF, 1);
}

// round 7
// speedup vs baseline: 3.7603x; 1.2617x over previous
#include <cuda_runtime.h>
#include <cuda_fp16.h>
#include <math.h>
#include <stdint.h>

// Problem constants
#define BB 2
#define SS 2048
#define DD 1024
#define HH 16
#define HD 64
#define WW 16
#define DFF 4096
#define MM (BB * SS)   // 4096 rows

// ---------------- scratch (no allocations allowed) ----------------
__device__ float g_qkv[MM * 3 * DD];          // QKV fp32
__device__ float g_x1[MM * DD];               // residual-1 output fp32
__device__ __half g_h_h[MM * DD];             // LN1 out fp16
__device__ __half g_at_h[MM * DD];            // attn out fp16
__device__ __half g_xn_h[MM * DD];            // LN2 out fp16
__device__ __half g_ff_h[MM * DFF];           // MLP hidden fp16
__device__ __half g_wq_h[3 * DD * DD];
__device__ __half g_wo_h[DD * DD];
__device__ __half g_w1_h[DFF * DD];
__device__ __half g_w2_h[DD * DFF];

__device__ __forceinline__ uint32_t smem_u32(const void* p) {
    return (uint32_t)__cvta_generic_to_shared(p);
}

__device__ __forceinline__ float gelu_tanh(float x) {
    float x3 = x * x * x;
    return 0.5f * x * (1.0f + tanhf(0.7978845608028654f * (x + 0.044715f * x3)));
}

// ---------------- weight convert kernel (fp32 -> fp16) ----------------
__global__ void cvt_kernel(const float* __restrict__ in,
                           __half* __restrict__ out, int n) {
    int i = (blockIdx.x * blockDim.x + threadIdx.x) * 4;
    if (i >= n) return;
    float4 v = *(const float4*)(in + i);
    *(__half2*)(out + i)     = __floats2half2_rn(v.x, v.y);
    *(__half2*)(out + i + 2) = __floats2half2_rn(v.z, v.w);
}

// ---------------- LayerNorm -> fp16 ----------------
__global__ void ln_half_kernel(const float* __restrict__ x,
                               const float* __restrict__ g,
                               const float* __restrict__ b,
                               __half* __restrict__ y) {
    int row = blockIdx.x;
    const float* xp = x + (size_t)row * DD;
    int i = threadIdx.x * 4;
    float4 xv = *(const float4*)(xp + i);
    float s  = xv.x + xv.y + xv.z + xv.w;
    float ss = xv.x*xv.x + xv.y*xv.y + xv.z*xv.z + xv.w*xv.w;
    for (int o = 16; o > 0; o >>= 1) {
        s  += __shfl_xor_sync(0xffffffffu, s,  o);
        ss += __shfl_xor_sync(0xffffffffu, ss, o);
    }
    __shared__ float sh_s[8], sh_ss[8];
    int wid = threadIdx.x >> 5, lane = threadIdx.x & 31;
    if (lane == 0) { sh_s[wid] = s; sh_ss[wid] = ss; }
    __syncthreads();
    if (wid == 0) {
        s  = (lane < 8) ? sh_s[lane]  : 0.f;
        ss = (lane < 8) ? sh_ss[lane] : 0.f;
        for (int o = 4; o > 0; o >>= 1) {
            s  += __shfl_xor_sync(0xffffffffu, s,  o);
            ss += __shfl_xor_sync(0xffffffffu, ss, o);
        }
        if (lane == 0) { sh_s[0] = s; sh_ss[0] = ss; }
    }
    __syncthreads();
    float mean = sh_s[0] * (1.0f / DD);
    float var  = sh_ss[0] * (1.0f / DD) - mean * mean;
    float inv  = rsqrtf(var + 1e-5f);
    float4 gv = *(const float4*)(g + i);
    float4 bv = *(const float4*)(b + i);
    float o0 = (xv.x - mean) * inv * gv.x + bv.x;
    float o1 = (xv.y - mean) * inv * gv.y + bv.y;
    float o2 = (xv.z - mean) * inv * gv.z + bv.z;
    float o3 = (xv.w - mean) * inv * gv.w + bv.w;
    size_t idx = (size_t)row * DD + i;
    *(__half2*)(y + idx)     = __floats2half2_rn(o0, o1);
    *(__half2*)(y + idx + 2) = __floats2half2_rn(o2, o3);
}

// ---------------- mma.sync fp16 GEMM: C[M,N] = A[M,K] @ Bw[N,K]^T (+epi) ----------------
// 3-stage cp.async pipeline, XOR-swizzled smem (64B rows), 1 barrier/chunk.
// epi: 0 = fp32 +bias ; 1 = fp32 +bias+res ; 2 = gelu(+bias) -> fp16
#define BKT 32
#define TILE_BYTES (128 * 64)           // 8192 (32 fp16 = 64 B per row)
#define OFF_A 0
#define OFF_B TILE_BYTES
#define STAGE_BYTES (2 * TILE_BYTES)    // 16384
#define NSTAGE 3
#define GEMM_SMEM (NSTAGE * STAGE_BYTES)  // 49152

#define LDMX4(r0, r1, r2, r3, addr) \
    asm volatile("ldmatrix.sync.aligned.m8n8.x4.shared.b16 {%0,%1,%2,%3}, [%4];" \
                 : "=r"(r0), "=r"(r1), "=r"(r2), "=r"(r3) : "r"(addr))

#define MMA_F16(d, a, b0, b1) \
    asm volatile("mma.sync.aligned.m16n8k16.row.col.f32.f16.f16.f32 " \
                 "{%0,%1,%2,%3}, {%4,%5,%6,%7}, {%8,%9}, {%0,%1,%2,%3};" \
                 : "+f"((d)[0]), "+f"((d)[1]), "+f"((d)[2]), "+f"((d)[3]) \
                 : "r"((a)[0]), "r"((a)[1]), "r"((a)[2]), "r"((a)[3]), "r"(b0), "r"(b1))

// swizzled byte offset inside one 128x32 tile: row r (0..127), 16B-unit u (0..3)
__device__ __forceinline__ uint32_t sw_off(int r, int u) {
    return (uint32_t)(r * 64 + ((u ^ (r & 3)) << 4));
}

__device__ __forceinline__ void load_tile(const __half* __restrict__ g,
                                          int ldk, int row0, int k0,
                                          uint32_t sbase, int tid) {
    #pragma unroll
    for (int j = 0; j < 2; j++) {
        int ch = tid + 256 * j;          // 0..511
        int r = ch >> 2;
        int u = ch & 3;
        const void* gp = g + (size_t)(row0 + r) * ldk + k0 + u * 8;
        uint32_t sa = sbase + sw_off(r, u);
        asm volatile("cp.async.cg.shared.global [%0], [%1], 16;" :: "r"(sa), "l"(gp) : "memory");
    }
}

__device__ __forceinline__ void load_chunk(const __half* A, const __half* Bw,
                                           int Kk, int bm, int bn, int k0,
                                           uint32_t st, int tid) {
    load_tile(A,  Kk, bm, k0, st + OFF_A, tid);
    load_tile(Bw, Kk, bn, k0, st + OFF_B, tid);
    asm volatile("cp.async.commit_group;" ::: "memory");
}

__global__ __launch_bounds__(256, 2)
void gemmh(const __half* __restrict__ A, const __half* __restrict__ Bw,
           const float* __restrict__ bias, const float* __restrict__ res,
           float* __restrict__ outF, __half* __restrict__ outH,
           int Nn, int Kk, int epi) {
    extern __shared__ __align__(16) char dsm[];
    uint32_t sbase = smem_u32(dsm);
    int tid = threadIdx.x;
    int lane = tid & 31;
    int wid = tid >> 5;
    int wr = wid & 1;      // warp row: m offset wr*64
    int wc = wid >> 1;     // warp col: n offset wc*32
    int bm = blockIdx.y * 128;
    int bn = blockIdx.x * 128;

    float acc[4][4][4];
    #pragma unroll
    for (int mi = 0; mi < 4; mi++)
        #pragma unroll
        for (int ni = 0; ni < 4; ni++)
            #pragma unroll
            for (int q = 0; q < 4; q++) acc[mi][ni][q] = 0.f;

    const int NC = Kk >> 5;   // BKT=32 chunks

    // prologue: chunks 0 and 1
    load_chunk(A, Bw, Kk, bm, bn, 0, sbase, tid);
    if (NC > 1)
        load_chunk(A, Bw, Kk, bm, bn, 32, sbase + STAGE_BYTES, tid);

    int a_row = wr * 64 + (lane & 15);
    int a_usel = (lane >> 4) & 1;
    int b_row = wc * 32 + (lane & 7) + ((lane >> 4) & 1) * 8;
    int b_usel = (lane >> 3) & 1;

    for (int c = 0; c < NC; c++) {
        if (c == NC - 1) asm volatile("cp.async.wait_group 0;" ::: "memory");
        else             asm volatile("cp.async.wait_group 1;" ::: "memory");
        __syncthreads();   // all warps done with chunk c-1 -> safe to overwrite stage (c+2)%3
        if (c + 2 < NC)
            load_chunk(A, Bw, Kk, bm, bn, (c + 2) << 5,
                       sbase + ((c + 2) % NSTAGE) * STAGE_BYTES, tid);

        uint32_t st = sbase + (c % NSTAGE) * STAGE_BYTES;
        #pragma unroll
        for (int kk = 0; kk < 2; kk++) {
            uint32_t bh[8];
            #pragma unroll
            for (int g = 0; g < 2; g++) {
                int r = b_row + g * 16;
                uint32_t off = sw_off(r, kk * 2 + b_usel);
                LDMX4(bh[g*4+0], bh[g*4+1], bh[g*4+2], bh[g*4+3], st + OFF_B + off);
            }
            #pragma unroll
            for (int mi = 0; mi < 4; mi++) {
                uint32_t ah[4];
                int r = a_row + mi * 16;
                uint32_t off = sw_off(r, kk * 2 + a_usel);
                LDMX4(ah[0], ah[1], ah[2], ah[3], st + OFF_A + off);
                #pragma unroll
                for (int ni = 0; ni < 4; ni++) {
                    MMA_F16(acc[mi][ni], ah, bh[ni*2], bh[ni*2+1]);
                }
            }
        }
    }

    // epilogue
    int m0 = bm + wr * 64 + (lane >> 2);
    int n0 = bn + wc * 32 + (lane & 3) * 2;
    #pragma unroll
    for (int mi = 0; mi < 4; mi++) {
        #pragma unroll
        for (int r2 = 0; r2 < 2; r2++) {
            int row = m0 + mi * 16 + r2 * 8;
            size_t rbase = (size_t)row * Nn;
            #pragma unroll
            for (int ni = 0; ni < 4; ni++) {
                int col = n0 + ni * 8;
                float v0 = acc[mi][ni][r2*2+0] + bias[col];
                float v1 = acc[mi][ni][r2*2+1] + bias[col+1];
                if (epi == 0) {
                    *(float2*)(outF + rbase + col) = make_float2(v0, v1);
                } else if (epi == 1) {
                    float2 rv = *(const float2*)(res + rbase + col);
                    *(float2*)(outF + rbase + col) = make_float2(v0 + rv.x, v1 + rv.y);
                } else {
                    v0 = gelu_tanh(v0); v1 = gelu_tanh(v1);
                    *(__half2*)(outH + rbase + col) = __floats2half2_rn(v0, v1);
                }
            }
        }
    }
}

// ---------------- Sliding-window causal attention (W=16), smem-tiled ----------------
// One CTA per (query tile of 64, head, batch). 42.5 KB smem -> 4 CTAs/SM.
#define TQ 64
#define KR (TQ + WW - 1)     // 79 key rows
#define PK 68                // padded floats per smem row
#define ATTN_SMEM (2 * 80 * PK * 4)   // 43520 bytes

__global__ __launch_bounds__(256, 4)
void attn_kernel(const float* __restrict__ qkv,
                 __half* __restrict__ oh) {
    extern __shared__ __align__(16) float asm_f[];
    float* Ks = asm_f;                 // [80][PK]
    float* Vs = asm_f + 80 * PK;       // [80][PK]

    int tile = blockIdx.x;
    int h = blockIdx.y;
    int b = blockIdx.z;
    int s0 = tile * TQ;
    int tid = threadIdx.x;
    int lane = tid & 31;
    int w = tid >> 5;

    // cooperative load of K/V rows [s0-15, s0+63] -> smem rows 0..78
    for (int i = tid; i < KR * (HD / 4); i += 256) {
        int r = i >> 4;                // row 0..78
        int c = (i & 15) * 4;          // dim 0..60
        int seq = s0 - (WW - 1) + r;
        if (seq >= 0) {
            size_t base = ((size_t)(b * SS + seq)) * (3 * DD) + h * HD + c;
            *(float4*)&Ks[r * PK + c] = *(const float4*)(qkv + base + DD);
            *(float4*)&Vs[r * PK + c] = *(const float4*)(qkv + base + 2 * DD);
        }
    }
    __syncthreads();

    // each warp handles 8 queries
    for (int qq = 0; qq < 8; qq++) {
        int qi = w * 8 + qq;           // local query 0..63
        int s = s0 + qi;               // global seq
        int m = b * SS + s;
        const float* qp = qkv + (size_t)m * (3 * DD) + h * HD;

        float score = -INFINITY;
        if (lane < WW && lane <= s) {
            const float* kp = &Ks[(qi + WW - 1 - lane) * PK];
            float acc = 0.f;
            #pragma unroll
            for (int d = 0; d < HD; d += 4) {
                float4 qa = *(const float4*)(qp + d);
                float4 ka = *(const float4*)(kp + d);
                acc = fmaf(qa.x, ka.x, acc);
                acc = fmaf(qa.y, ka.y, acc);
                acc = fmaf(qa.z, ka.z, acc);
                acc = fmaf(qa.w, ka.w, acc);
            }
            score = acc * 0.125f;
        }
        float mx = score;
        for (int o = 16; o > 0; o >>= 1) mx = fmaxf(mx, __shfl_xor_sync(0xffffffffu, mx, o));
        float p = (score == -INFINITY) ? 0.f : __expf(score - mx);
        float sum = p;
        for (int o = 16; o > 0; o >>= 1) sum += __shfl_xor_sync(0xffffffffu, sum, o);
        float inv = 1.f / sum;

        // V accumulation: lane owns dims 2*lane, 2*lane+1
        float o0 = 0.f, o1 = 0.f;
        int jmax = min(WW - 1, s);
        for (int jj = 0; jj <= jmax; jj++) {
            float pj = __shfl_sync(0xffffffffu, p, jj);
            float2 vv = *(const float2*)&Vs[(qi + WW - 1 - jj) * PK + 2 * lane];
            o0 = fmaf(pj, vv.x, o0);
            o1 = fmaf(pj, vv.y, o1);
        }
        o0 *= inv; o1 *= inv;
        size_t idx = (size_t)m * DD + h * HD + 2 * lane;
        *(__half2*)(oh + idx) = __floats2half2_rn(o0, o1);
    }
}

// ---------------- launch ----------------
extern "C" void kernel_launch(void* const* d_in, const int* in_sizes, int n_in,
                              void* d_out, int out_size) {
    const float* x          = (const float*)d_in[0];
    const float* ln1_g      = (const float*)d_in[1];
    const float* ln1_b      = (const float*)d_in[2];
    const float* in_proj_w  = (const float*)d_in[3];
    const float* in_proj_b  = (const float*)d_in[4];
    const float* out_proj_w = (const float*)d_in[5];
    const float* out_proj_b = (const float*)d_in[6];
    const float* ln2_g      = (const float*)d_in[7];
    const float* ln2_b      = (const float*)d_in[8];
    const float* mlp_w1     = (const float*)d_in[9];
    const float* mlp_b1     = (const float*)d_in[10];
    const float* mlp_w2     = (const float*)d_in[11];
    const float* mlp_b2     = (const float*)d_in[12];
    float* out = (float*)d_out;

    float *p_qkv, *p_x1;
    __half *p_h, *p_at, *p_xn, *p_ff, *p_wq, *p_wo, *p_w1, *p_w2;
    cudaGetSymbolAddress((void**)&p_qkv, g_qkv);
    cudaGetSymbolAddress((void**)&p_x1,  g_x1);
    cudaGetSymbolAddress((void**)&p_h,   g_h_h);
    cudaGetSymbolAddress((void**)&p_at,  g_at_h);
    cudaGetSymbolAddress((void**)&p_xn,  g_xn_h);
    cudaGetSymbolAddress((void**)&p_ff,  g_ff_h);
    cudaGetSymbolAddress((void**)&p_wq,  g_wq_h);
    cudaGetSymbolAddress((void**)&p_wo,  g_wo_h);
    cudaGetSymbolAddress((void**)&p_w1,  g_w1_h);
    cudaGetSymbolAddress((void**)&p_w2,  g_w2_h);

    cudaFuncSetAttribute(gemmh, cudaFuncAttributeMaxDynamicSharedMemorySize, GEMM_SMEM);
    cudaFuncSetAttribute(attn_kernel, cudaFuncAttributeMaxDynamicSharedMemorySize, ATTN_SMEM);

    cvt_kernel<<<(3 * DD * DD) / 1024, 256>>>(in_proj_w, p_wq, 3 * DD * DD);
    ln_half_kernel<<<MM, 256>>>(x, ln1_g, ln1_b, p_h);
    // QKV = h @ W_in^T + b   [4096, 3072]
    gemmh<<<dim3(3 * DD / 128, MM / 128), 256, GEMM_SMEM>>>(
        p_h, p_wq, in_proj_b, nullptr, p_qkv, nullptr, 3 * DD, DD, 0);
    // windowed attention (smem-tiled) -> fp16
    attn_kernel<<<dim3(SS / TQ, HH, BB), 256, ATTN_SMEM>>>(p_qkv, p_at);
    cvt_kernel<<<(DD * DD) / 1024, 256>>>(out_proj_w, p_wo, DD * DD);
    // out proj + residual(x) -> x1 fp32  [4096, 1024]
    gemmh<<<dim3(DD / 128, MM / 128), 256, GEMM_SMEM>>>(
        p_at, p_wo, out_proj_b, x, p_x1, nullptr, DD, DD, 1);
    // LN2 -> fp16
    ln_half_kernel<<<MM, 256>>>(p_x1, ln2_g, ln2_b, p_xn);
    cvt_kernel<<<(DFF * DD) / 1024, 256>>>(mlp_w1, p_w1, DFF * DD);
    // MLP up + GELU -> fp16   [4096, 4096]
    gemmh<<<dim3(DFF / 128, MM / 128), 256, GEMM_SMEM>>>(
        p_xn, p_w1, mlp_b1, nullptr, nullptr, p_ff, DFF, DD, 2);
    cvt_kernel<<<(DD * DFF) / 1024, 256>>>(mlp_w2, p_w2, DD * DFF);
    // MLP down + residual(x1) -> out   [4096, 1024]
    gemmh<<<dim3(DD / 128, MM / 128), 256, GEMM_SMEM>>>(
        p_ff, p_w2, mlp_b2, p_x1, out, nullptr, DD, DFF, 1);
}

// round 9
// speedup vs baseline: 8.0648x; 2.1447x over previous
#include <cuda_runtime.h>
#include <cuda.h>
#include <cuda_fp16.h>
#include <math.h>
#include <stdint.h>

// Problem constants
#define BB 2
#define SS 2048
#define DD 1024
#define HH 16
#define HD 64
#define WW 16
#define DFF 4096
#define MM (BB * SS)   // 4096 rows

// ---------------- scratch (no allocations allowed) ----------------
__device__ float g_qkv[MM * 3 * DD];          // QKV fp32
__device__ float g_x1[MM * DD];               // residual-1 output fp32
__device__ __half g_h_h[MM * DD];             // LN1 out fp16
__device__ __half g_at_h[MM * DD];            // attn out fp16
__device__ __half g_xn_h[MM * DD];            // LN2 out fp16
__device__ __half g_ff_h[MM * DFF];           // MLP hidden fp16
__device__ __half g_wq_h[3 * DD * DD];
__device__ __half g_wo_h[DD * DD];
__device__ __half g_w1_h[DFF * DD];
__device__ __half g_w2_h[DD * DFF];

__device__ __forceinline__ uint32_t smem_u32(const void* p) {
    return (uint32_t)__cvta_generic_to_shared(p);
}

__device__ __forceinline__ float gelu_tanh(float x) {
    float x3 = x * x * x;
    return 0.5f * x * (1.0f + tanhf(0.7978845608028654f * (x + 0.044715f * x3)));
}

// ---------------- weight convert kernel (fp32 -> fp16) ----------------
__global__ void cvt_kernel(const float* __restrict__ in,
                           __half* __restrict__ out, int n) {
    int i = (blockIdx.x * blockDim.x + threadIdx.x) * 4;
    if (i >= n) return;
    float4 v = *(const float4*)(in + i);
    *(__half2*)(out + i)     = __floats2half2_rn(v.x, v.y);
    *(__half2*)(out + i + 2) = __floats2half2_rn(v.z, v.w);
}

// ---------------- LayerNorm -> fp16 ----------------
__global__ void ln_half_kernel(const float* __restrict__ x,
                               const float* __restrict__ g,
                               const float* __restrict__ b,
                               __half* __restrict__ y) {
    int row = blockIdx.x;
    const float* xp = x + (size_t)row * DD;
    int i = threadIdx.x * 4;
    float4 xv = *(const float4*)(xp + i);
    float s  = xv.x + xv.y + xv.z + xv.w;
    float ss = xv.x*xv.x + xv.y*xv.y + xv.z*xv.z + xv.w*xv.w;
    for (int o = 16; o > 0; o >>= 1) {
        s  += __shfl_xor_sync(0xffffffffu, s,  o);
        ss += __shfl_xor_sync(0xffffffffu, ss, o);
    }
    __shared__ float sh_s[8], sh_ss[8];
    int wid = threadIdx.x >> 5, lane = threadIdx.x & 31;
    if (lane == 0) { sh_s[wid] = s; sh_ss[wid] = ss; }
    __syncthreads();
    if (wid == 0) {
        s  = (lane < 8) ? sh_s[lane]  : 0.f;
        ss = (lane < 8) ? sh_ss[lane] : 0.f;
        for (int o = 4; o > 0; o >>= 1) {
            s  += __shfl_xor_sync(0xffffffffu, s,  o);
            ss += __shfl_xor_sync(0xffffffffu, ss, o);
        }
        if (lane == 0) { sh_s[0] = s; sh_ss[0] = ss; }
    }
    __syncthreads();
    float mean = sh_s[0] * (1.0f / DD);
    float var  = sh_ss[0] * (1.0f / DD) - mean * mean;
    float inv  = rsqrtf(var + 1e-5f);
    float4 gv = *(const float4*)(g + i);
    float4 bv = *(const float4*)(b + i);
    float o0 = (xv.x - mean) * inv * gv.x + bv.x;
    float o1 = (xv.y - mean) * inv * gv.y + bv.y;
    float o2 = (xv.z - mean) * inv * gv.z + bv.z;
    float o3 = (xv.w - mean) * inv * gv.w + bv.w;
    size_t idx = (size_t)row * DD + i;
    *(__half2*)(y + idx)     = __floats2half2_rn(o0, o1);
    *(__half2*)(y + idx + 2) = __floats2half2_rn(o2, o3);
}

// ---------------- TMA + mma.sync fp16 GEMM: C[M,N] = A[M,K] @ Bw[N,K]^T (+epi) ----------------
// 3-stage TMA pipeline, SW128-swizzled smem (128B rows), mbarrier per stage.
// Tile bases MUST be 1024B-aligned so the manual swizzle matches TMA's.
// epi: 0 = fp32 +bias ; 1 = fp32 +bias+res ; 2 = gelu(+bias) -> fp16
#define BKT 64
#define TILE_BYTES (128 * 128)          // 16384 (64 fp16 = 128 B per row)
#define OFF_A 0
#define OFF_B TILE_BYTES
#define STAGE_BYTES (2 * TILE_BYTES)    // 32768
#define NSTAGE 3
#define GEMM_SMEM (NSTAGE * STAGE_BYTES + 1024)  // 99328 (1KB alignment slack)

#define LDMX4(r0, r1, r2, r3, addr) \
    asm volatile("ldmatrix.sync.aligned.m8n8.x4.shared.b16 {%0,%1,%2,%3}, [%4];" \
                 : "=r"(r0), "=r"(r1), "=r"(r2), "=r"(r3) : "r"(addr))

#define MMA_F16(d, a, b0, b1) \
    asm volatile("mma.sync.aligned.m16n8k16.row.col.f32.f16.f16.f32 " \
                 "{%0,%1,%2,%3}, {%4,%5,%6,%7}, {%8,%9}, {%0,%1,%2,%3};" \
                 : "+f"((d)[0]), "+f"((d)[1]), "+f"((d)[2]), "+f"((d)[3]) \
                 : "r"((a)[0]), "r"((a)[1]), "r"((a)[2]), "r"((a)[3]), "r"(b0), "r"(b1))

#define MBAR_INIT(mbar, cnt) \
    asm volatile("mbarrier.init.shared.b64 [%0], %1;" :: "r"(mbar), "r"(cnt) : "memory")

#define MBAR_EXPECT(mbar, bytes) \
    asm volatile("mbarrier.arrive.expect_tx.shared.b64 _, [%0], %1;" :: "r"(mbar), "r"(bytes) : "memory")

#define MBAR_WAIT(mbar, parity) do {                                            \
    uint32_t _m = (mbar); uint32_t _p = (parity); uint32_t _d;                  \
    asm volatile("{\n\t.reg .pred p;\n\t"                                       \
        "mbarrier.try_wait.parity.acquire.cta.shared::cta.b64 p, [%1], %2;\n\t" \
        "selp.b32 %0, 1, 0, p;\n\t}"                                            \
        : "=r"(_d) : "r"(_m), "r"(_p) : "memory");                              \
    if (!_d) {                                                                  \
        asm volatile("{\n\t.reg .pred P1;\n\t"                                  \
            "WL_%=:\n\t"                                                        \
            "mbarrier.try_wait.parity.acquire.cta.shared::cta.b64 P1, [%0], %1, 0x989680;\n\t" \
            "@P1 bra.uni WD_%=;\n\t"                                            \
            "bra.uni WL_%=;\n\t"                                                \
            "WD_%=:\n\t}" :: "r"(_m), "r"(_p) : "memory");                      \
    }                                                                           \
} while (0)

#define TMA_LD2D(smem, tmap, cx, cy, mbar) \
    asm volatile("cp.async.bulk.tensor.2d.shared::cta.global.tile.mbarrier::complete_tx::bytes " \
                 "[%0], [%1, {%2, %3}], [%4];" \
                 :: "r"(smem), "l"(tmap), "r"(cx), "r"(cy), "r"(mbar) : "memory")

// swizzled byte offset inside one 128x64(fp16) tile: row r (0..127), 16B unit u (0..7)
// valid ONLY when tile base is 1024B-aligned
__device__ __forceinline__ uint32_t sw_off(int r, int u) {
    return (uint32_t)(r * 128 + ((u ^ (r & 7)) << 4));
}

__global__ __launch_bounds__(256, 2)
void gemmh(const __grid_constant__ CUtensorMap tmA,
           const __grid_constant__ CUtensorMap tmB,
           const float* __restrict__ bias, const float* __restrict__ res,
           float* __restrict__ outF, __half* __restrict__ outH,
           int Nn, int Kk, int epi) {
    extern __shared__ __align__(128) char dsm[];
    __shared__ __align__(8) uint64_t s_mbar[NSTAGE];
    uint32_t sbase = (smem_u32(dsm) + 1023) & ~1023u;   // 1024B-align: swizzle phase contract
    int tid = threadIdx.x;
    int lane = tid & 31;
    int wid = tid >> 5;
    int wr = wid & 1;      // warp row: m offset wr*64
    int wc = wid >> 1;     // warp col: n offset wc*32
    int bm = blockIdx.y * 128;
    int bn = blockIdx.x * 128;

    float acc[4][4][4];
    #pragma unroll
    for (int mi = 0; mi < 4; mi++)
        #pragma unroll
        for (int ni = 0; ni < 4; ni++)
            #pragma unroll
            for (int q = 0; q < 4; q++) acc[mi][ni][q] = 0.f;

    const int NC = Kk >> 6;   // BKT=64 chunks

    if (tid == 0) {
        #pragma unroll
        for (int s = 0; s < NSTAGE; s++) MBAR_INIT(smem_u32(&s_mbar[s]), 1);
    }
    __syncthreads();

    // prologue: issue chunks 0, 1
    if (tid == 0) {
        #pragma unroll
        for (int c0 = 0; c0 < 2; c0++) {
            if (c0 < NC) {
                uint32_t st = sbase + c0 * STAGE_BYTES;
                uint32_t mb = smem_u32(&s_mbar[c0]);
                MBAR_EXPECT(mb, STAGE_BYTES);
                TMA_LD2D(st + OFF_A, &tmA, c0 << 6, bm, mb);
                TMA_LD2D(st + OFF_B, &tmB, c0 << 6, bn, mb);
            }
        }
    }

    int a_row = wr * 64 + (lane & 15);
    int a_usel = (lane >> 4) & 1;
    int b_row = wc * 32 + (lane & 7) + ((lane >> 4) & 1) * 8;
    int b_usel = (lane >> 3) & 1;

    for (int c = 0; c < NC; c++) {
        int stg = c % NSTAGE;
        int ph = (c / NSTAGE) & 1;
        MBAR_WAIT(smem_u32(&s_mbar[stg]), ph);

        uint32_t st = sbase + stg * STAGE_BYTES;
        #pragma unroll
        for (int kk = 0; kk < 4; kk++) {
            uint32_t bh[8];
            #pragma unroll
            for (int g = 0; g < 2; g++) {
                int r = b_row + g * 16;
                uint32_t off = sw_off(r, kk * 2 + b_usel);
                LDMX4(bh[g*4+0], bh[g*4+1], bh[g*4+2], bh[g*4+3], st + OFF_B + off);
            }
            #pragma unroll
            for (int mi = 0; mi < 4; mi++) {
                uint32_t ah[4];
                int r = a_row + mi * 16;
                uint32_t off = sw_off(r, kk * 2 + a_usel);
                LDMX4(ah[0], ah[1], ah[2], ah[3], st + OFF_A + off);
                #pragma unroll
                for (int ni = 0; ni < 4; ni++) {
                    MMA_F16(acc[mi][ni], ah, bh[ni*2], bh[ni*2+1]);
                }
            }
        }
        __syncthreads();   // all warps done with chunk c -> stage (c+2)%3 is free
        if (tid == 0 && c + 2 < NC) {
            int cn = c + 2;
            uint32_t st2 = sbase + (cn % NSTAGE) * STAGE_BYTES;
            uint32_t mb = smem_u32(&s_mbar[cn % NSTAGE]);
            MBAR_EXPECT(mb, STAGE_BYTES);
            TMA_LD2D(st2 + OFF_A, &tmA, cn << 6, bm, mb);
            TMA_LD2D(st2 + OFF_B, &tmB, cn << 6, bn, mb);
        }
    }

    // epilogue
    int m0 = bm + wr * 64 + (lane >> 2);
    int n0 = bn + wc * 32 + (lane & 3) * 2;
    #pragma unroll
    for (int mi = 0; mi < 4; mi++) {
        #pragma unroll
        for (int r2 = 0; r2 < 2; r2++) {
            int row = m0 + mi * 16 + r2 * 8;
            size_t rbase = (size_t)row * Nn;
            #pragma unroll
            for (int ni = 0; ni < 4; ni++) {
                int col = n0 + ni * 8;
                float v0 = acc[mi][ni][r2*2+0] + bias[col];
                float v1 = acc[mi][ni][r2*2+1] + bias[col+1];
                if (epi == 0) {
                    *(float2*)(outF + rbase + col) = make_float2(v0, v1);
                } else if (epi == 1) {
                    float2 rv = *(const float2*)(res + rbase + col);
                    *(float2*)(outF + rbase + col) = make_float2(v0 + rv.x, v1 + rv.y);
                } else {
                    v0 = gelu_tanh(v0); v1 = gelu_tanh(v1);
                    *(__half2*)(outH + rbase + col) = __floats2half2_rn(v0, v1);
                }
            }
        }
    }
}

// ---------------- Sliding-window causal attention (W=16), smem-tiled ----------------
#define TQ 64
#define KR (TQ + WW - 1)     // 79 key rows
#define PK 68                // padded floats per smem row
#define ATTN_SMEM (2 * 80 * PK * 4)   // 43520 bytes

__global__ __launch_bounds__(256, 4)
void attn_kernel(const float* __restrict__ qkv,
                 __half* __restrict__ oh) {
    extern __shared__ __align__(16) float asm_f[];
    float* Ks = asm_f;                 // [80][PK]
    float* Vs = asm_f + 80 * PK;       // [80][PK]

    int tile = blockIdx.x;
    int h = blockIdx.y;
    int b = blockIdx.z;
    int s0 = tile * TQ;
    int tid = threadIdx.x;
    int lane = tid & 31;
    int w = tid >> 5;

    for (int i = tid; i < KR * (HD / 4); i += 256) {
        int r = i >> 4;
        int c = (i & 15) * 4;
        int seq = s0 - (WW - 1) + r;
        if (seq >= 0) {
            size_t base = ((size_t)(b * SS + seq)) * (3 * DD) + h * HD + c;
            *(float4*)&Ks[r * PK + c] = *(const float4*)(qkv + base + DD);
            *(float4*)&Vs[r * PK + c] = *(const float4*)(qkv + base + 2 * DD);
        }
    }
    __syncthreads();

    for (int qq = 0; qq < 8; qq++) {
        int qi = w * 8 + qq;
        int s = s0 + qi;
        int m = b * SS + s;
        const float* qp = qkv + (size_t)m * (3 * DD) + h * HD;

        float score = -INFINITY;
        if (lane < WW && lane <= s) {
            const float* kp = &Ks[(qi + WW - 1 - lane) * PK];
            float acc = 0.f;
            #pragma unroll
            for (int d = 0; d < HD; d += 4) {
                float4 qa = *(const float4*)(qp + d);
                float4 ka = *(const float4*)(kp + d);
                acc = fmaf(qa.x, ka.x, acc);
                acc = fmaf(qa.y, ka.y, acc);
                acc = fmaf(qa.z, ka.z, acc);
                acc = fmaf(qa.w, ka.w, acc);
            }
            score = acc * 0.125f;
        }
        float mx = score;
        for (int o = 16; o > 0; o >>= 1) mx = fmaxf(mx, __shfl_xor_sync(0xffffffffu, mx, o));
        float p = (score == -INFINITY) ? 0.f : __expf(score - mx);
        float sum = p;
        for (int o = 16; o > 0; o >>= 1) sum += __shfl_xor_sync(0xffffffffu, sum, o);
        float inv = 1.f / sum;

        float o0 = 0.f, o1 = 0.f;
        int jmax = min(WW - 1, s);
        for (int jj = 0; jj <= jmax; jj++) {
            float pj = __shfl_sync(0xffffffffu, p, jj);
            float2 vv = *(const float2*)&Vs[(qi + WW - 1 - jj) * PK + 2 * lane];
            o0 = fmaf(pj, vv.x, o0);
            o1 = fmaf(pj, vv.y, o1);
        }
        o0 *= inv; o1 *= inv;
        size_t idx = (size_t)m * DD + h * HD + 2 * lane;
        *(__half2*)(oh + idx) = __floats2half2_rn(o0, o1);
    }
}

// ---------------- launch ----------------
typedef CUresult (*PFN_encode)(CUtensorMap*, CUtensorMapDataType, cuuint32_t, void*,
                               const cuuint64_t*, const cuuint64_t*, const cuuint32_t*,
                               const cuuint32_t*, CUtensorMapInterleave, CUtensorMapSwizzle,
                               CUtensorMapL2promotion, CUtensorMapFloatOOBfill);

static void make_map(PFN_encode enc, CUtensorMap* m, void* ptr, uint64_t K, uint64_t R) {
    cuuint64_t dims[2]    = {K, R};
    cuuint64_t strides[1] = {K * 2};
    cuuint32_t box[2]     = {64, 128};
    cuuint32_t es[2]      = {1, 1};
    enc(m, CU_TENSOR_MAP_DATA_TYPE_FLOAT16, 2, ptr, dims, strides, box, es,
        CU_TENSOR_MAP_INTERLEAVE_NONE, CU_TENSOR_MAP_SWIZZLE_128B,
        CU_TENSOR_MAP_L2_PROMOTION_L2_128B, CU_TENSOR_MAP_FLOAT_OOB_FILL_NONE);
}

extern "C" void kernel_launch(void* const* d_in, const int* in_sizes, int n_in,
                              void* d_out, int out_size) {
    const float* x          = (const float*)d_in[0];
    const float* ln1_g      = (const float*)d_in[1];
    const float* ln1_b      = (const float*)d_in[2];
    const float* in_proj_w  = (const float*)d_in[3];
    const float* in_proj_b  = (const float*)d_in[4];
    const float* out_proj_w = (const float*)d_in[5];
    const float* out_proj_b = (const float*)d_in[6];
    const float* ln2_g      = (const float*)d_in[7];
    const float* ln2_b      = (const float*)d_in[8];
    const float* mlp_w1     = (const float*)d_in[9];
    const float* mlp_b1     = (const float*)d_in[10];
    const float* mlp_w2     = (const float*)d_in[11];
    const float* mlp_b2     = (const float*)d_in[12];
    float* out = (float*)d_out;

    float *p_qkv, *p_x1;
    __half *p_h, *p_at, *p_xn, *p_ff, *p_wq, *p_wo, *p_w1, *p_w2;
    cudaGetSymbolAddress((void**)&p_qkv, g_qkv);
    cudaGetSymbolAddress((void**)&p_x1,  g_x1);
    cudaGetSymbolAddress((void**)&p_h,   g_h_h);
    cudaGetSymbolAddress((void**)&p_at,  g_at_h);
    cudaGetSymbolAddress((void**)&p_xn,  g_xn_h);
    cudaGetSymbolAddress((void**)&p_ff,  g_ff_h);
    cudaGetSymbolAddress((void**)&p_wq,  g_wq_h);
    cudaGetSymbolAddress((void**)&p_wo,  g_wo_h);
    cudaGetSymbolAddress((void**)&p_w1,  g_w1_h);
    cudaGetSymbolAddress((void**)&p_w2,  g_w2_h);

    // driver entry point via runtime API (no -lcuda needed)
    PFN_encode enc = nullptr;
    cudaDriverEntryPointQueryResult qr;
    cudaGetDriverEntryPoint("cuTensorMapEncodeTiled", (void**)&enc,
                            cudaEnableDefault, &qr);

    CUtensorMap tm_h, tm_wq, tm_at, tm_wo, tm_xn, tm_w1, tm_ff, tm_w2;
    make_map(enc, &tm_h,  p_h,  DD,  MM);
    make_map(enc, &tm_wq, p_wq, DD,  3 * DD);
    make_map(enc, &tm_at, p_at, DD,  MM);
    make_map(enc, &tm_wo, p_wo, DD,  DD);
    make_map(enc, &tm_xn, p_xn, DD,  MM);
    make_map(enc, &tm_w1, p_w1, DD,  DFF);
    make_map(enc, &tm_ff, p_ff, DFF, MM);
    make_map(enc, &tm_w2, p_w2, DFF, DD);

    cudaFuncSetAttribute(gemmh, cudaFuncAttributeMaxDynamicSharedMemorySize, GEMM_SMEM);
    cudaFuncSetAttribute(attn_kernel, cudaFuncAttributeMaxDynamicSharedMemorySize, ATTN_SMEM);

    cvt_kernel<<<(3 * DD * DD) / 1024, 256>>>(in_proj_w, p_wq, 3 * DD * DD);
    ln_half_kernel<<<MM, 256>>>(x, ln1_g, ln1_b, p_h);
    // QKV = h @ W_in^T + b   [4096, 3072]
    gemmh<<<dim3(3 * DD / 128, MM / 128), 256, GEMM_SMEM>>>(
        tm_h, tm_wq, in_proj_b, nullptr, p_qkv, nullptr, 3 * DD, DD, 0);
    // windowed attention (smem-tiled) -> fp16
    attn_kernel<<<dim3(SS / TQ, HH, BB), 256, ATTN_SMEM>>>(p_qkv, p_at);
    cvt_kernel<<<(DD * DD) / 1024, 256>>>(out_proj_w, p_wo, DD * DD);
    // out proj + residual(x) -> x1 fp32  [4096, 1024]
    gemmh<<<dim3(DD / 128, MM / 128), 256, GEMM_SMEM>>>(
        tm_at, tm_wo, out_proj_b, x, p_x1, nullptr, DD, DD, 1);
    // LN2 -> fp16
    ln_half_kernel<<<MM, 256>>>(p_x1, ln2_g, ln2_b, p_xn);
    cvt_kernel<<<(DFF * DD) / 1024, 256>>>(mlp_w1, p_w1, DFF * DD);
    // MLP up + GELU -> fp16   [4096, 4096]
    gemmh<<<dim3(DFF / 128, MM / 128), 256, GEMM_SMEM>>>(
        tm_xn, tm_w1, mlp_b1, nullptr, nullptr, p_ff, DFF, DD, 2);
    cvt_kernel<<<(DD * DFF) / 1024, 256>>>(mlp_w2, p_w2, DD * DFF);
    // MLP down + residual(x1) -> out   [4096, 1024]
    gemmh<<<dim3(DD / 128, MM / 128), 256, GEMM_SMEM>>>(
        tm_ff, tm_w2, mlp_b2, p_x1, out, nullptr, DD, DFF, 1);
}

// round 10
// speedup vs baseline: 8.3472x; 1.0350x over previous
#include <cuda_runtime.h>
#include <cuda.h>
#include <cuda_fp16.h>
#include <math.h>
#include <stdint.h>

// Problem constants
#define BB 2
#define SS 2048
#define DD 1024
#define HH 16
#define HD 64
#define WW 16
#define DFF 4096
#define MM (BB * SS)   // 4096 rows

// ---------------- scratch (no allocations allowed) ----------------
__device__ __half g_qkv_h[MM * 3 * DD];       // QKV fp16
__device__ float g_x1[MM * DD];               // residual-1 output fp32
__device__ __half g_h_h[MM * DD];             // LN1 out fp16
__device__ __half g_at_h[MM * DD];            // attn out fp16
__device__ __half g_xn_h[MM * DD];            // LN2 out fp16
__device__ __half g_ff_h[MM * DFF];           // MLP hidden fp16
__device__ __half g_wq_h[3 * DD * DD];
__device__ __half g_wo_h[DD * DD];
__device__ __half g_w1_h[DFF * DD];
__device__ __half g_w2_h[DD * DFF];

__device__ __forceinline__ uint32_t smem_u32(const void* p) {
    return (uint32_t)__cvta_generic_to_shared(p);
}

__device__ __forceinline__ float gelu_tanh(float x) {
    float x3 = x * x * x;
    return 0.5f * x * (1.0f + tanhf(0.7978845608028654f * (x + 0.044715f * x3)));
}

// ---------------- merged weight convert kernel (fp32 -> fp16, 4 segments) ----------------
// block counts: wq 3072, wo 1024, w1 4096, w2 4096 (1024 elems per block)
__global__ void cvt4_kernel(const float* __restrict__ wq, __half* __restrict__ owq,
                            const float* __restrict__ wo, __half* __restrict__ owo,
                            const float* __restrict__ w1, __half* __restrict__ ow1,
                            const float* __restrict__ w2, __half* __restrict__ ow2) {
    int blk = blockIdx.x;
    const float* in; __half* out; int base;
    if (blk < 3072)       { in = wq; out = owq; base = blk; }
    else if (blk < 4096)  { in = wo; out = owo; base = blk - 3072; }
    else if (blk < 8192)  { in = w1; out = ow1; base = blk - 4096; }
    else                  { in = w2; out = ow2; base = blk - 8192; }
    int i = base * 1024 + threadIdx.x * 4;
    float4 v = *(const float4*)(in + i);
    *(__half2*)(out + i)     = __floats2half2_rn(v.x, v.y);
    *(__half2*)(out + i + 2) = __floats2half2_rn(v.z, v.w);
}

// ---------------- LayerNorm -> fp16 ----------------
__global__ void ln_half_kernel(const float* __restrict__ x,
                               const float* __restrict__ g,
                               const float* __restrict__ b,
                               __half* __restrict__ y) {
    int row = blockIdx.x;
    const float* xp = x + (size_t)row * DD;
    int i = threadIdx.x * 4;
    float4 xv = *(const float4*)(xp + i);
    float s  = xv.x + xv.y + xv.z + xv.w;
    float ss = xv.x*xv.x + xv.y*xv.y + xv.z*xv.z + xv.w*xv.w;
    for (int o = 16; o > 0; o >>= 1) {
        s  += __shfl_xor_sync(0xffffffffu, s,  o);
        ss += __shfl_xor_sync(0xffffffffu, ss, o);
    }
    __shared__ float sh_s[8], sh_ss[8];
    int wid = threadIdx.x >> 5, lane = threadIdx.x & 31;
    if (lane == 0) { sh_s[wid] = s; sh_ss[wid] = ss; }
    __syncthreads();
    if (wid == 0) {
        s  = (lane < 8) ? sh_s[lane]  : 0.f;
        ss = (lane < 8) ? sh_ss[lane] : 0.f;
        for (int o = 4; o > 0; o >>= 1) {
            s  += __shfl_xor_sync(0xffffffffu, s,  o);
            ss += __shfl_xor_sync(0xffffffffu, ss, o);
        }
        if (lane == 0) { sh_s[0] = s; sh_ss[0] = ss; }
    }
    __syncthreads();
    float mean = sh_s[0] * (1.0f / DD);
    float var  = sh_ss[0] * (1.0f / DD) - mean * mean;
    float inv  = rsqrtf(var + 1e-5f);
    float4 gv = *(const float4*)(g + i);
    float4 bv = *(const float4*)(b + i);
    float o0 = (xv.x - mean) * inv * gv.x + bv.x;
    float o1 = (xv.y - mean) * inv * gv.y + bv.y;
    float o2 = (xv.z - mean) * inv * gv.z + bv.z;
    float o3 = (xv.w - mean) * inv * gv.w + bv.w;
    size_t idx = (size_t)row * DD + i;
    *(__half2*)(y + idx)     = __floats2half2_rn(o0, o1);
    *(__half2*)(y + idx + 2) = __floats2half2_rn(o2, o3);
}

// ---------------- TMA + mma.sync fp16 GEMM: C[M,N] = A[M,K] @ Bw[N,K]^T (+epi) ----------------
// 3-stage TMA pipeline, SW128-swizzled smem (128B rows), mbarrier per stage.
// Tile bases MUST be 1024B-aligned so the manual swizzle matches TMA's.
// epi: 0 = +bias -> fp16 ; 1 = fp32 +bias+res ; 2 = gelu(+bias) -> fp16
#define BKT 64
#define TILE_BYTES (128 * 128)          // 16384 (64 fp16 = 128 B per row)
#define OFF_A 0
#define OFF_B TILE_BYTES
#define STAGE_BYTES (2 * TILE_BYTES)    // 32768
#define NSTAGE 3
#define GEMM_SMEM (NSTAGE * STAGE_BYTES + 1024)  // 99328 (1KB alignment slack)

#define LDMX4(r0, r1, r2, r3, addr) \
    asm volatile("ldmatrix.sync.aligned.m8n8.x4.shared.b16 {%0,%1,%2,%3}, [%4];" \
                 : "=r"(r0), "=r"(r1), "=r"(r2), "=r"(r3) : "r"(addr))

#define MMA_F16(d, a, b0, b1) \
    asm volatile("mma.sync.aligned.m16n8k16.row.col.f32.f16.f16.f32 " \
                 "{%0,%1,%2,%3}, {%4,%5,%6,%7}, {%8,%9}, {%0,%1,%2,%3};" \
                 : "+f"((d)[0]), "+f"((d)[1]), "+f"((d)[2]), "+f"((d)[3]) \
                 : "r"((a)[0]), "r"((a)[1]), "r"((a)[2]), "r"((a)[3]), "r"(b0), "r"(b1))

#define MBAR_INIT(mbar, cnt) \
    asm volatile("mbarrier.init.shared.b64 [%0], %1;" :: "r"(mbar), "r"(cnt) : "memory")

#define MBAR_EXPECT(mbar, bytes) \
    asm volatile("mbarrier.arrive.expect_tx.shared.b64 _, [%0], %1;" :: "r"(mbar), "r"(bytes) : "memory")

#define MBAR_WAIT(mbar, parity) do {                                            \
    uint32_t _m = (mbar); uint32_t _p = (parity); uint32_t _d;                  \
    asm volatile("{\n\t.reg .pred p;\n\t"                                       \
        "mbarrier.try_wait.parity.acquire.cta.shared::cta.b64 p, [%1], %2;\n\t" \
        "selp.b32 %0, 1, 0, p;\n\t}"                                            \
        : "=r"(_d) : "r"(_m), "r"(_p) : "memory");                              \
    if (!_d) {                                                                  \
        asm volatile("{\n\t.reg .pred P1;\n\t"                                  \
            "WL_%=:\n\t"                                                        \
            "mbarrier.try_wait.parity.acquire.cta.shared::cta.b64 P1, [%0], %1, 0x989680;\n\t" \
            "@P1 bra.uni WD_%=;\n\t"                                            \
            "bra.uni WL_%=;\n\t"                                                \
            "WD_%=:\n\t}" :: "r"(_m), "r"(_p) : "memory");                      \
    }                                                                           \
} while (0)

#define TMA_LD2D(smem, tmap, cx, cy, mbar) \
    asm volatile("cp.async.bulk.tensor.2d.shared::cta.global.tile.mbarrier::complete_tx::bytes " \
                 "[%0], [%1, {%2, %3}], [%4];" \
                 :: "r"(smem), "l"(tmap), "r"(cx), "r"(cy), "r"(mbar) : "memory")

// swizzled byte offset inside one 128x64(fp16) tile: row r (0..127), 16B unit u (0..7)
// valid ONLY when tile base is 1024B-aligned
__device__ __forceinline__ uint32_t sw_off(int r, int u) {
    return (uint32_t)(r * 128 + ((u ^ (r & 7)) << 4));
}

__global__ __launch_bounds__(256, 2)
void gemmh(const __grid_constant__ CUtensorMap tmA,
           const __grid_constant__ CUtensorMap tmB,
           const float* __restrict__ bias, const float* __restrict__ res,
           float* __restrict__ outF, __half* __restrict__ outH,
           int Nn, int Kk, int epi) {
    extern __shared__ __align__(128) char dsm[];
    __shared__ __align__(8) uint64_t s_mbar[NSTAGE];
    uint32_t sbase = (smem_u32(dsm) + 1023) & ~1023u;   // 1024B-align: swizzle phase contract
    int tid = threadIdx.x;
    int lane = tid & 31;
    int wid = tid >> 5;
    int wr = wid & 1;      // warp row: m offset wr*64
    int wc = wid >> 1;     // warp col: n offset wc*32
    int bm = blockIdx.y * 128;
    int bn = blockIdx.x * 128;

    float acc[4][4][4];
    #pragma unroll
    for (int mi = 0; mi < 4; mi++)
        #pragma unroll
        for (int ni = 0; ni < 4; ni++)
            #pragma unroll
            for (int q = 0; q < 4; q++) acc[mi][ni][q] = 0.f;

    const int NC = Kk >> 6;   // BKT=64 chunks

    if (tid == 0) {
        #pragma unroll
        for (int s = 0; s < NSTAGE; s++) MBAR_INIT(smem_u32(&s_mbar[s]), 1);
    }
    __syncthreads();

    // prologue: issue chunks 0, 1
    if (tid == 0) {
        #pragma unroll
        for (int c0 = 0; c0 < 2; c0++) {
            if (c0 < NC) {
                uint32_t st = sbase + c0 * STAGE_BYTES;
                uint32_t mb = smem_u32(&s_mbar[c0]);
                MBAR_EXPECT(mb, STAGE_BYTES);
                TMA_LD2D(st + OFF_A, &tmA, c0 << 6, bm, mb);
                TMA_LD2D(st + OFF_B, &tmB, c0 << 6, bn, mb);
            }
        }
    }

    int a_row = wr * 64 + (lane & 15);
    int a_usel = (lane >> 4) & 1;
    int b_row = wc * 32 + (lane & 7) + ((lane >> 4) & 1) * 8;
    int b_usel = (lane >> 3) & 1;

    for (int c = 0; c < NC; c++) {
        int stg = c % NSTAGE;
        int ph = (c / NSTAGE) & 1;
        MBAR_WAIT(smem_u32(&s_mbar[stg]), ph);

        uint32_t st = sbase + stg * STAGE_BYTES;
        #pragma unroll
        for (int kk = 0; kk < 4; kk++) {
            uint32_t bh[8];
            #pragma unroll
            for (int g = 0; g < 2; g++) {
                int r = b_row + g * 16;
                uint32_t off = sw_off(r, kk * 2 + b_usel);
                LDMX4(bh[g*4+0], bh[g*4+1], bh[g*4+2], bh[g*4+3], st + OFF_B + off);
            }
            #pragma unroll
            for (int mi = 0; mi < 4; mi++) {
                uint32_t ah[4];
                int r = a_row + mi * 16;
                uint32_t off = sw_off(r, kk * 2 + a_usel);
                LDMX4(ah[0], ah[1], ah[2], ah[3], st + OFF_A + off);
                #pragma unroll
                for (int ni = 0; ni < 4; ni++) {
                    MMA_F16(acc[mi][ni], ah, bh[ni*2], bh[ni*2+1]);
                }
            }
        }
        __syncthreads();   // all warps done with chunk c -> stage (c+2)%3 is free
        if (tid == 0 && c + 2 < NC) {
            int cn = c + 2;
            uint32_t st2 = sbase + (cn % NSTAGE) * STAGE_BYTES;
            uint32_t mb = smem_u32(&s_mbar[cn % NSTAGE]);
            MBAR_EXPECT(mb, STAGE_BYTES);
            TMA_LD2D(st2 + OFF_A, &tmA, cn << 6, bm, mb);
            TMA_LD2D(st2 + OFF_B, &tmB, cn << 6, bn, mb);
        }
    }

    // epilogue
    int m0 = bm + wr * 64 + (lane >> 2);
    int n0 = bn + wc * 32 + (lane & 3) * 2;
    #pragma unroll
    for (int mi = 0; mi < 4; mi++) {
        #pragma unroll
        for (int r2 = 0; r2 < 2; r2++) {
            int row = m0 + mi * 16 + r2 * 8;
            size_t rbase = (size_t)row * Nn;
            #pragma unroll
            for (int ni = 0; ni < 4; ni++) {
                int col = n0 + ni * 8;
                float v0 = acc[mi][ni][r2*2+0] + bias[col];
                float v1 = acc[mi][ni][r2*2+1] + bias[col+1];
                if (epi == 0) {
                    *(__half2*)(outH + rbase + col) = __floats2half2_rn(v0, v1);
                } else if (epi == 1) {
                    float2 rv = *(const float2*)(res + rbase + col);
                    *(float2*)(outF + rbase + col) = make_float2(v0 + rv.x, v1 + rv.y);
                } else {
                    v0 = gelu_tanh(v0); v1 = gelu_tanh(v1);
                    *(__half2*)(outH + rbase + col) = __floats2half2_rn(v0, v1);
                }
            }
        }
    }
}

// ---------------- Sliding-window causal attention (W=16), fp16 smem-tiled ----------------
#define TQ 64
#define KR (TQ + WW - 1)     // 79 key rows
#define PKH 72               // halves per smem row (144B, 16B-aligned rows)
#define ATTN_SMEM (2 * 80 * PKH * 2)   // 23040 bytes

__global__ __launch_bounds__(256, 6)
void attn_kernel(const __half* __restrict__ qkv,
                 __half* __restrict__ oh) {
    extern __shared__ __align__(16) __half asm_h[];
    __half* Ks = asm_h;                 // [80][PKH]
    __half* Vs = asm_h + 80 * PKH;      // [80][PKH]

    int tile = blockIdx.x;
    int h = blockIdx.y;
    int b = blockIdx.z;
    int s0 = tile * TQ;
    int tid = threadIdx.x;
    int lane = tid & 31;
    int w = tid >> 5;

    // cooperative load: 79 rows x 64 halves, 16B (8-half) chunks
    for (int i = tid; i < KR * (HD / 8); i += 256) {
        int r = i >> 3;
        int c = (i & 7) * 8;
        int seq = s0 - (WW - 1) + r;
        if (seq >= 0) {
            size_t base = ((size_t)(b * SS + seq)) * (3 * DD) + h * HD + c;
            *(float4*)&Ks[r * PKH + c] = *(const float4*)(qkv + base + DD);
            *(float4*)&Vs[r * PKH + c] = *(const float4*)(qkv + base + 2 * DD);
        }
    }
    __syncthreads();

    for (int qq = 0; qq < 8; qq++) {
        int qi = w * 8 + qq;
        int s = s0 + qi;
        int m = b * SS + s;
        const __half* qp = qkv + (size_t)m * (3 * DD) + h * HD;

        float score = -INFINITY;
        if (lane < WW && lane <= s) {
            const __half* kp = &Ks[(qi + WW - 1 - lane) * PKH];
            float acc = 0.f;
            #pragma unroll
            for (int d = 0; d < HD; d += 8) {
                float4 qa4 = *(const float4*)(qp + d);
                float4 ka4 = *(const float4*)(kp + d);
                const __half2* qh = (const __half2*)&qa4;
                const __half2* kh = (const __half2*)&ka4;
                #pragma unroll
                for (int t = 0; t < 4; t++) {
                    float2 qf = __half22float2(qh[t]);
                    float2 kf = __half22float2(kh[t]);
                    acc = fmaf(qf.x, kf.x, acc);
                    acc = fmaf(qf.y, kf.y, acc);
                }
            }
            score = acc * 0.125f;
        }
        float mx = score;
        for (int o = 16; o > 0; o >>= 1) mx = fmaxf(mx, __shfl_xor_sync(0xffffffffu, mx, o));
        float p = (score == -INFINITY) ? 0.f : __expf(score - mx);
        float sum = p;
        for (int o = 16; o > 0; o >>= 1) sum += __shfl_xor_sync(0xffffffffu, sum, o);
        float inv = 1.f / sum;

        // V accumulation: lane owns dims 2*lane, 2*lane+1
        float o0 = 0.f, o1 = 0.f;
        int jmax = min(WW - 1, s);
        for (int jj = 0; jj <= jmax; jj++) {
            float pj = __shfl_sync(0xffffffffu, p, jj);
            float2 vv = __half22float2(*(const __half2*)&Vs[(qi + WW - 1 - jj) * PKH + 2 * lane]);
            o0 = fmaf(pj, vv.x, o0);
            o1 = fmaf(pj, vv.y, o1);
        }
        o0 *= inv; o1 *= inv;
        size_t idx = (size_t)m * DD + h * HD + 2 * lane;
        *(__half2*)(oh + idx) = __floats2half2_rn(o0, o1);
    }
}

// ---------------- launch ----------------
typedef CUresult (*PFN_encode)(CUtensorMap*, CUtensorMapDataType, cuuint32_t, void*,
                               const cuuint64_t*, const cuuint64_t*, const cuuint32_t*,
                               const cuuint32_t*, CUtensorMapInterleave, CUtensorMapSwizzle,
                               CUtensorMapL2promotion, CUtensorMapFloatOOBfill);

static void make_map(PFN_encode enc, CUtensorMap* m, void* ptr, uint64_t K, uint64_t R) {
    cuuint64_t dims[2]    = {K, R};
    cuuint64_t strides[1] = {K * 2};
    cuuint32_t box[2]     = {64, 128};
    cuuint32_t es[2]      = {1, 1};
    enc(m, CU_TENSOR_MAP_DATA_TYPE_FLOAT16, 2, ptr, dims, strides, box, es,
        CU_TENSOR_MAP_INTERLEAVE_NONE, CU_TENSOR_MAP_SWIZZLE_128B,
        CU_TENSOR_MAP_L2_PROMOTION_L2_128B, CU_TENSOR_MAP_FLOAT_OOB_FILL_NONE);
}

extern "C" void kernel_launch(void* const* d_in, const int* in_sizes, int n_in,
                              void* d_out, int out_size) {
    const float* x          = (const float*)d_in[0];
    const float* ln1_g      = (const float*)d_in[1];
    const float* ln1_b      = (const float*)d_in[2];
    const float* in_proj_w  = (const float*)d_in[3];
    const float* in_proj_b  = (const float*)d_in[4];
    const float* out_proj_w = (const float*)d_in[5];
    const float* out_proj_b = (const float*)d_in[6];
    const float* ln2_g      = (const float*)d_in[7];
    const float* ln2_b      = (const float*)d_in[8];
    const float* mlp_w1     = (const float*)d_in[9];
    const float* mlp_b1     = (const float*)d_in[10];
    const float* mlp_w2     = (const float*)d_in[11];
    const float* mlp_b2     = (const float*)d_in[12];
    float* out = (float*)d_out;

    float *p_x1;
    __half *p_qkvh, *p_h, *p_at, *p_xn, *p_ff, *p_wq, *p_wo, *p_w1, *p_w2;
    cudaGetSymbolAddress((void**)&p_qkvh, g_qkv_h);
    cudaGetSymbolAddress((void**)&p_x1,  g_x1);
    cudaGetSymbolAddress((void**)&p_h,   g_h_h);
    cudaGetSymbolAddress((void**)&p_at,  g_at_h);
    cudaGetSymbolAddress((void**)&p_xn,  g_xn_h);
    cudaGetSymbolAddress((void**)&p_ff,  g_ff_h);
    cudaGetSymbolAddress((void**)&p_wq,  g_wq_h);
    cudaGetSymbolAddress((void**)&p_wo,  g_wo_h);
    cudaGetSymbolAddress((void**)&p_w1,  g_w1_h);
    cudaGetSymbolAddress((void**)&p_w2,  g_w2_h);

    // driver entry point via runtime API (no -lcuda needed)
    PFN_encode enc = nullptr;
    cudaDriverEntryPointQueryResult qr;
    cudaGetDriverEntryPoint("cuTensorMapEncodeTiled", (void**)&enc,
                            cudaEnableDefault, &qr);

    CUtensorMap tm_h, tm_wq, tm_at, tm_wo, tm_xn, tm_w1, tm_ff, tm_w2;
    make_map(enc, &tm_h,  p_h,  DD,  MM);
    make_map(enc, &tm_wq, p_wq, DD,  3 * DD);
    make_map(enc, &tm_at, p_at, DD,  MM);
    make_map(enc, &tm_wo, p_wo, DD,  DD);
    make_map(enc, &tm_xn, p_xn, DD,  MM);
    make_map(enc, &tm_w1, p_w1, DD,  DFF);
    make_map(enc, &tm_ff, p_ff, DFF, MM);
    make_map(enc, &tm_w2, p_w2, DFF, DD);

    cudaFuncSetAttribute(gemmh, cudaFuncAttributeMaxDynamicSharedMemorySize, GEMM_SMEM);
    cudaFuncSetAttribute(attn_kernel, cudaFuncAttributeMaxDynamicSharedMemorySize, ATTN_SMEM);

    cvt4_kernel<<<12288, 256>>>(in_proj_w, p_wq, out_proj_w, p_wo,
                                mlp_w1, p_w1, mlp_w2, p_w2);
    ln_half_kernel<<<MM, 256>>>(x, ln1_g, ln1_b, p_h);
    // QKV = h @ W_in^T + b -> fp16   [4096, 3072]
    gemmh<<<dim3(3 * DD / 128, MM / 128), 256, GEMM_SMEM>>>(
        tm_h, tm_wq, in_proj_b, nullptr, nullptr, p_qkvh, 3 * DD, DD, 0);
    // windowed attention (fp16 smem-tiled) -> fp16
    attn_kernel<<<dim3(SS / TQ, HH, BB), 256, ATTN_SMEM>>>(p_qkvh, p_at);
    // out proj + residual(x) -> x1 fp32  [4096, 1024]
    gemmh<<<dim3(DD / 128, MM / 128), 256, GEMM_SMEM>>>(
        tm_at, tm_wo, out_proj_b, x, p_x1, nullptr, DD, DD, 1);
    // LN2 -> fp16
    ln_half_kernel<<<MM, 256>>>(p_x1, ln2_g, ln2_b, p_xn);
    // MLP up + GELU -> fp16   [4096, 4096]
    gemmh<<<dim3(DFF / 128, MM / 128), 256, GEMM_SMEM>>>(
        tm_xn, tm_w1, mlp_b1, nullptr, nullptr, p_ff, DFF, DD, 2);
    // MLP down + residual(x1) -> out   [4096, 1024]
    gemmh<<<dim3(DD / 128, MM / 128), 256, GEMM_SMEM>>>(
        tm_ff, tm_w2, mlp_b2, p_x1, out, nullptr, DD, DFF, 1);
}

// round 11
// speedup vs baseline: 8.8672x; 1.0623x over previous
#include <cuda_runtime.h>
#include <cuda.h>
#include <cuda_fp16.h>
#include <math.h>
#include <stdint.h>

// Problem constants
#define BB 2
#define SS 2048
#define DD 1024
#define HH 16
#define HD 64
#define WW 16
#define DFF 4096
#define MM (BB * SS)   // 4096 rows

// ---------------- scratch (no allocations allowed) ----------------
__device__ __half g_qkv_h[MM * 3 * DD];       // QKV fp16
__device__ float g_x1[MM * DD];               // residual-1 output fp32
__device__ __half g_h_h[MM * DD];             // LN1 out fp16
__device__ __half g_at_h[MM * DD];            // attn out fp16
__device__ __half g_xn_h[MM * DD];            // LN2 out fp16
__device__ __half g_ff_h[MM * DFF];           // MLP hidden fp16
__device__ __half g_wq_h[3 * DD * DD];
__device__ __half g_wo_h[DD * DD];
__device__ __half g_w1_h[DFF * DD];
__device__ __half g_w2_h[DD * DFF];

__device__ __forceinline__ uint32_t smem_u32(const void* p) {
    return (uint32_t)__cvta_generic_to_shared(p);
}

__device__ __forceinline__ float gelu_tanh(float x) {
    float x3 = x * x * x;
    return 0.5f * x * (1.0f + tanhf(0.7978845608028654f * (x + 0.044715f * x3)));
}

// ---------------- merged weight convert kernel (fp32 -> fp16, 4 segments) ----------------
__global__ void cvt4_kernel(const float* __restrict__ wq, __half* __restrict__ owq,
                            const float* __restrict__ wo, __half* __restrict__ owo,
                            const float* __restrict__ w1, __half* __restrict__ ow1,
                            const float* __restrict__ w2, __half* __restrict__ ow2) {
    int blk = blockIdx.x;
    const float* in; __half* out; int base;
    if (blk < 3072)       { in = wq; out = owq; base = blk; }
    else if (blk < 4096)  { in = wo; out = owo; base = blk - 3072; }
    else if (blk < 8192)  { in = w1; out = ow1; base = blk - 4096; }
    else                  { in = w2; out = ow2; base = blk - 8192; }
    int i = base * 1024 + threadIdx.x * 4;
    float4 v = *(const float4*)(in + i);
    *(__half2*)(out + i)     = __floats2half2_rn(v.x, v.y);
    *(__half2*)(out + i + 2) = __floats2half2_rn(v.z, v.w);
}

// ---------------- LayerNorm -> fp16 ----------------
__global__ void ln_half_kernel(const float* __restrict__ x,
                               const float* __restrict__ g,
                               const float* __restrict__ b,
                               __half* __restrict__ y) {
    int row = blockIdx.x;
    const float* xp = x + (size_t)row * DD;
    int i = threadIdx.x * 4;
    float4 xv = *(const float4*)(xp + i);
    float s  = xv.x + xv.y + xv.z + xv.w;
    float ss = xv.x*xv.x + xv.y*xv.y + xv.z*xv.z + xv.w*xv.w;
    for (int o = 16; o > 0; o >>= 1) {
        s  += __shfl_xor_sync(0xffffffffu, s,  o);
        ss += __shfl_xor_sync(0xffffffffu, ss, o);
    }
    __shared__ float sh_s[8], sh_ss[8];
    int wid = threadIdx.x >> 5, lane = threadIdx.x & 31;
    if (lane == 0) { sh_s[wid] = s; sh_ss[wid] = ss; }
    __syncthreads();
    if (wid == 0) {
        s  = (lane < 8) ? sh_s[lane]  : 0.f;
        ss = (lane < 8) ? sh_ss[lane] : 0.f;
        for (int o = 4; o > 0; o >>= 1) {
            s  += __shfl_xor_sync(0xffffffffu, s,  o);
            ss += __shfl_xor_sync(0xffffffffu, ss, o);
        }
        if (lane == 0) { sh_s[0] = s; sh_ss[0] = ss; }
    }
    __syncthreads();
    float mean = sh_s[0] * (1.0f / DD);
    float var  = sh_ss[0] * (1.0f / DD) - mean * mean;
    float inv  = rsqrtf(var + 1e-5f);
    float4 gv = *(const float4*)(g + i);
    float4 bv = *(const float4*)(b + i);
    float o0 = (xv.x - mean) * inv * gv.x + bv.x;
    float o1 = (xv.y - mean) * inv * gv.y + bv.y;
    float o2 = (xv.z - mean) * inv * gv.z + bv.z;
    float o3 = (xv.w - mean) * inv * gv.w + bv.w;
    size_t idx = (size_t)row * DD + i;
    *(__half2*)(y + idx)     = __floats2half2_rn(o0, o1);
    *(__half2*)(y + idx + 2) = __floats2half2_rn(o2, o3);
}

// ---------------- TMA + mma.sync fp16 GEMM: C[M,N] = A[M,K] @ Bw[N,K]^T (+epi) ----------------
// 3-stage TMA pipeline, SW128-swizzled smem (128B rows), mbarrier per stage.
// Tile bases MUST be 1024B-aligned so the manual swizzle matches TMA's.
// epi: 0 = +bias -> fp16 ; 1 = fp32 +bias+res ; 2 = gelu(+bias) -> fp16
#define BKT 64
#define TILE_BYTES (128 * 128)          // 16384 (64 fp16 = 128 B per row)
#define OFF_A 0
#define OFF_B TILE_BYTES
#define STAGE_BYTES (2 * TILE_BYTES)    // 32768
#define NSTAGE 3
#define GEMM_SMEM (NSTAGE * STAGE_BYTES + 1024)  // 99328 (1KB alignment slack)

#define LDMX4(r0, r1, r2, r3, addr) \
    asm volatile("ldmatrix.sync.aligned.m8n8.x4.shared.b16 {%0,%1,%2,%3}, [%4];" \
                 : "=r"(r0), "=r"(r1), "=r"(r2), "=r"(r3) : "r"(addr))

#define MMA_F16(d, a, b0, b1) \
    asm volatile("mma.sync.aligned.m16n8k16.row.col.f32.f16.f16.f32 " \
                 "{%0,%1,%2,%3}, {%4,%5,%6,%7}, {%8,%9}, {%0,%1,%2,%3};" \
                 : "+f"((d)[0]), "+f"((d)[1]), "+f"((d)[2]), "+f"((d)[3]) \
                 : "r"((a)[0]), "r"((a)[1]), "r"((a)[2]), "r"((a)[3]), "r"(b0), "r"(b1))

#define MBAR_INIT(mbar, cnt) \
    asm volatile("mbarrier.init.shared.b64 [%0], %1;" :: "r"(mbar), "r"(cnt) : "memory")

#define MBAR_EXPECT(mbar, bytes) \
    asm volatile("mbarrier.arrive.expect_tx.shared.b64 _, [%0], %1;" :: "r"(mbar), "r"(bytes) : "memory")

#define MBAR_WAIT(mbar, parity) do {                                            \
    uint32_t _m = (mbar); uint32_t _p = (parity); uint32_t _d;                  \
    asm volatile("{\n\t.reg .pred p;\n\t"                                       \
        "mbarrier.try_wait.parity.acquire.cta.shared::cta.b64 p, [%1], %2;\n\t" \
        "selp.b32 %0, 1, 0, p;\n\t}"                                            \
        : "=r"(_d) : "r"(_m), "r"(_p) : "memory");                              \
    if (!_d) {                                                                  \
        asm volatile("{\n\t.reg .pred P1;\n\t"                                  \
            "WL_%=:\n\t"                                                        \
            "mbarrier.try_wait.parity.acquire.cta.shared::cta.b64 P1, [%0], %1, 0x989680;\n\t" \
            "@P1 bra.uni WD_%=;\n\t"                                            \
            "bra.uni WL_%=;\n\t"                                                \
            "WD_%=:\n\t}" :: "r"(_m), "r"(_p) : "memory");                      \
    }                                                                           \
} while (0)

#define TMA_LD2D(smem, tmap, cx, cy, mbar) \
    asm volatile("cp.async.bulk.tensor.2d.shared::cta.global.tile.mbarrier::complete_tx::bytes " \
                 "[%0], [%1, {%2, %3}], [%4];" \
                 :: "r"(smem), "l"(tmap), "r"(cx), "r"(cy), "r"(mbar) : "memory")

// swizzled byte offset inside one 128x64(fp16) tile: row r (0..127), 16B unit u (0..7)
// valid ONLY when tile base is 1024B-aligned
__device__ __forceinline__ uint32_t sw_off(int r, int u) {
    return (uint32_t)(r * 128 + ((u ^ (r & 7)) << 4));
}

__global__ __launch_bounds__(256, 2)
void gemmh(const __grid_constant__ CUtensorMap tmA,
           const __grid_constant__ CUtensorMap tmB,
           const float* __restrict__ bias, const float* __restrict__ res,
           float* __restrict__ outF, __half* __restrict__ outH,
           int Nn, int Kk, int epi) {
    extern __shared__ __align__(128) char dsm[];
    __shared__ __align__(8) uint64_t s_mbar[NSTAGE];
    uint32_t sbase = (smem_u32(dsm) + 1023) & ~1023u;   // 1024B-align: swizzle phase contract
    int tid = threadIdx.x;
    int lane = tid & 31;
    int wid = tid >> 5;
    int wr = wid & 1;      // warp row: m offset wr*64
    int wc = wid >> 1;     // warp col: n offset wc*32
    int bm = blockIdx.y * 128;
    int bn = blockIdx.x * 128;

    float acc[4][4][4];
    #pragma unroll
    for (int mi = 0; mi < 4; mi++)
        #pragma unroll
        for (int ni = 0; ni < 4; ni++)
            #pragma unroll
            for (int q = 0; q < 4; q++) acc[mi][ni][q] = 0.f;

    const int NC = Kk >> 6;   // BKT=64 chunks

    if (tid == 0) {
        #pragma unroll
        for (int s = 0; s < NSTAGE; s++) MBAR_INIT(smem_u32(&s_mbar[s]), 1);
    }
    __syncthreads();

    // prologue: issue chunks 0, 1
    if (tid == 0) {
        #pragma unroll
        for (int c0 = 0; c0 < 2; c0++) {
            if (c0 < NC) {
                uint32_t st = sbase + c0 * STAGE_BYTES;
                uint32_t mb = smem_u32(&s_mbar[c0]);
                MBAR_EXPECT(mb, STAGE_BYTES);
                TMA_LD2D(st + OFF_A, &tmA, c0 << 6, bm, mb);
                TMA_LD2D(st + OFF_B, &tmB, c0 << 6, bn, mb);
            }
        }
    }

    int a_row = wr * 64 + (lane & 15);
    int a_usel = (lane >> 4) & 1;
    int b_row = wc * 32 + (lane & 7) + ((lane >> 4) & 1) * 8;
    int b_usel = (lane >> 3) & 1;

    for (int c = 0; c < NC; c++) {
        int stg = c % NSTAGE;
        int ph = (c / NSTAGE) & 1;
        MBAR_WAIT(smem_u32(&s_mbar[stg]), ph);

        uint32_t st = sbase + stg * STAGE_BYTES;
        #pragma unroll
        for (int kk = 0; kk < 4; kk++) {
            uint32_t bh[8];
            #pragma unroll
            for (int g = 0; g < 2; g++) {
                int r = b_row + g * 16;
                uint32_t off = sw_off(r, kk * 2 + b_usel);
                LDMX4(bh[g*4+0], bh[g*4+1], bh[g*4+2], bh[g*4+3], st + OFF_B + off);
            }
            #pragma unroll
            for (int mi = 0; mi < 4; mi++) {
                uint32_t ah[4];
                int r = a_row + mi * 16;
                uint32_t off = sw_off(r, kk * 2 + a_usel);
                LDMX4(ah[0], ah[1], ah[2], ah[3], st + OFF_A + off);
                #pragma unroll
                for (int ni = 0; ni < 4; ni++) {
                    MMA_F16(acc[mi][ni], ah, bh[ni*2], bh[ni*2+1]);
                }
            }
        }
        __syncthreads();   // all warps done with chunk c -> stage (c+2)%3 is free
        if (tid == 0 && c + 2 < NC) {
            int cn = c + 2;
            uint32_t st2 = sbase + (cn % NSTAGE) * STAGE_BYTES;
            uint32_t mb = smem_u32(&s_mbar[cn % NSTAGE]);
            MBAR_EXPECT(mb, STAGE_BYTES);
            TMA_LD2D(st2 + OFF_A, &tmA, cn << 6, bm, mb);
            TMA_LD2D(st2 + OFF_B, &tmB, cn << 6, bn, mb);
        }
    }

    // epilogue
    int m0 = bm + wr * 64 + (lane >> 2);
    int n0 = bn + wc * 32 + (lane & 3) * 2;
    #pragma unroll
    for (int mi = 0; mi < 4; mi++) {
        #pragma unroll
        for (int r2 = 0; r2 < 2; r2++) {
            int row = m0 + mi * 16 + r2 * 8;
            size_t rbase = (size_t)row * Nn;
            #pragma unroll
            for (int ni = 0; ni < 4; ni++) {
                int col = n0 + ni * 8;
                float v0 = acc[mi][ni][r2*2+0] + bias[col];
                float v1 = acc[mi][ni][r2*2+1] + bias[col+1];
                if (epi == 0) {
                    *(__half2*)(outH + rbase + col) = __floats2half2_rn(v0, v1);
                } else if (epi == 1) {
                    float2 rv = *(const float2*)(res + rbase + col);
                    *(float2*)(outF + rbase + col) = make_float2(v0 + rv.x, v1 + rv.y);
                } else {
                    v0 = gelu_tanh(v0); v1 = gelu_tanh(v1);
                    *(__half2*)(outH + rbase + col) = __floats2half2_rn(v0, v1);
                }
            }
        }
    }
}

// ---------------- Sliding-window causal attention (W=16), fp16, dual-query warps ----------------
// Lanes 0-15 score query A, lanes 16-31 score query B (no idle half-warp).
#define TQ 64
#define KR (TQ + WW - 1)     // 79 key rows
#define PKH 72               // halves per smem row (144B, 16B-aligned rows)
#define ATTN_SMEM (2 * 80 * PKH * 2)   // 23040 bytes

__global__ __launch_bounds__(256, 6)
void attn_kernel(const __half* __restrict__ qkv,
                 __half* __restrict__ oh) {
    extern __shared__ __align__(16) __half asm_h[];
    __half* Ks = asm_h;                 // [80][PKH]
    __half* Vs = asm_h + 80 * PKH;      // [80][PKH]

    int tile = blockIdx.x;
    int h = blockIdx.y;
    int b = blockIdx.z;
    int s0 = tile * TQ;
    int tid = threadIdx.x;
    int lane = tid & 31;
    int w = tid >> 5;

    // cooperative load: 79 rows x 64 halves, 16B chunks; zero-fill seq<0 rows
    for (int i = tid; i < KR * (HD / 8); i += 256) {
        int r = i >> 3;
        int c = (i & 7) * 8;
        int seq = s0 - (WW - 1) + r;
        if (seq >= 0) {
            size_t base = ((size_t)(b * SS + seq)) * (3 * DD) + h * HD + c;
            *(float4*)&Ks[r * PKH + c] = *(const float4*)(qkv + base + DD);
            *(float4*)&Vs[r * PKH + c] = *(const float4*)(qkv + base + 2 * DD);
        } else {
            float4 z = make_float4(0.f, 0.f, 0.f, 0.f);
            *(float4*)&Ks[r * PKH + c] = z;
            *(float4*)&Vs[r * PKH + c] = z;
        }
    }
    __syncthreads();

    int half = lane >> 4;   // 0: query A, 1: query B
    int hl = lane & 15;     // key offset j for the score phase

    for (int qq = 0; qq < 4; qq++) {
        int qi = w * 8 + qq * 2 + half;   // this lane's score query (local)
        int s = s0 + qi;
        int m = b * SS + s;
        const __half* qp = qkv + (size_t)m * (3 * DD) + h * HD;

        float score = -INFINITY;
        if (hl <= s) {
            const __half* kp = &Ks[(qi + WW - 1 - hl) * PKH];
            float acc = 0.f;
            #pragma unroll
            for (int d = 0; d < HD; d += 8) {
                float4 qa4 = *(const float4*)(qp + d);
                float4 ka4 = *(const float4*)(kp + d);
                const __half2* qh = (const __half2*)&qa4;
                const __half2* kh = (const __half2*)&ka4;
                #pragma unroll
                for (int t = 0; t < 4; t++) {
                    float2 qf = __half22float2(qh[t]);
                    float2 kf = __half22float2(kh[t]);
                    acc = fmaf(qf.x, kf.x, acc);
                    acc = fmaf(qf.y, kf.y, acc);
                }
            }
            score = acc * 0.125f;
        }
        // 16-lane reductions (XOR < 16 stays within each half-warp)
        float mx = score;
        #pragma unroll
        for (int o = 8; o > 0; o >>= 1) mx = fmaxf(mx, __shfl_xor_sync(0xffffffffu, mx, o));
        float p = (score == -INFINITY) ? 0.f : __expf(score - mx);
        float sum = p;
        #pragma unroll
        for (int o = 8; o > 0; o >>= 1) sum += __shfl_xor_sync(0xffffffffu, sum, o);
        float inv = 1.f / sum;
        float invA = __shfl_sync(0xffffffffu, inv, 0);
        float invB = __shfl_sync(0xffffffffu, inv, 16);

        // V accumulation for both queries; lane owns dims 2*lane, 2*lane+1
        int qiA = w * 8 + qq * 2;
        int qiB = qiA + 1;
        float a0 = 0.f, a1 = 0.f, b0 = 0.f, b1 = 0.f;
        #pragma unroll
        for (int jj = 0; jj < WW; jj++) {
            float pA = __shfl_sync(0xffffffffu, p, jj);
            float pB = __shfl_sync(0xffffffffu, p, 16 + jj);
            float2 vA = __half22float2(*(const __half2*)&Vs[(qiA + WW - 1 - jj) * PKH + 2 * lane]);
            float2 vB = __half22float2(*(const __half2*)&Vs[(qiB + WW - 1 - jj) * PKH + 2 * lane]);
            a0 = fmaf(pA, vA.x, a0); a1 = fmaf(pA, vA.y, a1);
            b0 = fmaf(pB, vB.x, b0); b1 = fmaf(pB, vB.y, b1);
        }
        size_t mA = (size_t)(b * SS + s0 + qiA);
        *(__half2*)(oh + mA * DD + h * HD + 2 * lane)       = __floats2half2_rn(a0 * invA, a1 * invA);
        *(__half2*)(oh + (mA + 1) * DD + h * HD + 2 * lane) = __floats2half2_rn(b0 * invB, b1 * invB);
    }
}

// ---------------- launch ----------------
typedef CUresult (*PFN_encode)(CUtensorMap*, CUtensorMapDataType, cuuint32_t, void*,
                               const cuuint64_t*, const cuuint64_t*, const cuuint32_t*,
                               const cuuint32_t*, CUtensorMapInterleave, CUtensorMapSwizzle,
                               CUtensorMapL2promotion, CUtensorMapFloatOOBfill);

static void make_map(PFN_encode enc, CUtensorMap* m, void* ptr, uint64_t K, uint64_t R) {
    cuuint64_t dims[2]    = {K, R};
    cuuint64_t strides[1] = {K * 2};
    cuuint32_t box[2]     = {64, 128};
    cuuint32_t es[2]      = {1, 1};
    enc(m, CU_TENSOR_MAP_DATA_TYPE_FLOAT16, 2, ptr, dims, strides, box, es,
        CU_TENSOR_MAP_INTERLEAVE_NONE, CU_TENSOR_MAP_SWIZZLE_128B,
        CU_TENSOR_MAP_L2_PROMOTION_L2_128B, CU_TENSOR_MAP_FLOAT_OOB_FILL_NONE);
}

extern "C" void kernel_launch(void* const* d_in, const int* in_sizes, int n_in,
                              void* d_out, int out_size) {
    const float* x          = (const float*)d_in[0];
    const float* ln1_g      = (const float*)d_in[1];
    const float* ln1_b      = (const float*)d_in[2];
    const float* in_proj_w  = (const float*)d_in[3];
    const float* in_proj_b  = (const float*)d_in[4];
    const float* out_proj_w = (const float*)d_in[5];
    const float* out_proj_b = (const float*)d_in[6];
    const float* ln2_g      = (const float*)d_in[7];
    const float* ln2_b      = (const float*)d_in[8];
    const float* mlp_w1     = (const float*)d_in[9];
    const float* mlp_b1     = (const float*)d_in[10];
    const float* mlp_w2     = (const float*)d_in[11];
    const float* mlp_b2     = (const float*)d_in[12];
    float* out = (float*)d_out;

    float *p_x1;
    __half *p_qkvh, *p_h, *p_at, *p_xn, *p_ff, *p_wq, *p_wo, *p_w1, *p_w2;
    cudaGetSymbolAddress((void**)&p_qkvh, g_qkv_h);
    cudaGetSymbolAddress((void**)&p_x1,  g_x1);
    cudaGetSymbolAddress((void**)&p_h,   g_h_h);
    cudaGetSymbolAddress((void**)&p_at,  g_at_h);
    cudaGetSymbolAddress((void**)&p_xn,  g_xn_h);
    cudaGetSymbolAddress((void**)&p_ff,  g_ff_h);
    cudaGetSymbolAddress((void**)&p_wq,  g_wq_h);
    cudaGetSymbolAddress((void**)&p_wo,  g_wo_h);
    cudaGetSymbolAddress((void**)&p_w1,  g_w1_h);
    cudaGetSymbolAddress((void**)&p_w2,  g_w2_h);

    // driver entry point via runtime API (no -lcuda needed)
    PFN_encode enc = nullptr;
    cudaDriverEntryPointQueryResult qr;
    cudaGetDriverEntryPoint("cuTensorMapEncodeTiled", (void**)&enc,
                            cudaEnableDefault, &qr);

    CUtensorMap tm_h, tm_wq, tm_at, tm_wo, tm_xn, tm_w1, tm_ff, tm_w2;
    make_map(enc, &tm_h,  p_h,  DD,  MM);
    make_map(enc, &tm_wq, p_wq, DD,  3 * DD);
    make_map(enc, &tm_at, p_at, DD,  MM);
    make_map(enc, &tm_wo, p_wo, DD,  DD);
    make_map(enc, &tm_xn, p_xn, DD,  MM);
    make_map(enc, &tm_w1, p_w1, DD,  DFF);
    make_map(enc, &tm_ff, p_ff, DFF, MM);
    make_map(enc, &tm_w2, p_w2, DFF, DD);

    cudaFuncSetAttribute(gemmh, cudaFuncAttributeMaxDynamicSharedMemorySize, GEMM_SMEM);
    cudaFuncSetAttribute(attn_kernel, cudaFuncAttributeMaxDynamicSharedMemorySize, ATTN_SMEM);

    cvt4_kernel<<<12288, 256>>>(in_proj_w, p_wq, out_proj_w, p_wo,
                                mlp_w1, p_w1, mlp_w2, p_w2);
    ln_half_kernel<<<MM, 256>>>(x, ln1_g, ln1_b, p_h);
    // QKV = h @ W_in^T + b -> fp16   [4096, 3072]
    gemmh<<<dim3(3 * DD / 128, MM / 128), 256, GEMM_SMEM>>>(
        tm_h, tm_wq, in_proj_b, nullptr, nullptr, p_qkvh, 3 * DD, DD, 0);
    // windowed attention (fp16 smem-tiled, dual-query) -> fp16
    attn_kernel<<<dim3(SS / TQ, HH, BB), 256, ATTN_SMEM>>>(p_qkvh, p_at);
    // out proj + residual(x) -> x1 fp32  [4096, 1024]
    gemmh<<<dim3(DD / 128, MM / 128), 256, GEMM_SMEM>>>(
        tm_at, tm_wo, out_proj_b, x, p_x1, nullptr, DD, DD, 1);
    // LN2 -> fp16
    ln_half_kernel<<<MM, 256>>>(p_x1, ln2_g, ln2_b, p_xn);
    // MLP up + GELU -> fp16   [4096, 4096]
    gemmh<<<dim3(DFF / 128, MM / 128), 256, GEMM_SMEM>>>(
        tm_xn, tm_w1, mlp_b1, nullptr, nullptr, p_ff, DFF, DD, 2);
    // MLP down + residual(x1) -> out   [4096, 1024]
    gemmh<<<dim3(DD / 128, MM / 128), 256, GEMM_SMEM>>>(
        tm_ff, tm_w2, mlp_b2, p_x1, out, nullptr, DD, DFF, 1);
}

// round 12
// speedup vs baseline: 9.1247x; 1.0290x over previous
#include <cuda_runtime.h>
#include <cuda.h>
#include <cuda_fp16.h>
#include <math.h>
#include <stdint.h>

// Problem constants
#define BB 2
#define SS 2048
#define DD 1024
#define HH 16
#define HD 64
#define WW 16
#define DFF 4096
#define MM (BB * SS)   // 4096 rows

// ---------------- scratch (no allocations allowed) ----------------
__device__ __half g_qkv_h[MM * 3 * DD];       // QKV fp16
__device__ float g_x1[MM * DD];               // residual-1 output fp32
__device__ __half g_h_h[MM * DD];             // LN1 out fp16
__device__ __half g_at_h[MM * DD];            // attn out fp16
__device__ __half g_xn_h[MM * DD];            // LN2 out fp16
__device__ __half g_ff_h[MM * DFF];           // MLP hidden fp16
__device__ __half g_wq_h[3 * DD * DD];
__device__ __half g_wo_h[DD * DD];
__device__ __half g_w1_h[DFF * DD];
__device__ __half g_w2_h[DD * DFF];

__device__ __forceinline__ uint32_t smem_u32(const void* p) {
    return (uint32_t)__cvta_generic_to_shared(p);
}

__device__ __forceinline__ float gelu_tanh(float x) {
    float x3 = x * x * x;
    return 0.5f * x * (1.0f + tanhf(0.7978845608028654f * (x + 0.044715f * x3)));
}

// ---------------- merged weight convert kernel (fp32 -> fp16, 4 segments) ----------------
__global__ void cvt4_kernel(const float* __restrict__ wq, __half* __restrict__ owq,
                            const float* __restrict__ wo, __half* __restrict__ owo,
                            const float* __restrict__ w1, __half* __restrict__ ow1,
                            const float* __restrict__ w2, __half* __restrict__ ow2) {
    int blk = blockIdx.x;
    const float* in; __half* out; int base;
    if (blk < 3072)       { in = wq; out = owq; base = blk; }
    else if (blk < 4096)  { in = wo; out = owo; base = blk - 3072; }
    else if (blk < 8192)  { in = w1; out = ow1; base = blk - 4096; }
    else                  { in = w2; out = ow2; base = blk - 8192; }
    int i = base * 1024 + threadIdx.x * 4;
    float4 v = *(const float4*)(in + i);
    *(__half2*)(out + i)     = __floats2half2_rn(v.x, v.y);
    *(__half2*)(out + i + 2) = __floats2half2_rn(v.z, v.w);
}

// ---------------- LayerNorm -> fp16 ----------------
__global__ void ln_half_kernel(const float* __restrict__ x,
                               const float* __restrict__ g,
                               const float* __restrict__ b,
                               __half* __restrict__ y) {
    int row = blockIdx.x;
    const float* xp = x + (size_t)row * DD;
    int i = threadIdx.x * 4;
    float4 xv = *(const float4*)(xp + i);
    float s  = xv.x + xv.y + xv.z + xv.w;
    float ss = xv.x*xv.x + xv.y*xv.y + xv.z*xv.z + xv.w*xv.w;
    for (int o = 16; o > 0; o >>= 1) {
        s  += __shfl_xor_sync(0xffffffffu, s,  o);
        ss += __shfl_xor_sync(0xffffffffu, ss, o);
    }
    __shared__ float sh_s[8], sh_ss[8];
    int wid = threadIdx.x >> 5, lane = threadIdx.x & 31;
    if (lane == 0) { sh_s[wid] = s; sh_ss[wid] = ss; }
    __syncthreads();
    if (wid == 0) {
        s  = (lane < 8) ? sh_s[lane]  : 0.f;
        ss = (lane < 8) ? sh_ss[lane] : 0.f;
        for (int o = 4; o > 0; o >>= 1) {
            s  += __shfl_xor_sync(0xffffffffu, s,  o);
            ss += __shfl_xor_sync(0xffffffffu, ss, o);
        }
        if (lane == 0) { sh_s[0] = s; sh_ss[0] = ss; }
    }
    __syncthreads();
    float mean = sh_s[0] * (1.0f / DD);
    float var  = sh_ss[0] * (1.0f / DD) - mean * mean;
    float inv  = rsqrtf(var + 1e-5f);
    float4 gv = *(const float4*)(g + i);
    float4 bv = *(const float4*)(b + i);
    float o0 = (xv.x - mean) * inv * gv.x + bv.x;
    float o1 = (xv.y - mean) * inv * gv.y + bv.y;
    float o2 = (xv.z - mean) * inv * gv.z + bv.z;
    float o3 = (xv.w - mean) * inv * gv.w + bv.w;
    size_t idx = (size_t)row * DD + i;
    *(__half2*)(y + idx)     = __floats2half2_rn(o0, o1);
    *(__half2*)(y + idx + 2) = __floats2half2_rn(o2, o3);
}

// ---------------- TMA + mma.sync fp16 GEMM: C[M,N] = A[M,K] @ Bw[N,K]^T (+epi) ----------------
// 3-stage TMA pipeline, full/empty mbarriers (no per-chunk __syncthreads).
// Tile bases MUST be 1024B-aligned so the manual swizzle matches TMA's.
// epi: 0 = +bias -> fp16 ; 1 = fp32 +bias+res ; 2 = gelu(+bias) -> fp16
#define BKT 64
#define TILE_BYTES (128 * 128)          // 16384 (64 fp16 = 128 B per row)
#define OFF_A 0
#define OFF_B TILE_BYTES
#define STAGE_BYTES (2 * TILE_BYTES)    // 32768
#define NSTAGE 3
#define GEMM_SMEM (NSTAGE * STAGE_BYTES + 1024)  // 99328 (1KB alignment slack)

#define LDMX4(r0, r1, r2, r3, addr) \
    asm volatile("ldmatrix.sync.aligned.m8n8.x4.shared.b16 {%0,%1,%2,%3}, [%4];" \
                 : "=r"(r0), "=r"(r1), "=r"(r2), "=r"(r3) : "r"(addr))

#define MMA_F16(d, a, b0, b1) \
    asm volatile("mma.sync.aligned.m16n8k16.row.col.f32.f16.f16.f32 " \
                 "{%0,%1,%2,%3}, {%4,%5,%6,%7}, {%8,%9}, {%0,%1,%2,%3};" \
                 : "+f"((d)[0]), "+f"((d)[1]), "+f"((d)[2]), "+f"((d)[3]) \
                 : "r"((a)[0]), "r"((a)[1]), "r"((a)[2]), "r"((a)[3]), "r"(b0), "r"(b1))

#define MBAR_INIT(mbar, cnt) \
    asm volatile("mbarrier.init.shared.b64 [%0], %1;" :: "r"(mbar), "r"(cnt) : "memory")

#define MBAR_EXPECT(mbar, bytes) \
    asm volatile("mbarrier.arrive.expect_tx.shared.b64 _, [%0], %1;" :: "r"(mbar), "r"(bytes) : "memory")

#define MBAR_ARRIVE(mbar) \
    asm volatile("mbarrier.arrive.release.cta.shared::cta.b64 _, [%0];" :: "r"(mbar) : "memory")

#define MBAR_WAIT(mbar, parity) do {                                            \
    uint32_t _m = (mbar); uint32_t _p = (parity); uint32_t _d;                  \
    asm volatile("{\n\t.reg .pred p;\n\t"                                       \
        "mbarrier.try_wait.parity.acquire.cta.shared::cta.b64 p, [%1], %2;\n\t" \
        "selp.b32 %0, 1, 0, p;\n\t}"                                            \
        : "=r"(_d) : "r"(_m), "r"(_p) : "memory");                              \
    if (!_d) {                                                                  \
        asm volatile("{\n\t.reg .pred P1;\n\t"                                  \
            "WL_%=:\n\t"                                                        \
            "mbarrier.try_wait.parity.acquire.cta.shared::cta.b64 P1, [%0], %1, 0x989680;\n\t" \
            "@P1 bra.uni WD_%=;\n\t"                                            \
            "bra.uni WL_%=;\n\t"                                                \
            "WD_%=:\n\t}" :: "r"(_m), "r"(_p) : "memory");                      \
    }                                                                           \
} while (0)

#define TMA_LD2D(smem, tmap, cx, cy, mbar) \
    asm volatile("cp.async.bulk.tensor.2d.shared::cta.global.tile.mbarrier::complete_tx::bytes " \
                 "[%0], [%1, {%2, %3}], [%4];" \
                 :: "r"(smem), "l"(tmap), "r"(cx), "r"(cy), "r"(mbar) : "memory")

// swizzled byte offset inside one 128x64(fp16) tile: row r (0..127), 16B unit u (0..7)
// valid ONLY when tile base is 1024B-aligned
__device__ __forceinline__ uint32_t sw_off(int r, int u) {
    return (uint32_t)(r * 128 + ((u ^ (r & 7)) << 4));
}

__global__ __launch_bounds__(256, 2)
void gemmh(const __grid_constant__ CUtensorMap tmA,
           const __grid_constant__ CUtensorMap tmB,
           const float* __restrict__ bias, const float* __restrict__ res,
           float* __restrict__ outF, __half* __restrict__ outH,
           int Nn, int Kk, int epi) {
    extern __shared__ __align__(128) char dsm[];
    __shared__ __align__(8) uint64_t s_full[NSTAGE];
    __shared__ __align__(8) uint64_t s_empty[NSTAGE];
    uint32_t sbase = (smem_u32(dsm) + 1023) & ~1023u;   // 1024B-align: swizzle phase contract
    int tid = threadIdx.x;
    int lane = tid & 31;
    int wid = tid >> 5;
    int wr = wid & 1;      // warp row: m offset wr*64
    int wc = wid >> 1;     // warp col: n offset wc*32
    int bm = blockIdx.y * 128;
    int bn = blockIdx.x * 128;

    float acc[4][4][4];
    #pragma unroll
    for (int mi = 0; mi < 4; mi++)
        #pragma unroll
        for (int ni = 0; ni < 4; ni++)
            #pragma unroll
            for (int q = 0; q < 4; q++) acc[mi][ni][q] = 0.f;

    const int NC = Kk >> 6;   // BKT=64 chunks

    if (tid == 0) {
        #pragma unroll
        for (int s = 0; s < NSTAGE; s++) {
            MBAR_INIT(smem_u32(&s_full[s]), 1);
            MBAR_INIT(smem_u32(&s_empty[s]), 256);
        }
    }
    __syncthreads();

    // prologue: issue chunks 0, 1
    if (tid == 0) {
        #pragma unroll
        for (int c0 = 0; c0 < 2; c0++) {
            if (c0 < NC) {
                uint32_t st = sbase + c0 * STAGE_BYTES;
                uint32_t mb = smem_u32(&s_full[c0]);
                MBAR_EXPECT(mb, STAGE_BYTES);
                TMA_LD2D(st + OFF_A, &tmA, c0 << 6, bm, mb);
                TMA_LD2D(st + OFF_B, &tmB, c0 << 6, bn, mb);
            }
        }
    }

    int a_row = wr * 64 + (lane & 15);
    int a_usel = (lane >> 4) & 1;
    int b_row = wc * 32 + (lane & 7) + ((lane >> 4) & 1) * 8;
    int b_usel = (lane >> 3) & 1;

    for (int c = 0; c < NC; c++) {
        int stg = c % NSTAGE;
        MBAR_WAIT(smem_u32(&s_full[stg]), (c / NSTAGE) & 1);

        uint32_t st = sbase + stg * STAGE_BYTES;
        #pragma unroll
        for (int kk = 0; kk < 4; kk++) {
            uint32_t bh[8];
            #pragma unroll
            for (int g = 0; g < 2; g++) {
                int r = b_row + g * 16;
                uint32_t off = sw_off(r, kk * 2 + b_usel);
                LDMX4(bh[g*4+0], bh[g*4+1], bh[g*4+2], bh[g*4+3], st + OFF_B + off);
            }
            #pragma unroll
            for (int mi = 0; mi < 4; mi++) {
                uint32_t ah[4];
                int r = a_row + mi * 16;
                uint32_t off = sw_off(r, kk * 2 + a_usel);
                LDMX4(ah[0], ah[1], ah[2], ah[3], st + OFF_A + off);
                #pragma unroll
                for (int ni = 0; ni < 4; ni++) {
                    MMA_F16(acc[mi][ni], ah, bh[ni*2], bh[ni*2+1]);
                }
            }
        }
        // consumer done with this stage's smem
        MBAR_ARRIVE(smem_u32(&s_empty[stg]));

        if (tid == 0 && c + 2 < NC) {
            int cn = c + 2;
            int sn = cn % NSTAGE;
            if (cn >= NSTAGE)
                MBAR_WAIT(smem_u32(&s_empty[sn]), (cn / NSTAGE - 1) & 1);
            uint32_t st2 = sbase + sn * STAGE_BYTES;
            uint32_t mb = smem_u32(&s_full[sn]);
            MBAR_EXPECT(mb, STAGE_BYTES);
            TMA_LD2D(st2 + OFF_A, &tmA, cn << 6, bm, mb);
            TMA_LD2D(st2 + OFF_B, &tmB, cn << 6, bn, mb);
        }
    }

    // epilogue
    int m0 = bm + wr * 64 + (lane >> 2);
    int n0 = bn + wc * 32 + (lane & 3) * 2;
    #pragma unroll
    for (int mi = 0; mi < 4; mi++) {
        #pragma unroll
        for (int r2 = 0; r2 < 2; r2++) {
            int row = m0 + mi * 16 + r2 * 8;
            size_t rbase = (size_t)row * Nn;
            #pragma unroll
            for (int ni = 0; ni < 4; ni++) {
                int col = n0 + ni * 8;
                float v0 = acc[mi][ni][r2*2+0] + bias[col];
                float v1 = acc[mi][ni][r2*2+1] + bias[col+1];
                if (epi == 0) {
                    *(__half2*)(outH + rbase + col) = __floats2half2_rn(v0, v1);
                } else if (epi == 1) {
                    float2 rv = *(const float2*)(res + rbase + col);
                    *(float2*)(outF + rbase + col) = make_float2(v0 + rv.x, v1 + rv.y);
                } else {
                    v0 = gelu_tanh(v0); v1 = gelu_tanh(v1);
                    *(__half2*)(outH + rbase + col) = __floats2half2_rn(v0, v1);
                }
            }
        }
    }
}

// ---------------- Sliding-window causal attention (W=16), fp16, dual-query warps ----------------
// Lanes 0-15 score query A, lanes 16-31 score query B (no idle half-warp).
#define TQ 64
#define KR (TQ + WW - 1)     // 79 key rows
#define PKH 72               // halves per smem row (144B, 16B-aligned rows)
#define ATTN_SMEM (2 * 80 * PKH * 2)   // 23040 bytes

__global__ __launch_bounds__(256, 6)
void attn_kernel(const __half* __restrict__ qkv,
                 __half* __restrict__ oh) {
    extern __shared__ __align__(16) __half asm_h[];
    __half* Ks = asm_h;                 // [80][PKH]
    __half* Vs = asm_h + 80 * PKH;      // [80][PKH]

    int tile = blockIdx.x;
    int h = blockIdx.y;
    int b = blockIdx.z;
    int s0 = tile * TQ;
    int tid = threadIdx.x;
    int lane = tid & 31;
    int w = tid >> 5;

    // cooperative load: 79 rows x 64 halves, 16B chunks; zero-fill seq<0 rows
    for (int i = tid; i < KR * (HD / 8); i += 256) {
        int r = i >> 3;
        int c = (i & 7) * 8;
        int seq = s0 - (WW - 1) + r;
        if (seq >= 0) {
            size_t base = ((size_t)(b * SS + seq)) * (3 * DD) + h * HD + c;
            *(float4*)&Ks[r * PKH + c] = *(const float4*)(qkv + base + DD);
            *(float4*)&Vs[r * PKH + c] = *(const float4*)(qkv + base + 2 * DD);
        } else {
            float4 z = make_float4(0.f, 0.f, 0.f, 0.f);
            *(float4*)&Ks[r * PKH + c] = z;
            *(float4*)&Vs[r * PKH + c] = z;
        }
    }
    __syncthreads();

    int half = lane >> 4;   // 0: query A, 1: query B
    int hl = lane & 15;     // key offset j for the score phase

    for (int qq = 0; qq < 4; qq++) {
        int qi = w * 8 + qq * 2 + half;   // this lane's score query (local)
        int s = s0 + qi;
        int m = b * SS + s;
        const __half* qp = qkv + (size_t)m * (3 * DD) + h * HD;

        float score = -INFINITY;
        if (hl <= s) {
            const __half* kp = &Ks[(qi + WW - 1 - hl) * PKH];
            float acc = 0.f;
            #pragma unroll
            for (int d = 0; d < HD; d += 8) {
                float4 qa4 = *(const float4*)(qp + d);
                float4 ka4 = *(const float4*)(kp + d);
                const __half2* qh = (const __half2*)&qa4;
                const __half2* kh = (const __half2*)&ka4;
                #pragma unroll
                for (int t = 0; t < 4; t++) {
                    float2 qf = __half22float2(qh[t]);
                    float2 kf = __half22float2(kh[t]);
                    acc = fmaf(qf.x, kf.x, acc);
                    acc = fmaf(qf.y, kf.y, acc);
                }
            }
            score = acc * 0.125f;
        }
        // 16-lane reductions (XOR < 16 stays within each half-warp)
        float mx = score;
        #pragma unroll
        for (int o = 8; o > 0; o >>= 1) mx = fmaxf(mx, __shfl_xor_sync(0xffffffffu, mx, o));
        float p = (score == -INFINITY) ? 0.f : __expf(score - mx);
        float sum = p;
        #pragma unroll
        for (int o = 8; o > 0; o >>= 1) sum += __shfl_xor_sync(0xffffffffu, sum, o);
        float inv = 1.f / sum;
        float invA = __shfl_sync(0xffffffffu, inv, 0);
        float invB = __shfl_sync(0xffffffffu, inv, 16);

        // V accumulation for both queries; lane owns dims 2*lane, 2*lane+1
        int qiA = w * 8 + qq * 2;
        int qiB = qiA + 1;
        float a0 = 0.f, a1 = 0.f, b0 = 0.f, b1 = 0.f;
        #pragma unroll
        for (int jj = 0; jj < WW; jj++) {
            float pA = __shfl_sync(0xffffffffu, p, jj);
            float pB = __shfl_sync(0xffffffffu, p, 16 + jj);
            float2 vA = __half22float2(*(const __half2*)&Vs[(qiA + WW - 1 - jj) * PKH + 2 * lane]);
            float2 vB = __half22float2(*(const __half2*)&Vs[(qiB + WW - 1 - jj) * PKH + 2 * lane]);
            a0 = fmaf(pA, vA.x, a0); a1 = fmaf(pA, vA.y, a1);
            b0 = fmaf(pB, vB.x, b0); b1 = fmaf(pB, vB.y, b1);
        }
        size_t mA = (size_t)(b * SS + s0 + qiA);
        *(__half2*)(oh + mA * DD + h * HD + 2 * lane)       = __floats2half2_rn(a0 * invA, a1 * invA);
        *(__half2*)(oh + (mA + 1) * DD + h * HD + 2 * lane) = __floats2half2_rn(b0 * invB, b1 * invB);
    }
}

// ---------------- launch ----------------
typedef CUresult (*PFN_encode)(CUtensorMap*, CUtensorMapDataType, cuuint32_t, void*,
                               const cuuint64_t*, const cuuint64_t*, const cuuint32_t*,
                               const cuuint32_t*, CUtensorMapInterleave, CUtensorMapSwizzle,
                               CUtensorMapL2promotion, CUtensorMapFloatOOBfill);

static void make_map(PFN_encode enc, CUtensorMap* m, void* ptr, uint64_t K, uint64_t R) {
    cuuint64_t dims[2]    = {K, R};
    cuuint64_t strides[1] = {K * 2};
    cuuint32_t box[2]     = {64, 128};
    cuuint32_t es[2]      = {1, 1};
    enc(m, CU_TENSOR_MAP_DATA_TYPE_FLOAT16, 2, ptr, dims, strides, box, es,
        CU_TENSOR_MAP_INTERLEAVE_NONE, CU_TENSOR_MAP_SWIZZLE_128B,
        CU_TENSOR_MAP_L2_PROMOTION_L2_128B, CU_TENSOR_MAP_FLOAT_OOB_FILL_NONE);
}

extern "C" void kernel_launch(void* const* d_in, const int* in_sizes, int n_in,
                              void* d_out, int out_size) {
    const float* x          = (const float*)d_in[0];
    const float* ln1_g      = (const float*)d_in[1];
    const float* ln1_b      = (const float*)d_in[2];
    const float* in_proj_w  = (const float*)d_in[3];
    const float* in_proj_b  = (const float*)d_in[4];
    const float* out_proj_w = (const float*)d_in[5];
    const float* out_proj_b = (const float*)d_in[6];
    const float* ln2_g      = (const float*)d_in[7];
    const float* ln2_b      = (const float*)d_in[8];
    const float* mlp_w1     = (const float*)d_in[9];
    const float* mlp_b1     = (const float*)d_in[10];
    const float* mlp_w2     = (const float*)d_in[11];
    const float* mlp_b2     = (const float*)d_in[12];
    float* out = (float*)d_out;

    float *p_x1;
    __half *p_qkvh, *p_h, *p_at, *p_xn, *p_ff, *p_wq, *p_wo, *p_w1, *p_w2;
    cudaGetSymbolAddress((void**)&p_qkvh, g_qkv_h);
    cudaGetSymbolAddress((void**)&p_x1,  g_x1);
    cudaGetSymbolAddress((void**)&p_h,   g_h_h);
    cudaGetSymbolAddress((void**)&p_at,  g_at_h);
    cudaGetSymbolAddress((void**)&p_xn,  g_xn_h);
    cudaGetSymbolAddress((void**)&p_ff,  g_ff_h);
    cudaGetSymbolAddress((void**)&p_wq,  g_wq_h);
    cudaGetSymbolAddress((void**)&p_wo,  g_wo_h);
    cudaGetSymbolAddress((void**)&p_w1,  g_w1_h);
    cudaGetSymbolAddress((void**)&p_w2,  g_w2_h);

    // driver entry point via runtime API (no -lcuda needed)
    PFN_encode enc = nullptr;
    cudaDriverEntryPointQueryResult qr;
    cudaGetDriverEntryPoint("cuTensorMapEncodeTiled", (void**)&enc,
                            cudaEnableDefault, &qr);

    CUtensorMap tm_h, tm_wq, tm_at, tm_wo, tm_xn, tm_w1, tm_ff, tm_w2;
    make_map(enc, &tm_h,  p_h,  DD,  MM);
    make_map(enc, &tm_wq, p_wq, DD,  3 * DD);
    make_map(enc, &tm_at, p_at, DD,  MM);
    make_map(enc, &tm_wo, p_wo, DD,  DD);
    make_map(enc, &tm_xn, p_xn, DD,  MM);
    make_map(enc, &tm_w1, p_w1, DD,  DFF);
    make_map(enc, &tm_ff, p_ff, DFF, MM);
    make_map(enc, &tm_w2, p_w2, DFF, DD);

    cudaFuncSetAttribute(gemmh, cudaFuncAttributeMaxDynamicSharedMemorySize, GEMM_SMEM);
    cudaFuncSetAttribute(attn_kernel, cudaFuncAttributeMaxDynamicSharedMemorySize, ATTN_SMEM);

    cvt4_kernel<<<12288, 256>>>(in_proj_w, p_wq, out_proj_w, p_wo,
                                mlp_w1, p_w1, mlp_w2, p_w2);
    ln_half_kernel<<<MM, 256>>>(x, ln1_g, ln1_b, p_h);
    // QKV = h @ W_in^T + b -> fp16   [4096, 3072]
    gemmh<<<dim3(3 * DD / 128, MM / 128), 256, GEMM_SMEM>>>(
        tm_h, tm_wq, in_proj_b, nullptr, nullptr, p_qkvh, 3 * DD, DD, 0);
    // windowed attention (fp16 smem-tiled, dual-query) -> fp16
    attn_kernel<<<dim3(SS / TQ, HH, BB), 256, ATTN_SMEM>>>(p_qkvh, p_at);
    // out proj + residual(x) -> x1 fp32  [4096, 1024]
    gemmh<<<dim3(DD / 128, MM / 128), 256, GEMM_SMEM>>>(
        tm_at, tm_wo, out_proj_b, x, p_x1, nullptr, DD, DD, 1);
    // LN2 -> fp16
    ln_half_kernel<<<MM, 256>>>(p_x1, ln2_g, ln2_b, p_xn);
    // MLP up + GELU -> fp16   [4096, 4096]
    gemmh<<<dim3(DFF / 128, MM / 128), 256, GEMM_SMEM>>>(
        tm_xn, tm_w1, mlp_b1, nullptr, nullptr, p_ff, DFF, DD, 2);
    // MLP down + residual(x1) -> out   [4096, 1024]
    gemmh<<<dim3(DD / 128, MM / 128), 256, GEMM_SMEM>>>(
        tm_ff, tm_w2, mlp_b2, p_x1, out, nullptr, DD, DFF, 1);
}